// round 1
// baseline (speedup 1.0000x reference)
#include <cuda_runtime.h>
#include <cuda_bf16.h>

// Problem constants (fixed shapes)
#define NH    32
#define NKV   8
#define HD    128
#define S_LEN 2048
#define B_SZ  2
#define HID   4096
#define MROWS (B_SZ * S_LEN)   // 4096
#define NREP  (NH / NKV)       // 4

// ---------------------------------------------------------------------------
// Scratch (device globals; allocation-free per harness rules)
// ---------------------------------------------------------------------------
__device__ float g_q [(size_t)MROWS * NH  * HD];  // (b,s,h,d)
__device__ float g_k [(size_t)MROWS * NKV * HD];  // (b,s,g,d)
__device__ float g_v [(size_t)MROWS * NKV * HD];  // (b,s,g,d)
__device__ float g_ao[(size_t)MROWS * NH  * HD];  // attention output, (b,s,h,d)

// ---------------------------------------------------------------------------
// Packed f32x2 helpers (Blackwell sm_100+: 2 fp32 FMA per instruction)
// ---------------------------------------------------------------------------
__device__ __forceinline__ unsigned long long f2_fma(unsigned long long a,
                                                     unsigned long long b,
                                                     unsigned long long c) {
    unsigned long long d;
    asm("fma.rn.f32x2 %0, %1, %2, %3;" : "=l"(d) : "l"(a), "l"(b), "l"(c));
    return d;
}
__device__ __forceinline__ unsigned long long f2_mul(unsigned long long a,
                                                     unsigned long long b) {
    unsigned long long d;
    asm("mul.rn.f32x2 %0, %1, %2;" : "=l"(d) : "l"(a), "l"(b));
    return d;
}
__device__ __forceinline__ unsigned long long f2_dup(float a) {
    unsigned long long d;
    asm("mov.b64 %0, {%1, %1};" : "=l"(d) : "f"(a));
    return d;
}
__device__ __forceinline__ float2 f2_unpack(unsigned long long v) {
    float2 r;
    asm("mov.b64 {%0, %1}, %2;" : "=f"(r.x), "=f"(r.y) : "l"(v));
    return r;
}

// ---------------------------------------------------------------------------
// GEMM: C[M,N] = A[M,K] * B[N,K]^T   (both row-major, K contiguous)
// 128x128x8 tile, 256 threads, each thread: 8 rows x 4 column-pairs (f32x2)
// ---------------------------------------------------------------------------
#define GBM 128
#define GBN 128
#define GBK 8

__global__ __launch_bounds__(256) void gemm_nt_kernel(
    const float* __restrict__ A, const float* __restrict__ Bm,
    float* __restrict__ C, int M, int N, int K)
{
    __shared__ __align__(16) float As[GBK][GBM];
    __shared__ __align__(16) float Bs[GBK][GBN];

    const int tid = threadIdx.x;
    const int bm  = blockIdx.y * GBM;
    const int bn  = blockIdx.x * GBN;
    const int ty  = tid >> 4;           // 0..15 -> rows ty*8 + i
    const int tx  = tid & 15;           // 0..15 -> col pairs tx*2 + 32*j
    const int lr  = tid >> 1;           // 0..127 load row
    const int lc  = (tid & 1) << 2;     // 0 or 4  load k-offset

    const float* Ag = A  + (size_t)(bm + lr) * K + lc;
    const float* Bg = Bm + (size_t)(bn + lr) * K + lc;

    unsigned long long acc[8][4];
#pragma unroll
    for (int i = 0; i < 8; i++)
#pragma unroll
        for (int j = 0; j < 4; j++) acc[i][j] = 0ull;

    for (int k0 = 0; k0 < K; k0 += GBK) {
        float4 a4 = *(const float4*)(Ag + k0);
        float4 b4 = *(const float4*)(Bg + k0);
        __syncthreads();
        As[lc + 0][lr] = a4.x; As[lc + 1][lr] = a4.y;
        As[lc + 2][lr] = a4.z; As[lc + 3][lr] = a4.w;
        Bs[lc + 0][lr] = b4.x; Bs[lc + 1][lr] = b4.y;
        Bs[lc + 2][lr] = b4.z; Bs[lc + 3][lr] = b4.w;
        __syncthreads();
#pragma unroll
        for (int kk = 0; kk < GBK; kk++) {
            unsigned long long b2[4];
#pragma unroll
            for (int j = 0; j < 4; j++)
                b2[j] = *(const unsigned long long*)(&Bs[kk][tx * 2 + 32 * j]);
#pragma unroll
            for (int i = 0; i < 8; i++) {
                unsigned long long a2 = f2_dup(As[kk][ty * 8 + i]);
#pragma unroll
                for (int j = 0; j < 4; j++)
                    acc[i][j] = f2_fma(a2, b2[j], acc[i][j]);
            }
        }
    }

#pragma unroll
    for (int i = 0; i < 8; i++) {
        float* Crow = C + (size_t)(bm + ty * 8 + i) * N + bn;
#pragma unroll
        for (int j = 0; j < 4; j++) {
            float2 r = f2_unpack(acc[i][j]);
            *(float2*)(Crow + tx * 2 + 32 * j) = r;
        }
    }
}

// ---------------------------------------------------------------------------
// RoPE (in place on q and k). angle = pos * theta^(-d/64), d = 0..63
// out[d]    = x[d]*cos - x[d+64]*sin
// out[d+64] = x[d+64]*cos + x[d]*sin
// ---------------------------------------------------------------------------
__global__ void rope_kernel(float* __restrict__ q, float* __restrict__ k,
                            const int* __restrict__ pos)
{
    const int bs = blockIdx.x;                    // 0..MROWS-1
    const float p = (float)pos[bs];
    const float c1 = -0.2076205059304601f;        // -log2(10000)/64
    for (int i = threadIdx.x; i < (NH + NKV) * 64; i += blockDim.x) {
        float* base; int d;
        if (i < NH * 64) {
            int hh = i >> 6; d = i & 63;
            base = q + ((size_t)bs * NH + hh) * HD;
        } else {
            int j = i - NH * 64;
            int hh = j >> 6; d = j & 63;
            base = k + ((size_t)bs * NKV + hh) * HD;
        }
        float inv = exp2f(c1 * (float)d);
        float ang = p * inv;
        float sv, cv;
        sincosf(ang, &sv, &cv);
        float x1 = base[d], x2 = base[d + 64];
        base[d]      = x1 * cv - x2 * sv;
        base[d + 64] = x2 * cv + x1 * sv;
    }
}

// ---------------------------------------------------------------------------
// Flash attention, fp32, causal. 64x64 tiles, 256 threads.
// Score phase: thread (sg,sc4) computes 4x4 scores, pairs over d (f32x2).
// PV phase:    thread (sg,sc4) owns rows {sg+16m}, col pairs {sc4*2+32j}.
// Softmax state (m, l, alpha) lives in smem to bridge the two mappings.
// ---------------------------------------------------------------------------
#define BQ   64
#define BKV  64
#define QPAD 130
#define PPAD 65

__global__ __launch_bounds__(256) void attn_kernel(
    const float* __restrict__ Q, const float* __restrict__ K,
    const float* __restrict__ V, float* __restrict__ O)
{
    extern __shared__ __align__(16) float sm[];
    float* sQ  = sm;                          // BQ * QPAD
    float* sKV = sQ  + BQ * QPAD;             // BKV * QPAD (K then V)
    float* sP  = sKV + BKV * QPAD;            // BQ * PPAD
    float* sM  = sP  + BQ * PPAD;             // BQ running max
    float* sL  = sM  + BQ;                    // BQ running sum
    float* sA  = sL  + BQ;                    // BQ alpha

    const int qb  = (int)gridDim.x - 1 - (int)blockIdx.x;  // big blocks first
    const int h   = blockIdx.y, b = blockIdx.z;
    const int g   = h / NREP;
    const int tid = threadIdx.x;
    const int q0  = qb * BQ;
    const int sg  = tid >> 4;   // 0..15
    const int sc4 = tid & 15;   // 0..15

    // Load Q tile
    for (int i = tid; i < BQ * (HD / 4); i += 256) {
        int row = i >> 5;
        int c4  = (i & 31) << 2;
        float4 v4 = *(const float4*)(Q + ((size_t)(b * S_LEN + q0 + row) * NH + h) * HD + c4);
        float* dst = sQ + row * QPAD + c4;
        dst[0] = v4.x; dst[1] = v4.y; dst[2] = v4.z; dst[3] = v4.w;
    }
    if (tid < BQ) { sM[tid] = -1e30f; sL[tid] = 0.0f; }

    unsigned long long o2[4][4];
#pragma unroll
    for (int m = 0; m < 4; m++)
#pragma unroll
        for (int j = 0; j < 4; j++) o2[m][j] = 0ull;

    const float scale = 0.08838834764831845f;   // 1/sqrt(128)
    const int nkv = qb + 1;

    for (int kb = 0; kb < nkv; kb++) {
        const int k0 = kb * BKV;
        __syncthreads();   // previous PV done reading sKV
        for (int i = tid; i < BKV * (HD / 4); i += 256) {
            int row = i >> 5;
            int c4  = (i & 31) << 2;
            float4 v4 = *(const float4*)(K + ((size_t)(b * S_LEN + k0 + row) * NKV + g) * HD + c4);
            float* dst = sKV + row * QPAD + c4;
            dst[0] = v4.x; dst[1] = v4.y; dst[2] = v4.z; dst[3] = v4.w;
        }
        __syncthreads();

        // ---- scores: 4x4 per thread, paired over d ----
        unsigned long long s2[4][4];
#pragma unroll
        for (int ii = 0; ii < 4; ii++)
#pragma unroll
            for (int jj = 0; jj < 4; jj++) s2[ii][jj] = 0ull;

#pragma unroll 8
        for (int d = 0; d < HD; d += 2) {
            unsigned long long q2[4], k2[4];
#pragma unroll
            for (int ii = 0; ii < 4; ii++)
                q2[ii] = *(const unsigned long long*)(sQ + (sg * 4 + ii) * QPAD + d);
#pragma unroll
            for (int jj = 0; jj < 4; jj++)
                k2[jj] = *(const unsigned long long*)(sKV + (sc4 * 4 + jj) * QPAD + d);
#pragma unroll
            for (int ii = 0; ii < 4; ii++)
#pragma unroll
                for (int jj = 0; jj < 4; jj++)
                    s2[ii][jj] = f2_fma(q2[ii], k2[jj], s2[ii][jj]);
        }

        // ---- online softmax per row (16 lanes per row-group) ----
#pragma unroll
        for (int ii = 0; ii < 4; ii++) {
            const int row = sg * 4 + ii;
            const int rg  = q0 + row;
            float sc[4];
#pragma unroll
            for (int jj = 0; jj < 4; jj++) {
                float2 f = f2_unpack(s2[ii][jj]);
                float v  = (f.x + f.y) * scale;
                int cg = k0 + sc4 * 4 + jj;
                sc[jj] = (cg > rg) ? -1e30f : v;
            }
            float rmax = fmaxf(fmaxf(sc[0], sc[1]), fmaxf(sc[2], sc[3]));
#pragma unroll
            for (int off = 1; off < 16; off <<= 1)
                rmax = fmaxf(rmax, __shfl_xor_sync(0xffffffffu, rmax, off));
            float mold = sM[row];
            float mnew = fmaxf(mold, rmax);
            float p[4], psum = 0.0f;
#pragma unroll
            for (int jj = 0; jj < 4; jj++) { p[jj] = __expf(sc[jj] - mnew); psum += p[jj]; }
#pragma unroll
            for (int off = 1; off < 16; off <<= 1)
                psum += __shfl_xor_sync(0xffffffffu, psum, off);
            if (sc4 == 0) {
                float alpha = __expf(mold - mnew);
                sM[row] = mnew;
                sL[row] = sL[row] * alpha + psum;
                sA[row] = alpha;
            }
#pragma unroll
            for (int jj = 0; jj < 4; jj++)
                sP[row * PPAD + sc4 * 4 + jj] = p[jj];
        }
        __syncthreads();   // P/alpha written; K reads done

        // ---- load V over K's buffer ----
        for (int i = tid; i < BKV * (HD / 4); i += 256) {
            int row = i >> 5;
            int c4  = (i & 31) << 2;
            float4 v4 = *(const float4*)(V + ((size_t)(b * S_LEN + k0 + row) * NKV + g) * HD + c4);
            float* dst = sKV + row * QPAD + c4;
            dst[0] = v4.x; dst[1] = v4.y; dst[2] = v4.z; dst[3] = v4.w;
        }
        __syncthreads();

        // ---- rescale + P·V accumulate ----
#pragma unroll
        for (int m = 0; m < 4; m++) {
            unsigned long long al = f2_dup(sA[sg + 16 * m]);
#pragma unroll
            for (int j = 0; j < 4; j++) o2[m][j] = f2_mul(o2[m][j], al);
        }
#pragma unroll 4
        for (int c = 0; c < BKV; c++) {
            unsigned long long v2[4];
#pragma unroll
            for (int j = 0; j < 4; j++)
                v2[j] = *(const unsigned long long*)(sKV + c * QPAD + sc4 * 2 + 32 * j);
#pragma unroll
            for (int m = 0; m < 4; m++) {
                unsigned long long p2 = f2_dup(sP[(sg + 16 * m) * PPAD + c]);
#pragma unroll
                for (int j = 0; j < 4; j++)
                    o2[m][j] = f2_fma(p2, v2[j], o2[m][j]);
            }
        }
    }

    // ---- finalize: divide by l, write (b,s,h,d) ----
#pragma unroll
    for (int m = 0; m < 4; m++) {
        int row = sg + 16 * m;
        unsigned long long li = f2_dup(1.0f / sL[row]);
        float* Orow = O + ((size_t)(b * S_LEN + q0 + row) * NH + h) * HD;
#pragma unroll
        for (int j = 0; j < 4; j++) {
            float2 f = f2_unpack(f2_mul(o2[m][j], li));
            *(float2*)(Orow + sc4 * 2 + 32 * j) = f;
        }
    }
}

// ---------------------------------------------------------------------------
// Launch: QKV GEMMs -> RoPE -> attention -> output GEMM
// Inputs (metadata order): hidden_states, wq, wk, wv, wo, attention_mask,
// position_ids. attention_mask is pure causal -> handled analytically.
// ---------------------------------------------------------------------------
extern "C" void kernel_launch(void* const* d_in, const int* in_sizes, int n_in,
                              void* d_out, int out_size)
{
    const float* hs = (const float*)d_in[0];
    const float* wq = (const float*)d_in[1];
    const float* wk = (const float*)d_in[2];
    const float* wv = (const float*)d_in[3];
    const float* wo = (const float*)d_in[4];
    const int*  pos = (const int*)  d_in[6];
    float*      out = (float*)d_out;

    float *q, *k, *v, *ao;
    cudaGetSymbolAddress((void**)&q,  g_q);
    cudaGetSymbolAddress((void**)&k,  g_k);
    cudaGetSymbolAddress((void**)&v,  g_v);
    cudaGetSymbolAddress((void**)&ao, g_ao);

    const int smem_attn = (BQ * QPAD * 2 + BQ * PPAD + 3 * BQ) * (int)sizeof(float);
    cudaFuncSetAttribute(attn_kernel, cudaFuncAttributeMaxDynamicSharedMemorySize, smem_attn);

    // Q/K/V projections
    gemm_nt_kernel<<<dim3((NH  * HD) / GBN, MROWS / GBM), 256>>>(hs, wq, q, MROWS, NH  * HD, HID);
    gemm_nt_kernel<<<dim3((NKV * HD) / GBN, MROWS / GBM), 256>>>(hs, wk, k, MROWS, NKV * HD, HID);
    gemm_nt_kernel<<<dim3((NKV * HD) / GBN, MROWS / GBM), 256>>>(hs, wv, v, MROWS, NKV * HD, HID);

    // RoPE on q, k
    rope_kernel<<<MROWS, 256>>>(q, k, pos);

    // Causal flash attention (writes (b,s,h,d) == (b,s,NH*HD))
    attn_kernel<<<dim3(S_LEN / BQ, NH, B_SZ), 256, smem_attn>>>(q, k, v, ao);

    // Output projection
    gemm_nt_kernel<<<dim3(HID / GBN, MROWS / GBM), 256>>>(ao, wo, out, MROWS, HID, NH * HD);
}

// round 3
// speedup vs baseline: 1.2001x; 1.2001x over previous
#include <cuda_runtime.h>
#include <cuda_bf16.h>
#include <cstdint>

// Problem constants (fixed shapes)
#define NH    32
#define NKV   8
#define HD    128
#define S_LEN 2048
#define B_SZ  2
#define HID   4096
#define MROWS (B_SZ * S_LEN)   // 4096
#define NREP  (NH / NKV)       // 4

// ---------------------------------------------------------------------------
// Scratch (device globals; allocation-free per harness rules)
// ---------------------------------------------------------------------------
__device__ float g_q [(size_t)MROWS * NH  * HD];
__device__ float g_k [(size_t)MROWS * NKV * HD];
__device__ float g_v [(size_t)MROWS * NKV * HD];
__device__ float g_ao[(size_t)MROWS * NH  * HD];

// ---------------------------------------------------------------------------
// Packed f32x2 helpers (attention kernel)
// ---------------------------------------------------------------------------
__device__ __forceinline__ unsigned long long f2_fma(unsigned long long a,
                                                     unsigned long long b,
                                                     unsigned long long c) {
    unsigned long long d;
    asm("fma.rn.f32x2 %0, %1, %2, %3;" : "=l"(d) : "l"(a), "l"(b), "l"(c));
    return d;
}
__device__ __forceinline__ unsigned long long f2_mul(unsigned long long a,
                                                     unsigned long long b) {
    unsigned long long d;
    asm("mul.rn.f32x2 %0, %1, %2;" : "=l"(d) : "l"(a), "l"(b));
    return d;
}
__device__ __forceinline__ unsigned long long f2_dup(float a) {
    unsigned long long d;
    asm("mov.b64 %0, {%1, %1};" : "=l"(d) : "f"(a));
    return d;
}
__device__ __forceinline__ float2 f2_unpack(unsigned long long v) {
    float2 r;
    asm("mov.b64 {%0, %1}, %2;" : "=f"(r.x), "=f"(r.y) : "l"(v));
    return r;
}

// ---------------------------------------------------------------------------
// Helpers for mma.sync GEMM (no 'a'-suffix features: sm_80-level PTX only)
// ---------------------------------------------------------------------------
__device__ __forceinline__ uint32_t smem_u32(const void* p) {
    uint32_t a;
    asm("{ .reg .u64 t; cvta.to.shared.u64 t, %1; cvt.u32.u64 %0, t; }"
        : "=r"(a) : "l"(p));
    return a;
}
__device__ __forceinline__ uint32_t pack_bf16x2(float a, float b) {
    __nv_bfloat162 h = __floats2bfloat162_rn(a, b);
    return *reinterpret_cast<uint32_t*>(&h);
}
// ldmatrix.x4 of a 16-row x 32B region (two 16B chunks per row), XOR-swizzled.
// Rows are 128B wide (8 chunks of 16B); chunk' = chunk ^ (row & 7).
__device__ __forceinline__ void ldm_x4(uint32_t* r, uint32_t base, int row0, int c0) {
    const int l  = (int)(threadIdx.x & 31);
    const int rr = row0 + (l & 15);
    const int cc = (c0 + (l >> 4)) ^ (rr & 7);
    const uint32_t addr = base + (uint32_t)(rr * 128 + cc * 16);
    asm volatile("ldmatrix.sync.aligned.m8n8.x4.shared.b16 {%0,%1,%2,%3}, [%4];"
                 : "=r"(r[0]), "=r"(r[1]), "=r"(r[2]), "=r"(r[3]) : "r"(addr));
}
__device__ __forceinline__ void mma_bf16(float* d, const uint32_t* a,
                                         uint32_t b0, uint32_t b1) {
    asm volatile(
        "mma.sync.aligned.m16n8k16.row.col.f32.bf16.bf16.f32 "
        "{%0,%1,%2,%3}, {%4,%5,%6,%7}, {%8,%9}, {%0,%1,%2,%3};"
        : "+f"(d[0]), "+f"(d[1]), "+f"(d[2]), "+f"(d[3])
        : "r"(a[0]), "r"(a[1]), "r"(a[2]), "r"(a[3]), "r"(b0), "r"(b1));
}
// Split 8 floats into hi/lo bf16 chunks (16B each)
__device__ __forceinline__ void split8(float4 x0, float4 x1, uint4& hi, uint4& lo) {
    float xs[8] = {x0.x, x0.y, x0.z, x0.w, x1.x, x1.y, x1.z, x1.w};
    float hf[8], lf[8];
#pragma unroll
    for (int t = 0; t < 8; t++) {
        __nv_bfloat16 h = __float2bfloat16(xs[t]);
        hf[t] = __bfloat162float(h);
        lf[t] = xs[t] - hf[t];
    }
    hi.x = pack_bf16x2(hf[0], hf[1]); hi.y = pack_bf16x2(hf[2], hf[3]);
    hi.z = pack_bf16x2(hf[4], hf[5]); hi.w = pack_bf16x2(hf[6], hf[7]);
    lo.x = pack_bf16x2(lf[0], lf[1]); lo.y = pack_bf16x2(lf[2], lf[3]);
    lo.z = pack_bf16x2(lf[4], lf[5]); lo.w = pack_bf16x2(lf[6], lf[7]);
}

// ---------------------------------------------------------------------------
// GEMM: C[M,N] = A[M,K] * B[N,K]^T  (fp32 in/out, bf16 hi/lo x3 via mma.sync)
// Tile 128x128x64, 256 threads = 8 warps (2 M x 4 N), warp tile 64x32.
// Double-buffered smem; LDG for chunk ch+1 register-staged during compute.
// ---------------------------------------------------------------------------
#define TBM 128
#define TBN 128
#define TBK 64
#define OFF_AH 0
#define OFF_AL 16384
#define OFF_BH 32768
#define OFF_BL 49152
#define STAGE_BYTES 65536
#define GEMM_SMEM (2 * STAGE_BYTES)

__global__ __launch_bounds__(256) void gemm_mma_kernel(
    const float* __restrict__ A, const float* __restrict__ Bm,
    float* __restrict__ C, int M, int N, int K)
{
    extern __shared__ __align__(1024) char smem[];
    const uint32_t sbase = smem_u32(smem);
    const int tid  = threadIdx.x;
    const int lane = tid & 31;
    const int wid  = tid >> 5;
    const int wm   = wid & 1;        // 0..1  -> warp rows [wm*64, +64)
    const int wn   = wid >> 1;       // 0..3  -> warp cols [wn*32, +32)
    const int m0   = blockIdx.y * TBM;
    const int n0   = blockIdx.x * TBN;

    // gmem staging coords: thread -> (row = tid/2, 32 consecutive k floats)
    const int lrow = tid >> 1;              // 0..127
    const int lkof = (tid & 1) * 32;        // 0 or 32
    const float* Ag = A  + (size_t)(m0 + lrow) * K + lkof;
    const float* Bg = Bm + (size_t)(n0 + lrow) * K + lkof;

    float4 ra[8], rb[8];
    float acc[4][4][4];
#pragma unroll
    for (int i = 0; i < 4; i++)
#pragma unroll
        for (int j = 0; j < 4; j++)
#pragma unroll
            for (int t = 0; t < 4; t++) acc[i][j][t] = 0.0f;

    const int nch = K / TBK;

    // ---- prologue: load + convert + store chunk 0 ----
#pragma unroll
    for (int j = 0; j < 8; j++) {
        ra[j] = *(const float4*)(Ag + j * 4);
        rb[j] = *(const float4*)(Bg + j * 4);
    }
    {
        char* stg = smem;   // stage 0
#pragma unroll
        for (int p = 0; p < 4; p++) {
            const int c    = (tid & 1) * 4 + p;
            const int coff = lrow * 128 + (c ^ (lrow & 7)) * 16;
            uint4 hi, lo;
            split8(ra[2 * p], ra[2 * p + 1], hi, lo);
            *(uint4*)(stg + OFF_AH + coff) = hi;
            *(uint4*)(stg + OFF_AL + coff) = lo;
            split8(rb[2 * p], rb[2 * p + 1], hi, lo);
            *(uint4*)(stg + OFF_BH + coff) = hi;
            *(uint4*)(stg + OFF_BL + coff) = lo;
        }
    }
    __syncthreads();

    for (int ch = 0; ch < nch; ch++) {
        const int s = ch & 1;
        // prefetch next chunk into registers (hidden by the MMA work below)
        if (ch + 1 < nch) {
            const int k1 = (ch + 1) * TBK;
#pragma unroll
            for (int j = 0; j < 8; j++) {
                ra[j] = *(const float4*)(Ag + k1 + j * 4);
                rb[j] = *(const float4*)(Bg + k1 + j * 4);
            }
        }

        // ---- compute from stage s ----
        const uint32_t stAh = sbase + s * STAGE_BYTES + OFF_AH;
        const uint32_t stAl = sbase + s * STAGE_BYTES + OFF_AL;
        const uint32_t stBh = sbase + s * STAGE_BYTES + OFF_BH;
        const uint32_t stBl = sbase + s * STAGE_BYTES + OFF_BL;
#pragma unroll
        for (int kt = 0; kt < 4; kt++) {
            uint32_t ah[4][4], al[4][4], bh[2][4], bl[2][4];
#pragma unroll
            for (int mt = 0; mt < 4; mt++) {
                ldm_x4(ah[mt], stAh, wm * 64 + mt * 16, kt * 2);
                ldm_x4(al[mt], stAl, wm * 64 + mt * 16, kt * 2);
            }
#pragma unroll
            for (int bp = 0; bp < 2; bp++) {
                ldm_x4(bh[bp], stBh, wn * 32 + bp * 16, kt * 2);
                ldm_x4(bl[bp], stBl, wn * 32 + bp * 16, kt * 2);
            }
            // region regs: r0 = even tile b0, r1 = odd tile b0, r2/r3 = b1s
#pragma unroll
            for (int mt = 0; mt < 4; mt++)
#pragma unroll
                for (int nt = 0; nt < 4; nt++) {
                    const int bp = nt >> 1, o = nt & 1;
                    mma_bf16(acc[mt][nt], ah[mt], bh[bp][o], bh[bp][o + 2]);  // hh
                    mma_bf16(acc[mt][nt], ah[mt], bl[bp][o], bl[bp][o + 2]);  // hl
                    mma_bf16(acc[mt][nt], al[mt], bh[bp][o], bh[bp][o + 2]);  // lh
                }
        }

        // ---- convert + store next chunk into the other stage ----
        if (ch + 1 < nch) {
            char* stg = smem + ((ch + 1) & 1) * STAGE_BYTES;
#pragma unroll
            for (int p = 0; p < 4; p++) {
                const int c    = (tid & 1) * 4 + p;
                const int coff = lrow * 128 + (c ^ (lrow & 7)) * 16;
                uint4 hi, lo;
                split8(ra[2 * p], ra[2 * p + 1], hi, lo);
                *(uint4*)(stg + OFF_AH + coff) = hi;
                *(uint4*)(stg + OFF_AL + coff) = lo;
                split8(rb[2 * p], rb[2 * p + 1], hi, lo);
                *(uint4*)(stg + OFF_BH + coff) = hi;
                *(uint4*)(stg + OFF_BL + coff) = lo;
            }
        }
        __syncthreads();
    }

    // ---- epilogue: write C ----
#pragma unroll
    for (int mt = 0; mt < 4; mt++) {
        const int row = m0 + wm * 64 + mt * 16 + (lane >> 2);
#pragma unroll
        for (int nt = 0; nt < 4; nt++) {
            const int col = n0 + wn * 32 + nt * 8 + (lane & 3) * 2;
            float2 v0 = make_float2(acc[mt][nt][0], acc[mt][nt][1]);
            float2 v1 = make_float2(acc[mt][nt][2], acc[mt][nt][3]);
            *(float2*)(C + (size_t)row * N + col)       = v0;
            *(float2*)(C + (size_t)(row + 8) * N + col) = v1;
        }
    }
}

// ---------------------------------------------------------------------------
// RoPE (in place on q and k)
// ---------------------------------------------------------------------------
__global__ void rope_kernel(float* __restrict__ q, float* __restrict__ k,
                            const int* __restrict__ pos)
{
    const int bs = blockIdx.x;
    const float p = (float)pos[bs];
    const float c1 = -0.2076205059304601f;        // -log2(10000)/64
    for (int i = threadIdx.x; i < (NH + NKV) * 64; i += blockDim.x) {
        float* base; int d;
        if (i < NH * 64) {
            int hh = i >> 6; d = i & 63;
            base = q + ((size_t)bs * NH + hh) * HD;
        } else {
            int j = i - NH * 64;
            int hh = j >> 6; d = j & 63;
            base = k + ((size_t)bs * NKV + hh) * HD;
        }
        float inv = exp2f(c1 * (float)d);
        float ang = p * inv;
        float sv, cv;
        sincosf(ang, &sv, &cv);
        float x1 = base[d], x2 = base[d + 64];
        base[d]      = x1 * cv - x2 * sv;
        base[d + 64] = x2 * cv + x1 * sv;
    }
}

// ---------------------------------------------------------------------------
// Flash attention, fp32, causal. 64x64 tiles, 256 threads. (proven R1 kernel)
// ---------------------------------------------------------------------------
#define BQ   64
#define BKV  64
#define QPAD 130
#define PPAD 65

__global__ __launch_bounds__(256) void attn_kernel(
    const float* __restrict__ Q, const float* __restrict__ K,
    const float* __restrict__ V, float* __restrict__ O)
{
    extern __shared__ __align__(16) float sm[];
    float* sQ  = sm;
    float* sKV = sQ  + BQ * QPAD;
    float* sP  = sKV + BKV * QPAD;
    float* sM  = sP  + BQ * PPAD;
    float* sL  = sM  + BQ;
    float* sA  = sL  + BQ;

    const int qb  = (int)gridDim.x - 1 - (int)blockIdx.x;
    const int h   = blockIdx.y, b = blockIdx.z;
    const int g   = h / NREP;
    const int tid = threadIdx.x;
    const int q0  = qb * BQ;
    const int sg  = tid >> 4;
    const int sc4 = tid & 15;

    for (int i = tid; i < BQ * (HD / 4); i += 256) {
        int row = i >> 5;
        int c4  = (i & 31) << 2;
        float4 v4 = *(const float4*)(Q + ((size_t)(b * S_LEN + q0 + row) * NH + h) * HD + c4);
        float* dst = sQ + row * QPAD + c4;
        dst[0] = v4.x; dst[1] = v4.y; dst[2] = v4.z; dst[3] = v4.w;
    }
    if (tid < BQ) { sM[tid] = -1e30f; sL[tid] = 0.0f; }

    unsigned long long o2[4][4];
#pragma unroll
    for (int m = 0; m < 4; m++)
#pragma unroll
        for (int j = 0; j < 4; j++) o2[m][j] = 0ull;

    const float scale = 0.08838834764831845f;
    const int nkv = qb + 1;

    for (int kb = 0; kb < nkv; kb++) {
        const int k0 = kb * BKV;
        __syncthreads();
        for (int i = tid; i < BKV * (HD / 4); i += 256) {
            int row = i >> 5;
            int c4  = (i & 31) << 2;
            float4 v4 = *(const float4*)(K + ((size_t)(b * S_LEN + k0 + row) * NKV + g) * HD + c4);
            float* dst = sKV + row * QPAD + c4;
            dst[0] = v4.x; dst[1] = v4.y; dst[2] = v4.z; dst[3] = v4.w;
        }
        __syncthreads();

        unsigned long long s2[4][4];
#pragma unroll
        for (int ii = 0; ii < 4; ii++)
#pragma unroll
            for (int jj = 0; jj < 4; jj++) s2[ii][jj] = 0ull;

#pragma unroll 8
        for (int d = 0; d < HD; d += 2) {
            unsigned long long q2[4], k2[4];
#pragma unroll
            for (int ii = 0; ii < 4; ii++)
                q2[ii] = *(const unsigned long long*)(sQ + (sg * 4 + ii) * QPAD + d);
#pragma unroll
            for (int jj = 0; jj < 4; jj++)
                k2[jj] = *(const unsigned long long*)(sKV + (sc4 * 4 + jj) * QPAD + d);
#pragma unroll
            for (int ii = 0; ii < 4; ii++)
#pragma unroll
                for (int jj = 0; jj < 4; jj++)
                    s2[ii][jj] = f2_fma(q2[ii], k2[jj], s2[ii][jj]);
        }

#pragma unroll
        for (int ii = 0; ii < 4; ii++) {
            const int row = sg * 4 + ii;
            const int rg  = q0 + row;
            float sc[4];
#pragma unroll
            for (int jj = 0; jj < 4; jj++) {
                float2 f = f2_unpack(s2[ii][jj]);
                float v  = (f.x + f.y) * scale;
                int cg = k0 + sc4 * 4 + jj;
                sc[jj] = (cg > rg) ? -1e30f : v;
            }
            float rmax = fmaxf(fmaxf(sc[0], sc[1]), fmaxf(sc[2], sc[3]));
#pragma unroll
            for (int off = 1; off < 16; off <<= 1)
                rmax = fmaxf(rmax, __shfl_xor_sync(0xffffffffu, rmax, off));
            float mold = sM[row];
            float mnew = fmaxf(mold, rmax);
            float p[4], psum = 0.0f;
#pragma unroll
            for (int jj = 0; jj < 4; jj++) { p[jj] = __expf(sc[jj] - mnew); psum += p[jj]; }
#pragma unroll
            for (int off = 1; off < 16; off <<= 1)
                psum += __shfl_xor_sync(0xffffffffu, psum, off);
            if (sc4 == 0) {
                float alpha = __expf(mold - mnew);
                sM[row] = mnew;
                sL[row] = sL[row] * alpha + psum;
                sA[row] = alpha;
            }
#pragma unroll
            for (int jj = 0; jj < 4; jj++)
                sP[row * PPAD + sc4 * 4 + jj] = p[jj];
        }
        __syncthreads();

        for (int i = tid; i < BKV * (HD / 4); i += 256) {
            int row = i >> 5;
            int c4  = (i & 31) << 2;
            float4 v4 = *(const float4*)(V + ((size_t)(b * S_LEN + k0 + row) * NKV + g) * HD + c4);
            float* dst = sKV + row * QPAD + c4;
            dst[0] = v4.x; dst[1] = v4.y; dst[2] = v4.z; dst[3] = v4.w;
        }
        __syncthreads();

#pragma unroll
        for (int m = 0; m < 4; m++) {
            unsigned long long al = f2_dup(sA[sg + 16 * m]);
#pragma unroll
            for (int j = 0; j < 4; j++) o2[m][j] = f2_mul(o2[m][j], al);
        }
#pragma unroll 4
        for (int c = 0; c < BKV; c++) {
            unsigned long long v2[4];
#pragma unroll
            for (int j = 0; j < 4; j++)
                v2[j] = *(const unsigned long long*)(sKV + c * QPAD + sc4 * 2 + 32 * j);
#pragma unroll
            for (int m = 0; m < 4; m++) {
                unsigned long long p2 = f2_dup(sP[(sg + 16 * m) * PPAD + c]);
#pragma unroll
                for (int j = 0; j < 4; j++)
                    o2[m][j] = f2_fma(p2, v2[j], o2[m][j]);
            }
        }
    }

#pragma unroll
    for (int m = 0; m < 4; m++) {
        int row = sg + 16 * m;
        unsigned long long li = f2_dup(1.0f / sL[row]);
        float* Orow = O + ((size_t)(b * S_LEN + q0 + row) * NH + h) * HD;
#pragma unroll
        for (int j = 0; j < 4; j++) {
            float2 f = f2_unpack(f2_mul(o2[m][j], li));
            *(float2*)(Orow + sc4 * 2 + 32 * j) = f;
        }
    }
}

// ---------------------------------------------------------------------------
// Launch
// ---------------------------------------------------------------------------
extern "C" void kernel_launch(void* const* d_in, const int* in_sizes, int n_in,
                              void* d_out, int out_size)
{
    const float* hs = (const float*)d_in[0];
    const float* wq = (const float*)d_in[1];
    const float* wk = (const float*)d_in[2];
    const float* wv = (const float*)d_in[3];
    const float* wo = (const float*)d_in[4];
    const int*  pos = (const int*)  d_in[6];
    float*      out = (float*)d_out;

    float *q, *k, *v, *ao;
    cudaGetSymbolAddress((void**)&q,  g_q);
    cudaGetSymbolAddress((void**)&k,  g_k);
    cudaGetSymbolAddress((void**)&v,  g_v);
    cudaGetSymbolAddress((void**)&ao, g_ao);

    cudaFuncSetAttribute(gemm_mma_kernel, cudaFuncAttributeMaxDynamicSharedMemorySize, GEMM_SMEM);
    const int smem_attn = (BQ * QPAD * 2 + BQ * PPAD + 3 * BQ) * (int)sizeof(float);
    cudaFuncSetAttribute(attn_kernel, cudaFuncAttributeMaxDynamicSharedMemorySize, smem_attn);

    // Q/K/V projections (mma.sync bf16x3)
    gemm_mma_kernel<<<dim3((NH  * HD) / TBN, MROWS / TBM), 256, GEMM_SMEM>>>(hs, wq, q, MROWS, NH  * HD, HID);
    gemm_mma_kernel<<<dim3((NKV * HD) / TBN, MROWS / TBM), 256, GEMM_SMEM>>>(hs, wk, k, MROWS, NKV * HD, HID);
    gemm_mma_kernel<<<dim3((NKV * HD) / TBN, MROWS / TBM), 256, GEMM_SMEM>>>(hs, wv, v, MROWS, NKV * HD, HID);

    // RoPE on q, k
    rope_kernel<<<MROWS, 256>>>(q, k, pos);

    // Causal flash attention
    attn_kernel<<<dim3(S_LEN / BQ, NH, B_SZ), 256, smem_attn>>>(q, k, v, ao);

    // Output projection (mma.sync bf16x3)
    gemm_mma_kernel<<<dim3(HID / TBN, MROWS / TBM), 256, GEMM_SMEM>>>(ao, wo, out, MROWS, HID, NH * HD);
}

// round 4
// speedup vs baseline: 1.5612x; 1.3008x over previous
#include <cuda_runtime.h>
#include <cuda_bf16.h>
#include <cstdint>

// Problem constants (fixed shapes)
#define NH    32
#define NKV   8
#define HD    128
#define S_LEN 2048
#define B_SZ  2
#define HID   4096
#define MROWS (B_SZ * S_LEN)   // 4096
#define NREP  (NH / NKV)       // 4

#define E16M (16u * 1024u * 1024u)   // 16M elements
#define E4M  (4u  * 1024u * 1024u)

// ---------------------------------------------------------------------------
// Scratch (device globals; allocation-free per harness rules)
// ---------------------------------------------------------------------------
__device__ float g_q [(size_t)MROWS * NH  * HD];
__device__ float g_k [(size_t)MROWS * NKV * HD];
__device__ float g_v [(size_t)MROWS * NKV * HD];
__device__ float g_ao[(size_t)MROWS * NH  * HD];

// bf16 hi/lo copies (pre-converted once per call)
__device__ __nv_bfloat16 g_hs_h[E16M], g_hs_l[E16M];
__device__ __nv_bfloat16 g_wq_h[E16M], g_wq_l[E16M];
__device__ __nv_bfloat16 g_wk_h[E4M],  g_wk_l[E4M];
__device__ __nv_bfloat16 g_wv_h[E4M],  g_wv_l[E4M];
__device__ __nv_bfloat16 g_wo_h[E16M], g_wo_l[E16M];
__device__ __nv_bfloat16 g_ao_h[E16M], g_ao_l[E16M];

// ---------------------------------------------------------------------------
// Packed f32x2 helpers (attention kernel)
// ---------------------------------------------------------------------------
__device__ __forceinline__ unsigned long long f2_fma(unsigned long long a,
                                                     unsigned long long b,
                                                     unsigned long long c) {
    unsigned long long d;
    asm("fma.rn.f32x2 %0, %1, %2, %3;" : "=l"(d) : "l"(a), "l"(b), "l"(c));
    return d;
}
__device__ __forceinline__ unsigned long long f2_mul(unsigned long long a,
                                                     unsigned long long b) {
    unsigned long long d;
    asm("mul.rn.f32x2 %0, %1, %2;" : "=l"(d) : "l"(a), "l"(b));
    return d;
}
__device__ __forceinline__ unsigned long long f2_dup(float a) {
    unsigned long long d;
    asm("mov.b64 %0, {%1, %1};" : "=l"(d) : "f"(a));
    return d;
}
__device__ __forceinline__ float2 f2_unpack(unsigned long long v) {
    float2 r;
    asm("mov.b64 {%0, %1}, %2;" : "=f"(r.x), "=f"(r.y) : "l"(v));
    return r;
}

// ---------------------------------------------------------------------------
// Common helpers (sm_80-level PTX only; no 'a'-suffix features)
// ---------------------------------------------------------------------------
__device__ __forceinline__ uint32_t smem_u32(const void* p) {
    uint32_t a;
    asm("{ .reg .u64 t; cvta.to.shared.u64 t, %1; cvt.u32.u64 %0, t; }"
        : "=r"(a) : "l"(p));
    return a;
}
__device__ __forceinline__ uint32_t pack_bf16x2(float a, float b) {
    __nv_bfloat162 h = __floats2bfloat162_rn(a, b);
    return *reinterpret_cast<uint32_t*>(&h);
}
__device__ __forceinline__ void cp16(uint32_t saddr, const void* gptr) {
    asm volatile("cp.async.cg.shared.global [%0], [%1], 16;"
                 :: "r"(saddr), "l"(gptr));
}
__device__ __forceinline__ void cp_commit() {
    asm volatile("cp.async.commit_group;" ::: "memory");
}
template <int N>
__device__ __forceinline__ void cp_wait() {
    asm volatile("cp.async.wait_group %0;" :: "n"(N) : "memory");
}
// ldmatrix.x4 of a 16-row x 32B region (two 16B chunks per row), XOR-swizzled.
// Rows are 128B wide (8 chunks of 16B); chunk' = chunk ^ (row & 7).
__device__ __forceinline__ void ldm_x4(uint32_t* r, uint32_t base, int row0, int c0) {
    const int l  = (int)(threadIdx.x & 31);
    const int rr = row0 + (l & 15);
    const int cc = (c0 + (l >> 4)) ^ (rr & 7);
    const uint32_t addr = base + (uint32_t)(rr * 128 + cc * 16);
    asm volatile("ldmatrix.sync.aligned.m8n8.x4.shared.b16 {%0,%1,%2,%3}, [%4];"
                 : "=r"(r[0]), "=r"(r[1]), "=r"(r[2]), "=r"(r[3]) : "r"(addr));
}
__device__ __forceinline__ void mma_bf16(float* d, const uint32_t* a,
                                         uint32_t b0, uint32_t b1) {
    asm volatile(
        "mma.sync.aligned.m16n8k16.row.col.f32.bf16.bf16.f32 "
        "{%0,%1,%2,%3}, {%4,%5,%6,%7}, {%8,%9}, {%0,%1,%2,%3};"
        : "+f"(d[0]), "+f"(d[1]), "+f"(d[2]), "+f"(d[3])
        : "r"(a[0]), "r"(a[1]), "r"(a[2]), "r"(a[3]), "r"(b0), "r"(b1));
}

// ---------------------------------------------------------------------------
// fp32 -> bf16 hi/lo conversion (elementwise, vectorized)
// ---------------------------------------------------------------------------
__global__ __launch_bounds__(256) void cvt_kernel(
    const float4* __restrict__ x, uint2* __restrict__ hi,
    uint2* __restrict__ lo, int n4)
{
    int i = blockIdx.x * blockDim.x + threadIdx.x;
    if (i >= n4) return;
    float4 f = x[i];
    float xs[4] = {f.x, f.y, f.z, f.w};
    float hf[4], lf[4];
#pragma unroll
    for (int t = 0; t < 4; t++) {
        __nv_bfloat16 h = __float2bfloat16(xs[t]);
        hf[t] = __bfloat162float(h);
        lf[t] = xs[t] - hf[t];
    }
    uint2 H, L;
    H.x = pack_bf16x2(hf[0], hf[1]); H.y = pack_bf16x2(hf[2], hf[3]);
    L.x = pack_bf16x2(lf[0], lf[1]); L.y = pack_bf16x2(lf[2], lf[3]);
    hi[i] = H;
    lo[i] = L;
}

// ---------------------------------------------------------------------------
// GEMM: C[M,N] = A[M,K] * B[N,K]^T  (bf16 hi/lo inputs x3 MMAs, fp32 out)
// Tile 128x128x64, 256 threads = 8 warps (2 M x 4 N), warp tile 64x32.
// cp.async double-buffered smem; no register staging, no in-loop conversion.
// ---------------------------------------------------------------------------
#define TBM 128
#define TBN 128
#define TBK 64
#define OFF_AH 0
#define OFF_AL 16384
#define OFF_BH 32768
#define OFF_BL 49152
#define STAGE_BYTES 65536
#define GEMM_SMEM (2 * STAGE_BYTES)

__global__ __launch_bounds__(256) void gemm_mma_kernel(
    const __nv_bfloat16* __restrict__ Ah, const __nv_bfloat16* __restrict__ Al,
    const __nv_bfloat16* __restrict__ Bh, const __nv_bfloat16* __restrict__ Bl,
    float* __restrict__ C, int M, int N, int K)
{
    extern __shared__ __align__(1024) char smem[];
    const uint32_t sbase = smem_u32(smem);
    const int tid  = threadIdx.x;
    const int lane = tid & 31;
    const int wid  = tid >> 5;
    const int wm   = wid & 1;        // warp rows [wm*64, +64)
    const int wn   = wid >> 1;       // warp cols [wn*32, +32)
    const int m0   = blockIdx.y * TBM;
    const int n0   = blockIdx.x * TBN;

    // copy coords: thread -> (row = tid/2, 4 chunks of 8 bf16)
    const int lrow = tid >> 1;              // 0..127
    const int cbase = (tid & 1) * 4;        // chunk 0..3 or 4..7

    float acc[4][4][4];
#pragma unroll
    for (int i = 0; i < 4; i++)
#pragma unroll
        for (int j = 0; j < 4; j++)
#pragma unroll
            for (int t = 0; t < 4; t++) acc[i][j][t] = 0.0f;

    const int nch = K / TBK;

    auto issue = [&](int s, int k0) {
        const uint32_t st = sbase + s * STAGE_BYTES;
        const size_t ga = (size_t)(m0 + lrow) * K + k0;
        const size_t gb = (size_t)(n0 + lrow) * K + k0;
#pragma unroll
        for (int p = 0; p < 4; p++) {
            const int c    = cbase + p;
            const uint32_t coff = (uint32_t)(lrow * 128 + ((c ^ (lrow & 7)) * 16));
            const size_t eo = (size_t)c * 8;   // 8 bf16 per 16B chunk
            cp16(st + OFF_AH + coff, Ah + ga + eo);
            cp16(st + OFF_AL + coff, Al + ga + eo);
            cp16(st + OFF_BH + coff, Bh + gb + eo);
            cp16(st + OFF_BL + coff, Bl + gb + eo);
        }
        cp_commit();
    };

    issue(0, 0);

    for (int ch = 0; ch < nch; ch++) {
        const int s = ch & 1;
        if (ch + 1 < nch) {
            issue(1 - s, (ch + 1) * TBK);
            cp_wait<1>();
        } else {
            cp_wait<0>();
        }
        __syncthreads();

        const uint32_t stAh = sbase + s * STAGE_BYTES + OFF_AH;
        const uint32_t stAl = sbase + s * STAGE_BYTES + OFF_AL;
        const uint32_t stBh = sbase + s * STAGE_BYTES + OFF_BH;
        const uint32_t stBl = sbase + s * STAGE_BYTES + OFF_BL;
#pragma unroll
        for (int kt = 0; kt < 4; kt++) {
            uint32_t ah[4][4], al[4][4], bh[2][4], bl[2][4];
#pragma unroll
            for (int mt = 0; mt < 4; mt++) {
                ldm_x4(ah[mt], stAh, wm * 64 + mt * 16, kt * 2);
                ldm_x4(al[mt], stAl, wm * 64 + mt * 16, kt * 2);
            }
#pragma unroll
            for (int bp = 0; bp < 2; bp++) {
                ldm_x4(bh[bp], stBh, wn * 32 + bp * 16, kt * 2);
                ldm_x4(bl[bp], stBl, wn * 32 + bp * 16, kt * 2);
            }
#pragma unroll
            for (int mt = 0; mt < 4; mt++)
#pragma unroll
                for (int nt = 0; nt < 4; nt++) {
                    const int bp = nt >> 1, o = nt & 1;
                    mma_bf16(acc[mt][nt], ah[mt], bh[bp][o], bh[bp][o + 2]);  // hh
                    mma_bf16(acc[mt][nt], ah[mt], bl[bp][o], bl[bp][o + 2]);  // hl
                    mma_bf16(acc[mt][nt], al[mt], bh[bp][o], bh[bp][o + 2]);  // lh
                }
        }
        __syncthreads();
    }

    // ---- epilogue: write C ----
#pragma unroll
    for (int mt = 0; mt < 4; mt++) {
        const int row = m0 + wm * 64 + mt * 16 + (lane >> 2);
#pragma unroll
        for (int nt = 0; nt < 4; nt++) {
            const int col = n0 + wn * 32 + nt * 8 + (lane & 3) * 2;
            float2 v0 = make_float2(acc[mt][nt][0], acc[mt][nt][1]);
            float2 v1 = make_float2(acc[mt][nt][2], acc[mt][nt][3]);
            *(float2*)(C + (size_t)row * N + col)       = v0;
            *(float2*)(C + (size_t)(row + 8) * N + col) = v1;
        }
    }
}

// ---------------------------------------------------------------------------
// RoPE (in place on q and k)
// ---------------------------------------------------------------------------
__global__ void rope_kernel(float* __restrict__ q, float* __restrict__ k,
                            const int* __restrict__ pos)
{
    const int bs = blockIdx.x;
    const float p = (float)pos[bs];
    const float c1 = -0.2076205059304601f;        // -log2(10000)/64
    for (int i = threadIdx.x; i < (NH + NKV) * 64; i += blockDim.x) {
        float* base; int d;
        if (i < NH * 64) {
            int hh = i >> 6; d = i & 63;
            base = q + ((size_t)bs * NH + hh) * HD;
        } else {
            int j = i - NH * 64;
            int hh = j >> 6; d = j & 63;
            base = k + ((size_t)bs * NKV + hh) * HD;
        }
        float inv = exp2f(c1 * (float)d);
        float ang = p * inv;
        float sv, cv;
        sincosf(ang, &sv, &cv);
        float x1 = base[d], x2 = base[d + 64];
        base[d]      = x1 * cv - x2 * sv;
        base[d + 64] = x2 * cv + x1 * sv;
    }
}

// ---------------------------------------------------------------------------
// Flash attention, fp32, causal. 64x64 tiles, 256 threads. (proven R1 kernel)
// ---------------------------------------------------------------------------
#define BQ   64
#define BKV  64
#define QPAD 130
#define PPAD 65

__global__ __launch_bounds__(256) void attn_kernel(
    const float* __restrict__ Q, const float* __restrict__ K,
    const float* __restrict__ V, float* __restrict__ O)
{
    extern __shared__ __align__(16) float sm[];
    float* sQ  = sm;
    float* sKV = sQ  + BQ * QPAD;
    float* sP  = sKV + BKV * QPAD;
    float* sM  = sP  + BQ * PPAD;
    float* sL  = sM  + BQ;
    float* sA  = sL  + BQ;

    const int qb  = (int)gridDim.x - 1 - (int)blockIdx.x;
    const int h   = blockIdx.y, b = blockIdx.z;
    const int g   = h / NREP;
    const int tid = threadIdx.x;
    const int q0  = qb * BQ;
    const int sg  = tid >> 4;
    const int sc4 = tid & 15;

    for (int i = tid; i < BQ * (HD / 4); i += 256) {
        int row = i >> 5;
        int c4  = (i & 31) << 2;
        float4 v4 = *(const float4*)(Q + ((size_t)(b * S_LEN + q0 + row) * NH + h) * HD + c4);
        float* dst = sQ + row * QPAD + c4;
        dst[0] = v4.x; dst[1] = v4.y; dst[2] = v4.z; dst[3] = v4.w;
    }
    if (tid < BQ) { sM[tid] = -1e30f; sL[tid] = 0.0f; }

    unsigned long long o2[4][4];
#pragma unroll
    for (int m = 0; m < 4; m++)
#pragma unroll
        for (int j = 0; j < 4; j++) o2[m][j] = 0ull;

    const float scale = 0.08838834764831845f;
    const int nkv = qb + 1;

    for (int kb = 0; kb < nkv; kb++) {
        const int k0 = kb * BKV;
        __syncthreads();
        for (int i = tid; i < BKV * (HD / 4); i += 256) {
            int row = i >> 5;
            int c4  = (i & 31) << 2;
            float4 v4 = *(const float4*)(K + ((size_t)(b * S_LEN + k0 + row) * NKV + g) * HD + c4);
            float* dst = sKV + row * QPAD + c4;
            dst[0] = v4.x; dst[1] = v4.y; dst[2] = v4.z; dst[3] = v4.w;
        }
        __syncthreads();

        unsigned long long s2[4][4];
#pragma unroll
        for (int ii = 0; ii < 4; ii++)
#pragma unroll
            for (int jj = 0; jj < 4; jj++) s2[ii][jj] = 0ull;

#pragma unroll 8
        for (int d = 0; d < HD; d += 2) {
            unsigned long long q2[4], k2[4];
#pragma unroll
            for (int ii = 0; ii < 4; ii++)
                q2[ii] = *(const unsigned long long*)(sQ + (sg * 4 + ii) * QPAD + d);
#pragma unroll
            for (int jj = 0; jj < 4; jj++)
                k2[jj] = *(const unsigned long long*)(sKV + (sc4 * 4 + jj) * QPAD + d);
#pragma unroll
            for (int ii = 0; ii < 4; ii++)
#pragma unroll
                for (int jj = 0; jj < 4; jj++)
                    s2[ii][jj] = f2_fma(q2[ii], k2[jj], s2[ii][jj]);
        }

#pragma unroll
        for (int ii = 0; ii < 4; ii++) {
            const int row = sg * 4 + ii;
            const int rg  = q0 + row;
            float sc[4];
#pragma unroll
            for (int jj = 0; jj < 4; jj++) {
                float2 f = f2_unpack(s2[ii][jj]);
                float v  = (f.x + f.y) * scale;
                int cg = k0 + sc4 * 4 + jj;
                sc[jj] = (cg > rg) ? -1e30f : v;
            }
            float rmax = fmaxf(fmaxf(sc[0], sc[1]), fmaxf(sc[2], sc[3]));
#pragma unroll
            for (int off = 1; off < 16; off <<= 1)
                rmax = fmaxf(rmax, __shfl_xor_sync(0xffffffffu, rmax, off));
            float mold = sM[row];
            float mnew = fmaxf(mold, rmax);
            float p[4], psum = 0.0f;
#pragma unroll
            for (int jj = 0; jj < 4; jj++) { p[jj] = __expf(sc[jj] - mnew); psum += p[jj]; }
#pragma unroll
            for (int off = 1; off < 16; off <<= 1)
                psum += __shfl_xor_sync(0xffffffffu, psum, off);
            if (sc4 == 0) {
                float alpha = __expf(mold - mnew);
                sM[row] = mnew;
                sL[row] = sL[row] * alpha + psum;
                sA[row] = alpha;
            }
#pragma unroll
            for (int jj = 0; jj < 4; jj++)
                sP[row * PPAD + sc4 * 4 + jj] = p[jj];
        }
        __syncthreads();

        for (int i = tid; i < BKV * (HD / 4); i += 256) {
            int row = i >> 5;
            int c4  = (i & 31) << 2;
            float4 v4 = *(const float4*)(V + ((size_t)(b * S_LEN + k0 + row) * NKV + g) * HD + c4);
            float* dst = sKV + row * QPAD + c4;
            dst[0] = v4.x; dst[1] = v4.y; dst[2] = v4.z; dst[3] = v4.w;
        }
        __syncthreads();

#pragma unroll
        for (int m = 0; m < 4; m++) {
            unsigned long long al = f2_dup(sA[sg + 16 * m]);
#pragma unroll
            for (int j = 0; j < 4; j++) o2[m][j] = f2_mul(o2[m][j], al);
        }
#pragma unroll 4
        for (int c = 0; c < BKV; c++) {
            unsigned long long v2[4];
#pragma unroll
            for (int j = 0; j < 4; j++)
                v2[j] = *(const unsigned long long*)(sKV + c * QPAD + sc4 * 2 + 32 * j);
#pragma unroll
            for (int m = 0; m < 4; m++) {
                unsigned long long p2 = f2_dup(sP[(sg + 16 * m) * PPAD + c]);
#pragma unroll
                for (int j = 0; j < 4; j++)
                    o2[m][j] = f2_fma(p2, v2[j], o2[m][j]);
            }
        }
    }

#pragma unroll
    for (int m = 0; m < 4; m++) {
        int row = sg + 16 * m;
        unsigned long long li = f2_dup(1.0f / sL[row]);
        float* Orow = O + ((size_t)(b * S_LEN + q0 + row) * NH + h) * HD;
#pragma unroll
        for (int j = 0; j < 4; j++) {
            float2 f = f2_unpack(f2_mul(o2[m][j], li));
            *(float2*)(Orow + sc4 * 2 + 32 * j) = f;
        }
    }
}

// ---------------------------------------------------------------------------
// Launch
// ---------------------------------------------------------------------------
extern "C" void kernel_launch(void* const* d_in, const int* in_sizes, int n_in,
                              void* d_out, int out_size)
{
    const float* hs = (const float*)d_in[0];
    const float* wq = (const float*)d_in[1];
    const float* wk = (const float*)d_in[2];
    const float* wv = (const float*)d_in[3];
    const float* wo = (const float*)d_in[4];
    const int*  pos = (const int*)  d_in[6];
    float*      out = (float*)d_out;

    float *q, *k, *v, *ao;
    cudaGetSymbolAddress((void**)&q,  g_q);
    cudaGetSymbolAddress((void**)&k,  g_k);
    cudaGetSymbolAddress((void**)&v,  g_v);
    cudaGetSymbolAddress((void**)&ao, g_ao);

    __nv_bfloat16 *hsh, *hsl, *wqh, *wql, *wkh, *wkl, *wvh, *wvl, *woh, *wol, *aoh, *aol;
    cudaGetSymbolAddress((void**)&hsh, g_hs_h); cudaGetSymbolAddress((void**)&hsl, g_hs_l);
    cudaGetSymbolAddress((void**)&wqh, g_wq_h); cudaGetSymbolAddress((void**)&wql, g_wq_l);
    cudaGetSymbolAddress((void**)&wkh, g_wk_h); cudaGetSymbolAddress((void**)&wkl, g_wk_l);
    cudaGetSymbolAddress((void**)&wvh, g_wv_h); cudaGetSymbolAddress((void**)&wvl, g_wv_l);
    cudaGetSymbolAddress((void**)&woh, g_wo_h); cudaGetSymbolAddress((void**)&wol, g_wo_l);
    cudaGetSymbolAddress((void**)&aoh, g_ao_h); cudaGetSymbolAddress((void**)&aol, g_ao_l);

    cudaFuncSetAttribute(gemm_mma_kernel, cudaFuncAttributeMaxDynamicSharedMemorySize, GEMM_SMEM);
    const int smem_attn = (BQ * QPAD * 2 + BQ * PPAD + 3 * BQ) * (int)sizeof(float);
    cudaFuncSetAttribute(attn_kernel, cudaFuncAttributeMaxDynamicSharedMemorySize, smem_attn);

    auto cvt = [&](const float* x, __nv_bfloat16* hi, __nv_bfloat16* lo, int n) {
        int n4 = n / 4;
        cvt_kernel<<<(n4 + 255) / 256, 256>>>((const float4*)x, (uint2*)hi, (uint2*)lo, n4);
    };

    // pre-convert inputs to bf16 hi/lo
    cvt(hs, hsh, hsl, MROWS * HID);
    cvt(wq, wqh, wql, NH * HD * HID);
    cvt(wk, wkh, wkl, NKV * HD * HID);
    cvt(wv, wvh, wvl, NKV * HD * HID);
    cvt(wo, woh, wol, HID * NH * HD);

    // Q/K/V projections (mma.sync bf16x3, cp.async pipeline)
    gemm_mma_kernel<<<dim3((NH  * HD) / TBN, MROWS / TBM), 256, GEMM_SMEM>>>(hsh, hsl, wqh, wql, q, MROWS, NH  * HD, HID);
    gemm_mma_kernel<<<dim3((NKV * HD) / TBN, MROWS / TBM), 256, GEMM_SMEM>>>(hsh, hsl, wkh, wkl, k, MROWS, NKV * HD, HID);
    gemm_mma_kernel<<<dim3((NKV * HD) / TBN, MROWS / TBM), 256, GEMM_SMEM>>>(hsh, hsl, wvh, wvl, v, MROWS, NKV * HD, HID);

    // RoPE on q, k
    rope_kernel<<<MROWS, 256>>>(q, k, pos);

    // Causal flash attention
    attn_kernel<<<dim3(S_LEN / BQ, NH, B_SZ), 256, smem_attn>>>(q, k, v, ao);

    // Convert attention output, then output projection
    cvt(ao, aoh, aol, MROWS * NH * HD);
    gemm_mma_kernel<<<dim3(HID / TBN, MROWS / TBM), 256, GEMM_SMEM>>>(aoh, aol, woh, wol, out, MROWS, HID, NH * HD);
}

// round 5
// speedup vs baseline: 2.1171x; 1.3561x over previous
#include <cuda_runtime.h>
#include <cuda_bf16.h>
#include <cstdint>

// Problem constants (fixed shapes)
#define NH    32
#define NKV   8
#define HD    128
#define S_LEN 2048
#define B_SZ  2
#define HID   4096
#define MROWS (B_SZ * S_LEN)   // 4096
#define NREP  (NH / NKV)       // 4

#define E16M (16u * 1024u * 1024u)
#define E4M  (4u  * 1024u * 1024u)

// ---------------------------------------------------------------------------
// Scratch (device globals; allocation-free per harness rules)
// ---------------------------------------------------------------------------
__device__ float g_q [(size_t)MROWS * NH  * HD];
__device__ float g_k [(size_t)MROWS * NKV * HD];
__device__ float g_v [(size_t)MROWS * NKV * HD];
__device__ float g_ao[(size_t)MROWS * NH  * HD];

// bf16 hi/lo copies (pre-converted once per call)
__device__ __nv_bfloat16 g_hs_h[E16M], g_hs_l[E16M];
__device__ __nv_bfloat16 g_wq_h[E16M], g_wq_l[E16M];
__device__ __nv_bfloat16 g_wk_h[E4M],  g_wk_l[E4M];
__device__ __nv_bfloat16 g_wv_h[E4M],  g_wv_l[E4M];
__device__ __nv_bfloat16 g_wo_h[E16M], g_wo_l[E16M];
__device__ __nv_bfloat16 g_ao_h[E16M], g_ao_l[E16M];

// ---------------------------------------------------------------------------
// Common helpers (sm_80-level PTX only; no 'a'-suffix features)
// ---------------------------------------------------------------------------
__device__ __forceinline__ uint32_t smem_u32(const void* p) {
    uint32_t a;
    asm("{ .reg .u64 t; cvta.to.shared.u64 t, %1; cvt.u32.u64 %0, t; }"
        : "=r"(a) : "l"(p));
    return a;
}
__device__ __forceinline__ uint32_t pack_bf16x2(float a, float b) {
    __nv_bfloat162 h = __floats2bfloat162_rn(a, b);
    return *reinterpret_cast<uint32_t*>(&h);
}
__device__ __forceinline__ void cp16(uint32_t saddr, const void* gptr) {
    asm volatile("cp.async.cg.shared.global [%0], [%1], 16;"
                 :: "r"(saddr), "l"(gptr));
}
__device__ __forceinline__ void cp_commit() {
    asm volatile("cp.async.commit_group;" ::: "memory");
}
template <int N>
__device__ __forceinline__ void cp_wait() {
    asm volatile("cp.async.wait_group %0;" :: "n"(N) : "memory");
}
// ldmatrix.x4, 128B-wide rows (GEMM tiles)
__device__ __forceinline__ void ldm_x4(uint32_t* r, uint32_t base, int row0, int c0) {
    const int l  = (int)(threadIdx.x & 31);
    const int rr = row0 + (l & 15);
    const int cc = (c0 + (l >> 4)) ^ (rr & 7);
    const uint32_t addr = base + (uint32_t)(rr * 128 + cc * 16);
    asm volatile("ldmatrix.sync.aligned.m8n8.x4.shared.b16 {%0,%1,%2,%3}, [%4];"
                 : "=r"(r[0]), "=r"(r[1]), "=r"(r[2]), "=r"(r[3]) : "r"(addr));
}
// ldmatrix.x4, 256B-wide rows (attention tiles, HD=128 bf16 per row)
__device__ __forceinline__ void ldm_x4_256(uint32_t* r, uint32_t base, int row0, int c0) {
    const int l  = (int)(threadIdx.x & 31);
    const int rr = row0 + (l & 15);
    const int cc = (c0 + (l >> 4)) ^ (rr & 7);
    const uint32_t addr = base + (uint32_t)(rr * 256 + cc * 16);
    asm volatile("ldmatrix.sync.aligned.m8n8.x4.shared.b16 {%0,%1,%2,%3}, [%4];"
                 : "=r"(r[0]), "=r"(r[1]), "=r"(r[2]), "=r"(r[3]) : "r"(addr));
}
// transposed variant (V tiles: gives B fragments of V^T)
__device__ __forceinline__ void ldm_x4t_256(uint32_t* r, uint32_t base, int row0, int c0) {
    const int l  = (int)(threadIdx.x & 31);
    const int rr = row0 + (l & 15);
    const int cc = (c0 + (l >> 4)) ^ (rr & 7);
    const uint32_t addr = base + (uint32_t)(rr * 256 + cc * 16);
    asm volatile("ldmatrix.sync.aligned.m8n8.x4.trans.shared.b16 {%0,%1,%2,%3}, [%4];"
                 : "=r"(r[0]), "=r"(r[1]), "=r"(r[2]), "=r"(r[3]) : "r"(addr));
}
__device__ __forceinline__ void mma_bf16(float* d, const uint32_t* a,
                                         uint32_t b0, uint32_t b1) {
    asm volatile(
        "mma.sync.aligned.m16n8k16.row.col.f32.bf16.bf16.f32 "
        "{%0,%1,%2,%3}, {%4,%5,%6,%7}, {%8,%9}, {%0,%1,%2,%3};"
        : "+f"(d[0]), "+f"(d[1]), "+f"(d[2]), "+f"(d[3])
        : "r"(a[0]), "r"(a[1]), "r"(a[2]), "r"(a[3]), "r"(b0), "r"(b1));
}
// Split 8 floats into hi/lo bf16 chunks (16B each)
__device__ __forceinline__ void split8(float4 x0, float4 x1, uint4& hi, uint4& lo) {
    float xs[8] = {x0.x, x0.y, x0.z, x0.w, x1.x, x1.y, x1.z, x1.w};
    float hf[8], lf[8];
#pragma unroll
    for (int t = 0; t < 8; t++) {
        __nv_bfloat16 h = __float2bfloat16(xs[t]);
        hf[t] = __bfloat162float(h);
        lf[t] = xs[t] - hf[t];
    }
    hi.x = pack_bf16x2(hf[0], hf[1]); hi.y = pack_bf16x2(hf[2], hf[3]);
    hi.z = pack_bf16x2(hf[4], hf[5]); hi.w = pack_bf16x2(hf[6], hf[7]);
    lo.x = pack_bf16x2(lf[0], lf[1]); lo.y = pack_bf16x2(lf[2], lf[3]);
    lo.z = pack_bf16x2(lf[4], lf[5]); lo.w = pack_bf16x2(lf[6], lf[7]);
}
__device__ __forceinline__ void pack_hilo(float p0, float p1, uint32_t& hi, uint32_t& lo) {
    float h0 = __bfloat162float(__float2bfloat16(p0));
    float h1 = __bfloat162float(__float2bfloat16(p1));
    hi = pack_bf16x2(h0, h1);
    lo = pack_bf16x2(p0 - h0, p1 - h1);
}

// ---------------------------------------------------------------------------
// fp32 -> bf16 hi/lo conversion (elementwise)
// ---------------------------------------------------------------------------
__global__ __launch_bounds__(256) void cvt_kernel(
    const float4* __restrict__ x, uint2* __restrict__ hi,
    uint2* __restrict__ lo, int n4)
{
    int i = blockIdx.x * blockDim.x + threadIdx.x;
    if (i >= n4) return;
    float4 f = x[i];
    float xs[4] = {f.x, f.y, f.z, f.w};
    float hf[4], lf[4];
#pragma unroll
    for (int t = 0; t < 4; t++) {
        __nv_bfloat16 h = __float2bfloat16(xs[t]);
        hf[t] = __bfloat162float(h);
        lf[t] = xs[t] - hf[t];
    }
    uint2 H, L;
    H.x = pack_bf16x2(hf[0], hf[1]); H.y = pack_bf16x2(hf[2], hf[3]);
    L.x = pack_bf16x2(lf[0], lf[1]); L.y = pack_bf16x2(lf[2], lf[3]);
    hi[i] = H;
    lo[i] = L;
}

// ---------------------------------------------------------------------------
// GEMM: C[M,N] = A[M,K] * B[N,K]^T (bf16 hi/lo x3 MMAs, fp32 out) — R4 proven
// ---------------------------------------------------------------------------
#define TBM 128
#define TBN 128
#define TBK 64
#define OFF_AH 0
#define OFF_AL 16384
#define OFF_BH 32768
#define OFF_BL 49152
#define STAGE_BYTES 65536
#define GEMM_SMEM (2 * STAGE_BYTES)

__global__ __launch_bounds__(256) void gemm_mma_kernel(
    const __nv_bfloat16* __restrict__ Ah, const __nv_bfloat16* __restrict__ Al,
    const __nv_bfloat16* __restrict__ Bh, const __nv_bfloat16* __restrict__ Bl,
    float* __restrict__ C, int M, int N, int K)
{
    extern __shared__ __align__(1024) char smem[];
    const uint32_t sbase = smem_u32(smem);
    const int tid  = threadIdx.x;
    const int lane = tid & 31;
    const int wid  = tid >> 5;
    const int wm   = wid & 1;
    const int wn   = wid >> 1;
    const int m0   = blockIdx.y * TBM;
    const int n0   = blockIdx.x * TBN;

    const int lrow = tid >> 1;
    const int cbase = (tid & 1) * 4;

    float acc[4][4][4];
#pragma unroll
    for (int i = 0; i < 4; i++)
#pragma unroll
        for (int j = 0; j < 4; j++)
#pragma unroll
            for (int t = 0; t < 4; t++) acc[i][j][t] = 0.0f;

    const int nch = K / TBK;

    auto issue = [&](int s, int k0) {
        const uint32_t st = sbase + s * STAGE_BYTES;
        const size_t ga = (size_t)(m0 + lrow) * K + k0;
        const size_t gb = (size_t)(n0 + lrow) * K + k0;
#pragma unroll
        for (int p = 0; p < 4; p++) {
            const int c    = cbase + p;
            const uint32_t coff = (uint32_t)(lrow * 128 + ((c ^ (lrow & 7)) * 16));
            const size_t eo = (size_t)c * 8;
            cp16(st + OFF_AH + coff, Ah + ga + eo);
            cp16(st + OFF_AL + coff, Al + ga + eo);
            cp16(st + OFF_BH + coff, Bh + gb + eo);
            cp16(st + OFF_BL + coff, Bl + gb + eo);
        }
        cp_commit();
    };

    issue(0, 0);

    for (int ch = 0; ch < nch; ch++) {
        const int s = ch & 1;
        if (ch + 1 < nch) {
            issue(1 - s, (ch + 1) * TBK);
            cp_wait<1>();
        } else {
            cp_wait<0>();
        }
        __syncthreads();

        const uint32_t stAh = sbase + s * STAGE_BYTES + OFF_AH;
        const uint32_t stAl = sbase + s * STAGE_BYTES + OFF_AL;
        const uint32_t stBh = sbase + s * STAGE_BYTES + OFF_BH;
        const uint32_t stBl = sbase + s * STAGE_BYTES + OFF_BL;
#pragma unroll
        for (int kt = 0; kt < 4; kt++) {
            uint32_t ah[4][4], al[4][4], bh[2][4], bl[2][4];
#pragma unroll
            for (int mt = 0; mt < 4; mt++) {
                ldm_x4(ah[mt], stAh, wm * 64 + mt * 16, kt * 2);
                ldm_x4(al[mt], stAl, wm * 64 + mt * 16, kt * 2);
            }
#pragma unroll
            for (int bp = 0; bp < 2; bp++) {
                ldm_x4(bh[bp], stBh, wn * 32 + bp * 16, kt * 2);
                ldm_x4(bl[bp], stBl, wn * 32 + bp * 16, kt * 2);
            }
#pragma unroll
            for (int mt = 0; mt < 4; mt++)
#pragma unroll
                for (int nt = 0; nt < 4; nt++) {
                    const int bp = nt >> 1, o = nt & 1;
                    mma_bf16(acc[mt][nt], ah[mt], bh[bp][o], bh[bp][o + 2]);
                    mma_bf16(acc[mt][nt], ah[mt], bl[bp][o], bl[bp][o + 2]);
                    mma_bf16(acc[mt][nt], al[mt], bh[bp][o], bh[bp][o + 2]);
                }
        }
        __syncthreads();
    }

#pragma unroll
    for (int mt = 0; mt < 4; mt++) {
        const int row = m0 + wm * 64 + mt * 16 + (lane >> 2);
#pragma unroll
        for (int nt = 0; nt < 4; nt++) {
            const int col = n0 + wn * 32 + nt * 8 + (lane & 3) * 2;
            float2 v0 = make_float2(acc[mt][nt][0], acc[mt][nt][1]);
            float2 v1 = make_float2(acc[mt][nt][2], acc[mt][nt][3]);
            *(float2*)(C + (size_t)row * N + col)       = v0;
            *(float2*)(C + (size_t)(row + 8) * N + col) = v1;
        }
    }
}

// ---------------------------------------------------------------------------
// RoPE (in place on q and k)
// ---------------------------------------------------------------------------
__global__ void rope_kernel(float* __restrict__ q, float* __restrict__ k,
                            const int* __restrict__ pos)
{
    const int bs = blockIdx.x;
    const float p = (float)pos[bs];
    const float c1 = -0.2076205059304601f;        // -log2(10000)/64
    for (int i = threadIdx.x; i < (NH + NKV) * 64; i += blockDim.x) {
        float* base; int d;
        if (i < NH * 64) {
            int hh = i >> 6; d = i & 63;
            base = q + ((size_t)bs * NH + hh) * HD;
        } else {
            int j = i - NH * 64;
            int hh = j >> 6; d = j & 63;
            base = k + ((size_t)bs * NKV + hh) * HD;
        }
        float inv = exp2f(c1 * (float)d);
        float ang = p * inv;
        float sv, cv;
        sincosf(ang, &sv, &cv);
        float x1 = base[d], x2 = base[d + 64];
        base[d]      = x1 * cv - x2 * sv;
        base[d + 64] = x2 * cv + x1 * sv;
    }
}

// ---------------------------------------------------------------------------
// Flash attention via mma.sync (bf16 hi/lo x3), fp32 softmax, causal.
// CTA: 128 q-rows x 1 head, 8 warps (16 rows each, full 64-kv width).
// ---------------------------------------------------------------------------
#define ABQ  128
#define ABKV 64
#define AQH 0
#define AQL 32768
#define AKH 65536
#define AKL 81920
#define AVH 98304
#define AVL 114688
#define ATTN_SMEM 131072

__global__ __launch_bounds__(256) void attn_mma_kernel(
    const float* __restrict__ Q, const float* __restrict__ K,
    const float* __restrict__ V, float* __restrict__ O)
{
    extern __shared__ __align__(1024) char smem[];
    const uint32_t sbase = smem_u32(smem);
    const int tid  = threadIdx.x;
    const int lane = tid & 31;
    const int wq   = tid >> 5;                              // warp -> q rows [wq*16,+16)
    const int qb   = (int)gridDim.x - 1 - (int)blockIdx.x;  // big tiles first
    const int h    = blockIdx.y, b = blockIdx.z;
    const int g    = h / NREP;
    const int q0   = qb * ABQ;
    const int rowmin = q0 + wq * 16;

    // ---- load Q tile: fp32 -> bf16 hi/lo, swizzled 256B rows ----
    for (int idx = tid; idx < ABQ * 16; idx += 256) {
        int row = idx >> 4, c = idx & 15;
        const float* src = Q + ((size_t)(b * S_LEN + q0 + row) * NH + h) * HD + c * 8;
        float4 f0 = *(const float4*)src, f1 = *(const float4*)(src + 4);
        uint4 hi, lo; split8(f0, f1, hi, lo);
        uint32_t off = (uint32_t)(row * 256 + ((c ^ (row & 7)) * 16));
        *(uint4*)(smem + AQH + off) = hi;
        *(uint4*)(smem + AQL + off) = lo;
    }

    float out[16][4];
#pragma unroll
    for (int i = 0; i < 16; i++)
#pragma unroll
        for (int j = 0; j < 4; j++) out[i][j] = 0.0f;
    float m0 = -1e30f, m1 = -1e30f, l0 = 0.0f, l1 = 0.0f;
    const float scale = 0.08838834764831845f;   // 1/sqrt(128)
    const int ntile = 2 * qb + 2;

    for (int kb = 0; kb < ntile; kb++) {
        const int k0 = kb * ABKV;
        __syncthreads();   // prior tile's MMAs done with K/V buffers
        // ---- load K & V tiles: fp32 -> bf16 hi/lo ----
        for (int idx = tid; idx < ABKV * 16; idx += 256) {
            int row = idx >> 4, c = idx & 15;
            size_t goff = ((size_t)(b * S_LEN + k0 + row) * NKV + g) * HD + c * 8;
            uint32_t off = (uint32_t)(row * 256 + ((c ^ (row & 7)) * 16));
            float4 f0 = *(const float4*)(K + goff), f1 = *(const float4*)(K + goff + 4);
            uint4 hi, lo; split8(f0, f1, hi, lo);
            *(uint4*)(smem + AKH + off) = hi;
            *(uint4*)(smem + AKL + off) = lo;
            f0 = *(const float4*)(V + goff); f1 = *(const float4*)(V + goff + 4);
            split8(f0, f1, hi, lo);
            *(uint4*)(smem + AVH + off) = hi;
            *(uint4*)(smem + AVL + off) = lo;
        }
        __syncthreads();

        if (k0 > rowmin + 15) continue;   // tile fully masked for this warp

        // ---- S = Q K^T  (M=16, N=64, K=128; 3 hi/lo combos) ----
        float s[8][4];
#pragma unroll
        for (int nt = 0; nt < 8; nt++)
#pragma unroll
            for (int j = 0; j < 4; j++) s[nt][j] = 0.0f;
#pragma unroll
        for (int kt = 0; kt < 8; kt++) {
            uint32_t aqh[4], aql[4];
            ldm_x4_256(aqh, sbase + AQH, wq * 16, kt * 2);
            ldm_x4_256(aql, sbase + AQL, wq * 16, kt * 2);
#pragma unroll
            for (int bp = 0; bp < 4; bp++) {
                uint32_t bkh[4], bkl[4];
                ldm_x4_256(bkh, sbase + AKH, bp * 16, kt * 2);
                ldm_x4_256(bkl, sbase + AKL, bp * 16, kt * 2);
#pragma unroll
                for (int o = 0; o < 2; o++) {
                    const int nt = bp * 2 + o;
                    mma_bf16(s[nt], aqh, bkh[o], bkh[o + 2]);
                    mma_bf16(s[nt], aqh, bkl[o], bkl[o + 2]);
                    mma_bf16(s[nt], aql, bkh[o], bkh[o + 2]);
                }
            }
        }

        // ---- scale + causal mask + online softmax ----
        const int r0g = rowmin + (lane >> 2);
        const bool domask = (k0 + ABKV - 1) > rowmin;
        float mx0 = -1e30f, mx1 = -1e30f;
#pragma unroll
        for (int nt = 0; nt < 8; nt++) {
#pragma unroll
            for (int j = 0; j < 4; j++) {
                float v = s[nt][j] * scale;
                if (domask) {
                    int cg = k0 + nt * 8 + (lane & 3) * 2 + (j & 1);
                    int rg = r0g + ((j >> 1) << 3);
                    if (cg > rg) v = -1e30f;
                }
                s[nt][j] = v;
            }
            mx0 = fmaxf(mx0, fmaxf(s[nt][0], s[nt][1]));
            mx1 = fmaxf(mx1, fmaxf(s[nt][2], s[nt][3]));
        }
        mx0 = fmaxf(mx0, __shfl_xor_sync(0xffffffffu, mx0, 1));
        mx0 = fmaxf(mx0, __shfl_xor_sync(0xffffffffu, mx0, 2));
        mx1 = fmaxf(mx1, __shfl_xor_sync(0xffffffffu, mx1, 1));
        mx1 = fmaxf(mx1, __shfl_xor_sync(0xffffffffu, mx1, 2));
        const float mn0 = fmaxf(m0, mx0), mn1 = fmaxf(m1, mx1);
        const float a0 = __expf(m0 - mn0), a1 = __expf(m1 - mn1);
        m0 = mn0; m1 = mn1;
        float ps0 = 0.0f, ps1 = 0.0f;
#pragma unroll
        for (int nt = 0; nt < 8; nt++) {
            s[nt][0] = __expf(s[nt][0] - mn0); ps0 += s[nt][0];
            s[nt][1] = __expf(s[nt][1] - mn0); ps0 += s[nt][1];
            s[nt][2] = __expf(s[nt][2] - mn1); ps1 += s[nt][2];
            s[nt][3] = __expf(s[nt][3] - mn1); ps1 += s[nt][3];
        }
        l0 = l0 * a0 + ps0;
        l1 = l1 * a1 + ps1;
#pragma unroll
        for (int dt = 0; dt < 16; dt++) {
            out[dt][0] *= a0; out[dt][1] *= a0;
            out[dt][2] *= a1; out[dt][3] *= a1;
        }

        // ---- O += P V  (M=16, K=64, N=128; P hi/lo in regs, V hi/lo smem) ----
#pragma unroll
        for (int ktp = 0; ktp < 4; ktp++) {
            uint32_t aph[4], apl[4];
            const int t0 = ktp * 2, t1 = t0 + 1;
            pack_hilo(s[t0][0], s[t0][1], aph[0], apl[0]);
            pack_hilo(s[t0][2], s[t0][3], aph[1], apl[1]);
            pack_hilo(s[t1][0], s[t1][1], aph[2], apl[2]);
            pack_hilo(s[t1][2], s[t1][3], aph[3], apl[3]);
#pragma unroll
            for (int dt = 0; dt < 8; dt++) {
                uint32_t bvh[4], bvl[4];
                ldm_x4t_256(bvh, sbase + AVH, ktp * 16, dt * 2);
                ldm_x4t_256(bvl, sbase + AVL, ktp * 16, dt * 2);
                mma_bf16(out[dt * 2],     aph, bvh[0], bvh[1]);
                mma_bf16(out[dt * 2],     aph, bvl[0], bvl[1]);
                mma_bf16(out[dt * 2],     apl, bvh[0], bvh[1]);
                mma_bf16(out[dt * 2 + 1], aph, bvh[2], bvh[3]);
                mma_bf16(out[dt * 2 + 1], aph, bvl[2], bvl[3]);
                mma_bf16(out[dt * 2 + 1], apl, bvh[2], bvh[3]);
            }
        }
    }

    // ---- finalize ----
    l0 += __shfl_xor_sync(0xffffffffu, l0, 1);
    l0 += __shfl_xor_sync(0xffffffffu, l0, 2);
    l1 += __shfl_xor_sync(0xffffffffu, l1, 1);
    l1 += __shfl_xor_sync(0xffffffffu, l1, 2);
    const float i0 = 1.0f / l0, i1 = 1.0f / l1;
    const int r0g = rowmin + (lane >> 2);
    float* O0 = O + ((size_t)(b * S_LEN + r0g) * NH + h) * HD;
    float* O1 = O0 + (size_t)8 * NH * HD;
#pragma unroll
    for (int dt = 0; dt < 16; dt++) {
        const int col = dt * 8 + (lane & 3) * 2;
        *(float2*)(O0 + col) = make_float2(out[dt][0] * i0, out[dt][1] * i0);
        *(float2*)(O1 + col) = make_float2(out[dt][2] * i1, out[dt][3] * i1);
    }
}

// ---------------------------------------------------------------------------
// Launch
// ---------------------------------------------------------------------------
extern "C" void kernel_launch(void* const* d_in, const int* in_sizes, int n_in,
                              void* d_out, int out_size)
{
    const float* hs = (const float*)d_in[0];
    const float* wq = (const float*)d_in[1];
    const float* wk = (const float*)d_in[2];
    const float* wv = (const float*)d_in[3];
    const float* wo = (const float*)d_in[4];
    const int*  pos = (const int*)  d_in[6];
    float*      out = (float*)d_out;

    float *q, *k, *v, *ao;
    cudaGetSymbolAddress((void**)&q,  g_q);
    cudaGetSymbolAddress((void**)&k,  g_k);
    cudaGetSymbolAddress((void**)&v,  g_v);
    cudaGetSymbolAddress((void**)&ao, g_ao);

    __nv_bfloat16 *hsh, *hsl, *wqh, *wql, *wkh, *wkl, *wvh, *wvl, *woh, *wol, *aoh, *aol;
    cudaGetSymbolAddress((void**)&hsh, g_hs_h); cudaGetSymbolAddress((void**)&hsl, g_hs_l);
    cudaGetSymbolAddress((void**)&wqh, g_wq_h); cudaGetSymbolAddress((void**)&wql, g_wq_l);
    cudaGetSymbolAddress((void**)&wkh, g_wk_h); cudaGetSymbolAddress((void**)&wkl, g_wk_l);
    cudaGetSymbolAddress((void**)&wvh, g_wv_h); cudaGetSymbolAddress((void**)&wvl, g_wv_l);
    cudaGetSymbolAddress((void**)&woh, g_wo_h); cudaGetSymbolAddress((void**)&wol, g_wo_l);
    cudaGetSymbolAddress((void**)&aoh, g_ao_h); cudaGetSymbolAddress((void**)&aol, g_ao_l);

    cudaFuncSetAttribute(gemm_mma_kernel, cudaFuncAttributeMaxDynamicSharedMemorySize, GEMM_SMEM);
    cudaFuncSetAttribute(attn_mma_kernel, cudaFuncAttributeMaxDynamicSharedMemorySize, ATTN_SMEM);

    auto cvt = [&](const float* x, __nv_bfloat16* hi, __nv_bfloat16* lo, int n) {
        int n4 = n / 4;
        cvt_kernel<<<(n4 + 255) / 256, 256>>>((const float4*)x, (uint2*)hi, (uint2*)lo, n4);
    };

    // pre-convert inputs to bf16 hi/lo
    cvt(hs, hsh, hsl, MROWS * HID);
    cvt(wq, wqh, wql, NH * HD * HID);
    cvt(wk, wkh, wkl, NKV * HD * HID);
    cvt(wv, wvh, wvl, NKV * HD * HID);
    cvt(wo, woh, wol, HID * NH * HD);

    // Q/K/V projections (mma.sync bf16x3, cp.async pipeline)
    gemm_mma_kernel<<<dim3((NH  * HD) / TBN, MROWS / TBM), 256, GEMM_SMEM>>>(hsh, hsl, wqh, wql, q, MROWS, NH  * HD, HID);
    gemm_mma_kernel<<<dim3((NKV * HD) / TBN, MROWS / TBM), 256, GEMM_SMEM>>>(hsh, hsl, wkh, wkl, k, MROWS, NKV * HD, HID);
    gemm_mma_kernel<<<dim3((NKV * HD) / TBN, MROWS / TBM), 256, GEMM_SMEM>>>(hsh, hsl, wvh, wvl, v, MROWS, NKV * HD, HID);

    // RoPE on q, k
    rope_kernel<<<MROWS, 256>>>(q, k, pos);

    // Causal flash attention (mma.sync)
    attn_mma_kernel<<<dim3(S_LEN / ABQ, NH, B_SZ), 256, ATTN_SMEM>>>(q, k, v, ao);

    // Convert attention output, then output projection
    cvt(ao, aoh, aol, MROWS * NH * HD);
    gemm_mma_kernel<<<dim3(HID / TBN, MROWS / TBM), 256, GEMM_SMEM>>>(aoh, aol, woh, wol, out, MROWS, HID, NH * HD);
}

// round 6
// speedup vs baseline: 2.6538x; 1.2535x over previous
#include <cuda_runtime.h>
#include <cuda_bf16.h>
#include <cstdint>

// Problem constants (fixed shapes)
#define NH    32
#define NKV   8
#define HD    128
#define S_LEN 2048
#define B_SZ  2
#define HID   4096
#define MROWS (B_SZ * S_LEN)   // 4096
#define NREP  (NH / NKV)       // 4

#define E16M (16u * 1024u * 1024u)
#define E4M  (4u  * 1024u * 1024u)

// ---------------------------------------------------------------------------
// Scratch (device globals; allocation-free per harness rules)
// ---------------------------------------------------------------------------
__device__ float g_q [(size_t)MROWS * NH  * HD];
__device__ float g_k [(size_t)MROWS * NKV * HD];
__device__ float g_v [(size_t)MROWS * NKV * HD];
__device__ float g_ao[(size_t)MROWS * NH  * HD];

// bf16 hi/lo copies
__device__ __nv_bfloat16 g_hs_h[E16M], g_hs_l[E16M];
__device__ __nv_bfloat16 g_wq_h[E16M], g_wq_l[E16M];
__device__ __nv_bfloat16 g_wk_h[E4M],  g_wk_l[E4M];
__device__ __nv_bfloat16 g_wv_h[E4M],  g_wv_l[E4M];
__device__ __nv_bfloat16 g_wo_h[E16M], g_wo_l[E16M];
__device__ __nv_bfloat16 g_ao_h[E16M], g_ao_l[E16M];
// post-rope bf16 hi/lo q/k/v for attention
__device__ __nv_bfloat16 g_q_h[E16M], g_q_l[E16M];
__device__ __nv_bfloat16 g_k_h[E4M],  g_k_l[E4M];
__device__ __nv_bfloat16 g_v_h[E4M],  g_v_l[E4M];

// ---------------------------------------------------------------------------
// Common helpers (sm_80-level PTX only; no 'a'-suffix features)
// ---------------------------------------------------------------------------
__device__ __forceinline__ uint32_t smem_u32(const void* p) {
    uint32_t a;
    asm("{ .reg .u64 t; cvta.to.shared.u64 t, %1; cvt.u32.u64 %0, t; }"
        : "=r"(a) : "l"(p));
    return a;
}
__device__ __forceinline__ uint32_t pack_bf16x2(float a, float b) {
    __nv_bfloat162 h = __floats2bfloat162_rn(a, b);
    return *reinterpret_cast<uint32_t*>(&h);
}
__device__ __forceinline__ void cp16(uint32_t saddr, const void* gptr) {
    asm volatile("cp.async.cg.shared.global [%0], [%1], 16;"
                 :: "r"(saddr), "l"(gptr));
}
__device__ __forceinline__ void cp_commit() {
    asm volatile("cp.async.commit_group;" ::: "memory");
}
template <int N>
__device__ __forceinline__ void cp_wait() {
    asm volatile("cp.async.wait_group %0;" :: "n"(N) : "memory");
}
// ldmatrix.x4, 128B-wide rows (GEMM tiles)
__device__ __forceinline__ void ldm_x4(uint32_t* r, uint32_t base, int row0, int c0) {
    const int l  = (int)(threadIdx.x & 31);
    const int rr = row0 + (l & 15);
    const int cc = (c0 + (l >> 4)) ^ (rr & 7);
    const uint32_t addr = base + (uint32_t)(rr * 128 + cc * 16);
    asm volatile("ldmatrix.sync.aligned.m8n8.x4.shared.b16 {%0,%1,%2,%3}, [%4];"
                 : "=r"(r[0]), "=r"(r[1]), "=r"(r[2]), "=r"(r[3]) : "r"(addr));
}
// ldmatrix.x4, 256B-wide rows (attention tiles, HD=128 bf16 per row)
__device__ __forceinline__ void ldm_x4_256(uint32_t* r, uint32_t base, int row0, int c0) {
    const int l  = (int)(threadIdx.x & 31);
    const int rr = row0 + (l & 15);
    const int cc = (c0 + (l >> 4)) ^ (rr & 7);
    const uint32_t addr = base + (uint32_t)(rr * 256 + cc * 16);
    asm volatile("ldmatrix.sync.aligned.m8n8.x4.shared.b16 {%0,%1,%2,%3}, [%4];"
                 : "=r"(r[0]), "=r"(r[1]), "=r"(r[2]), "=r"(r[3]) : "r"(addr));
}
__device__ __forceinline__ void ldm_x4t_256(uint32_t* r, uint32_t base, int row0, int c0) {
    const int l  = (int)(threadIdx.x & 31);
    const int rr = row0 + (l & 15);
    const int cc = (c0 + (l >> 4)) ^ (rr & 7);
    const uint32_t addr = base + (uint32_t)(rr * 256 + cc * 16);
    asm volatile("ldmatrix.sync.aligned.m8n8.x4.trans.shared.b16 {%0,%1,%2,%3}, [%4];"
                 : "=r"(r[0]), "=r"(r[1]), "=r"(r[2]), "=r"(r[3]) : "r"(addr));
}
__device__ __forceinline__ void mma_bf16(float* d, const uint32_t* a,
                                         uint32_t b0, uint32_t b1) {
    asm volatile(
        "mma.sync.aligned.m16n8k16.row.col.f32.bf16.bf16.f32 "
        "{%0,%1,%2,%3}, {%4,%5,%6,%7}, {%8,%9}, {%0,%1,%2,%3};"
        : "+f"(d[0]), "+f"(d[1]), "+f"(d[2]), "+f"(d[3])
        : "r"(a[0]), "r"(a[1]), "r"(a[2]), "r"(a[3]), "r"(b0), "r"(b1));
}
__device__ __forceinline__ void pack_hilo(float p0, float p1, uint32_t& hi, uint32_t& lo) {
    float h0 = __bfloat162float(__float2bfloat16(p0));
    float h1 = __bfloat162float(__float2bfloat16(p1));
    hi = pack_bf16x2(h0, h1);
    lo = pack_bf16x2(p0 - h0, p1 - h1);
}
__device__ __forceinline__ void store_hilo(__nv_bfloat16* H, __nv_bfloat16* L,
                                           size_t idx, float val) {
    __nv_bfloat16 hb = __float2bfloat16(val);
    H[idx] = hb;
    L[idx] = __float2bfloat16(val - __bfloat162float(hb));
}

// ---------------------------------------------------------------------------
// fp32 -> bf16 hi/lo conversion (elementwise)
// ---------------------------------------------------------------------------
__global__ __launch_bounds__(256) void cvt_kernel(
    const float4* __restrict__ x, uint2* __restrict__ hi,
    uint2* __restrict__ lo, int n4)
{
    int i = blockIdx.x * blockDim.x + threadIdx.x;
    if (i >= n4) return;
    float4 f = x[i];
    float xs[4] = {f.x, f.y, f.z, f.w};
    float hf[4], lf[4];
#pragma unroll
    for (int t = 0; t < 4; t++) {
        __nv_bfloat16 h = __float2bfloat16(xs[t]);
        hf[t] = __bfloat162float(h);
        lf[t] = xs[t] - hf[t];
    }
    uint2 H, L;
    H.x = pack_bf16x2(hf[0], hf[1]); H.y = pack_bf16x2(hf[2], hf[3]);
    L.x = pack_bf16x2(lf[0], lf[1]); L.y = pack_bf16x2(lf[2], lf[3]);
    hi[i] = H;
    lo[i] = L;
}

// ---------------------------------------------------------------------------
// GEMM: C[M,N] = A[M,K] * B[N,K]^T  (bf16 hi/lo x3 MMAs, fp32 out)
// Tile 128x256x64, 256 threads = 8 warps (2 M x 4 N), warp tile 64x64.
// Coalesced cp.async (4 rows x 128B per warp instruction), 2-stage pipeline.
// ---------------------------------------------------------------------------
#define TBM 128
#define TBN 256
#define TBK 64
#define OFF_AH 0
#define OFF_AL 16384
#define OFF_BH 32768
#define OFF_BL 65536
#define STAGE_BYTES 98304
#define GEMM_SMEM (2 * STAGE_BYTES)   // 192 KB

__global__ __launch_bounds__(256) void gemm_mma_kernel(
    const __nv_bfloat16* __restrict__ Ah, const __nv_bfloat16* __restrict__ Al,
    const __nv_bfloat16* __restrict__ Bh, const __nv_bfloat16* __restrict__ Bl,
    float* __restrict__ C, int M, int N, int K)
{
    extern __shared__ __align__(1024) char smem[];
    const uint32_t sbase = smem_u32(smem);
    const int tid  = threadIdx.x;
    const int lane = tid & 31;
    const int wid  = tid >> 5;
    const int wm   = wid & 1;        // warp rows [wm*64,+64)
    const int wn   = wid >> 1;       // warp cols [wn*64,+64)
    const int m0   = blockIdx.y * TBM;
    const int n0   = blockIdx.x * TBN;
    const int lr4  = lane >> 3;      // 0..3 row within 4-row group
    const int lc   = lane & 7;       // 16B chunk 0..7 within 128B row

    float acc[4][8][4];
#pragma unroll
    for (int i = 0; i < 4; i++)
#pragma unroll
        for (int j = 0; j < 8; j++)
#pragma unroll
            for (int t = 0; t < 4; t++) acc[i][j][t] = 0.0f;

    const int nch = K / TBK;

    auto issue = [&](int s, int k0) {
        const uint32_t st = sbase + s * STAGE_BYTES;
#pragma unroll
        for (int i = 0; i < 4; i++) {           // A: warp owns 16 rows
            const int row = wid * 16 + i * 4 + lr4;
            const uint32_t off = (uint32_t)(row * 128 + ((lc ^ (row & 7)) * 16));
            const size_t gp = (size_t)(m0 + row) * K + k0 + lc * 8;
            cp16(st + OFF_AH + off, Ah + gp);
            cp16(st + OFF_AL + off, Al + gp);
        }
#pragma unroll
        for (int i = 0; i < 8; i++) {           // B: warp owns 32 rows
            const int row = wid * 32 + i * 4 + lr4;
            const uint32_t off = (uint32_t)(row * 128 + ((lc ^ (row & 7)) * 16));
            const size_t gp = (size_t)(n0 + row) * K + k0 + lc * 8;
            cp16(st + OFF_BH + off, Bh + gp);
            cp16(st + OFF_BL + off, Bl + gp);
        }
        cp_commit();
    };

    issue(0, 0);

    for (int ch = 0; ch < nch; ch++) {
        const int s = ch & 1;
        if (ch + 1 < nch) {
            issue(1 - s, (ch + 1) * TBK);
            cp_wait<1>();
        } else {
            cp_wait<0>();
        }
        __syncthreads();

        const uint32_t stAh = sbase + s * STAGE_BYTES + OFF_AH;
        const uint32_t stAl = sbase + s * STAGE_BYTES + OFF_AL;
        const uint32_t stBh = sbase + s * STAGE_BYTES + OFF_BH;
        const uint32_t stBl = sbase + s * STAGE_BYTES + OFF_BL;
#pragma unroll
        for (int kt = 0; kt < 4; kt++) {
            uint32_t ah[4][4], al[4][4], bh[4][4], bl[4][4];
#pragma unroll
            for (int mt = 0; mt < 4; mt++) {
                ldm_x4(ah[mt], stAh, wm * 64 + mt * 16, kt * 2);
                ldm_x4(al[mt], stAl, wm * 64 + mt * 16, kt * 2);
            }
#pragma unroll
            for (int bp = 0; bp < 4; bp++) {
                ldm_x4(bh[bp], stBh, wn * 64 + bp * 16, kt * 2);
                ldm_x4(bl[bp], stBl, wn * 64 + bp * 16, kt * 2);
            }
#pragma unroll
            for (int mt = 0; mt < 4; mt++)
#pragma unroll
                for (int nt = 0; nt < 8; nt++) {
                    const int bp = nt >> 1, o = nt & 1;
                    mma_bf16(acc[mt][nt], ah[mt], bh[bp][o], bh[bp][o + 2]);
                    mma_bf16(acc[mt][nt], ah[mt], bl[bp][o], bl[bp][o + 2]);
                    mma_bf16(acc[mt][nt], al[mt], bh[bp][o], bh[bp][o + 2]);
                }
        }
        __syncthreads();
    }

#pragma unroll
    for (int mt = 0; mt < 4; mt++) {
        const int row = m0 + wm * 64 + mt * 16 + (lane >> 2);
#pragma unroll
        for (int nt = 0; nt < 8; nt++) {
            const int col = n0 + wn * 64 + nt * 8 + (lane & 3) * 2;
            float2 v0 = make_float2(acc[mt][nt][0], acc[mt][nt][1]);
            float2 v1 = make_float2(acc[mt][nt][2], acc[mt][nt][3]);
            *(float2*)(C + (size_t)row * N + col)       = v0;
            *(float2*)(C + (size_t)(row + 8) * N + col) = v1;
        }
    }
}

// ---------------------------------------------------------------------------
// RoPE + fp32 -> bf16 hi/lo for q, k; straight hi/lo split for v
// ---------------------------------------------------------------------------
__global__ __launch_bounds__(256) void rope_cvt_kernel(
    const float* __restrict__ q, const float* __restrict__ k,
    const float* __restrict__ v, const int* __restrict__ pos,
    __nv_bfloat16* __restrict__ qh, __nv_bfloat16* __restrict__ ql,
    __nv_bfloat16* __restrict__ kh, __nv_bfloat16* __restrict__ kl,
    __nv_bfloat16* __restrict__ vh, __nv_bfloat16* __restrict__ vl)
{
    const int bs = blockIdx.x;
    const float p = (float)pos[bs];
    const float c1 = -0.2076205059304601f;        // -log2(10000)/64
    // q: 2048 rope pairs; k: 512 rope pairs; v: 512 float2 splits
    for (int i = threadIdx.x; i < 3072; i += 256) {
        if (i < 2560) {
            const float* base; size_t idx; int d;
            __nv_bfloat16 *H, *L;
            if (i < 2048) {
                int hh = i >> 6; d = i & 63;
                idx = ((size_t)bs * NH + hh) * HD;
                base = q + idx; H = qh; L = ql;
            } else {
                int j = i - 2048;
                int hh = j >> 6; d = j & 63;
                idx = ((size_t)bs * NKV + hh) * HD;
                base = k + idx; H = kh; L = kl;
            }
            float inv = exp2f(c1 * (float)d);
            float ang = p * inv;
            float sv, cv;
            sincosf(ang, &sv, &cv);
            float x1 = base[d], x2 = base[d + 64];
            store_hilo(H, L, idx + d,      x1 * cv - x2 * sv);
            store_hilo(H, L, idx + d + 64, x2 * cv + x1 * sv);
        } else {
            int j = i - 2560;                     // 0..511
            size_t idx = (size_t)bs * NKV * HD + j * 2;
            float2 f = *(const float2*)(v + idx);
            store_hilo(vh, vl, idx,     f.x);
            store_hilo(vh, vl, idx + 1, f.y);
        }
    }
}

// ---------------------------------------------------------------------------
// Flash attention via mma.sync (bf16 hi/lo x3), fp32 softmax, causal.
// CTA: 128 q-rows x 1 head, 8 warps. Pre-converted bf16 inputs, cp.async,
// 2-stage KV pipeline.
// ---------------------------------------------------------------------------
#define ABQ  128
#define ABKV 64
#define AQH 0
#define AQL 32768
#define KV0 65536          // stage base; per-stage: KH 0, KL 16K, VH 32K, VL 48K
#define SKH 0
#define SKL 16384
#define SVH 32768
#define SVL 49152
#define KVSTAGE 65536
#define ATTN_SMEM (65536 + 2 * KVSTAGE)   // 192 KB

__global__ __launch_bounds__(256) void attn_mma_kernel(
    const __nv_bfloat16* __restrict__ Qh, const __nv_bfloat16* __restrict__ Ql,
    const __nv_bfloat16* __restrict__ Kh, const __nv_bfloat16* __restrict__ Kl,
    const __nv_bfloat16* __restrict__ Vh, const __nv_bfloat16* __restrict__ Vl,
    float* __restrict__ O)
{
    extern __shared__ __align__(1024) char smem[];
    const uint32_t sbase = smem_u32(smem);
    const int tid  = threadIdx.x;
    const int lane = tid & 31;
    const int wq   = tid >> 5;
    const int qb   = (int)gridDim.x - 1 - (int)blockIdx.x;
    const int h    = blockIdx.y, b = blockIdx.z;
    const int g    = h / NREP;
    const int q0   = qb * ABQ;
    const int rowmin = q0 + wq * 16;
    const int lr2 = lane >> 4;      // 0..1
    const int lc  = lane & 15;      // 16B chunk within 256B row

    // ---- Q tile: cp.async (coalesced 2 rows x 256B per instr) ----
#pragma unroll
    for (int i = 0; i < 8; i++) {
        const int row = wq * 16 + i * 2 + lr2;
        const uint32_t off = (uint32_t)(row * 256 + ((lc ^ (row & 7)) * 16));
        const size_t gp = ((size_t)(b * S_LEN + q0 + row) * NH + h) * HD + lc * 8;
        cp16(sbase + AQH + off, Qh + gp);
        cp16(sbase + AQL + off, Ql + gp);
    }

    auto issue_kv = [&](int s, int k0) {
        const uint32_t st = sbase + KV0 + s * KVSTAGE;
#pragma unroll
        for (int i = 0; i < 4; i++) {
            const int row = wq * 8 + i * 2 + lr2;
            const uint32_t off = (uint32_t)(row * 256 + ((lc ^ (row & 7)) * 16));
            const size_t gp = ((size_t)(b * S_LEN + k0 + row) * NKV + g) * HD + lc * 8;
            cp16(st + SKH + off, Kh + gp);
            cp16(st + SKL + off, Kl + gp);
            cp16(st + SVH + off, Vh + gp);
            cp16(st + SVL + off, Vl + gp);
        }
    };
    issue_kv(0, 0);
    cp_commit();   // group0 = Q + kv0

    float out[16][4];
#pragma unroll
    for (int i = 0; i < 16; i++)
#pragma unroll
        for (int j = 0; j < 4; j++) out[i][j] = 0.0f;
    float m0 = -1e30f, m1 = -1e30f, l0 = 0.0f, l1 = 0.0f;
    const float scale = 0.08838834764831845f;   // 1/sqrt(128)
    const int ntile = 2 * qb + 2;

    for (int kb = 0; kb < ntile; kb++) {
        const int s = kb & 1;
        const int k0 = kb * ABKV;
        if (kb + 1 < ntile) {
            issue_kv(1 - s, (kb + 1) * ABKV);
            cp_commit();
            cp_wait<1>();
        } else {
            cp_wait<0>();
        }
        __syncthreads();

        if (k0 <= rowmin + 15) {   // else tile fully masked for this warp
            const uint32_t stK = sbase + KV0 + s * KVSTAGE;

            // ---- S = Q K^T ----
            float sc[8][4];
#pragma unroll
            for (int nt = 0; nt < 8; nt++)
#pragma unroll
                for (int j = 0; j < 4; j++) sc[nt][j] = 0.0f;
#pragma unroll
            for (int kt = 0; kt < 8; kt++) {
                uint32_t aqh[4], aql[4];
                ldm_x4_256(aqh, sbase + AQH, wq * 16, kt * 2);
                ldm_x4_256(aql, sbase + AQL, wq * 16, kt * 2);
#pragma unroll
                for (int bp = 0; bp < 4; bp++) {
                    uint32_t bkh[4], bkl[4];
                    ldm_x4_256(bkh, stK + SKH, bp * 16, kt * 2);
                    ldm_x4_256(bkl, stK + SKL, bp * 16, kt * 2);
#pragma unroll
                    for (int o = 0; o < 2; o++) {
                        const int nt = bp * 2 + o;
                        mma_bf16(sc[nt], aqh, bkh[o], bkh[o + 2]);
                        mma_bf16(sc[nt], aqh, bkl[o], bkl[o + 2]);
                        mma_bf16(sc[nt], aql, bkh[o], bkh[o + 2]);
                    }
                }
            }

            // ---- scale + causal mask + online softmax ----
            const int r0g = rowmin + (lane >> 2);
            const bool domask = (k0 + ABKV - 1) > rowmin;
            float mx0 = -1e30f, mx1 = -1e30f;
#pragma unroll
            for (int nt = 0; nt < 8; nt++) {
#pragma unroll
                for (int j = 0; j < 4; j++) {
                    float v = sc[nt][j] * scale;
                    if (domask) {
                        int cg = k0 + nt * 8 + (lane & 3) * 2 + (j & 1);
                        int rg = r0g + ((j >> 1) << 3);
                        if (cg > rg) v = -1e30f;
                    }
                    sc[nt][j] = v;
                }
                mx0 = fmaxf(mx0, fmaxf(sc[nt][0], sc[nt][1]));
                mx1 = fmaxf(mx1, fmaxf(sc[nt][2], sc[nt][3]));
            }
            mx0 = fmaxf(mx0, __shfl_xor_sync(0xffffffffu, mx0, 1));
            mx0 = fmaxf(mx0, __shfl_xor_sync(0xffffffffu, mx0, 2));
            mx1 = fmaxf(mx1, __shfl_xor_sync(0xffffffffu, mx1, 1));
            mx1 = fmaxf(mx1, __shfl_xor_sync(0xffffffffu, mx1, 2));
            const float mn0 = fmaxf(m0, mx0), mn1 = fmaxf(m1, mx1);
            const float a0 = __expf(m0 - mn0), a1 = __expf(m1 - mn1);
            m0 = mn0; m1 = mn1;
            float ps0 = 0.0f, ps1 = 0.0f;
#pragma unroll
            for (int nt = 0; nt < 8; nt++) {
                sc[nt][0] = __expf(sc[nt][0] - mn0); ps0 += sc[nt][0];
                sc[nt][1] = __expf(sc[nt][1] - mn0); ps0 += sc[nt][1];
                sc[nt][2] = __expf(sc[nt][2] - mn1); ps1 += sc[nt][2];
                sc[nt][3] = __expf(sc[nt][3] - mn1); ps1 += sc[nt][3];
            }
            l0 = l0 * a0 + ps0;
            l1 = l1 * a1 + ps1;
#pragma unroll
            for (int dt = 0; dt < 16; dt++) {
                out[dt][0] *= a0; out[dt][1] *= a0;
                out[dt][2] *= a1; out[dt][3] *= a1;
            }

            // ---- O += P V ----
#pragma unroll
            for (int ktp = 0; ktp < 4; ktp++) {
                uint32_t aph[4], apl[4];
                const int t0 = ktp * 2, t1 = t0 + 1;
                pack_hilo(sc[t0][0], sc[t0][1], aph[0], apl[0]);
                pack_hilo(sc[t0][2], sc[t0][3], aph[1], apl[1]);
                pack_hilo(sc[t1][0], sc[t1][1], aph[2], apl[2]);
                pack_hilo(sc[t1][2], sc[t1][3], aph[3], apl[3]);
#pragma unroll
                for (int dt = 0; dt < 8; dt++) {
                    uint32_t bvh[4], bvl[4];
                    ldm_x4t_256(bvh, stK + SVH, ktp * 16, dt * 2);
                    ldm_x4t_256(bvl, stK + SVL, ktp * 16, dt * 2);
                    mma_bf16(out[dt * 2],     aph, bvh[0], bvh[1]);
                    mma_bf16(out[dt * 2],     aph, bvl[0], bvl[1]);
                    mma_bf16(out[dt * 2],     apl, bvh[0], bvh[1]);
                    mma_bf16(out[dt * 2 + 1], aph, bvh[2], bvh[3]);
                    mma_bf16(out[dt * 2 + 1], aph, bvl[2], bvl[3]);
                    mma_bf16(out[dt * 2 + 1], apl, bvh[2], bvh[3]);
                }
            }
        }
        __syncthreads();   // all warps done with stage s before it is refilled
    }

    // ---- finalize ----
    l0 += __shfl_xor_sync(0xffffffffu, l0, 1);
    l0 += __shfl_xor_sync(0xffffffffu, l0, 2);
    l1 += __shfl_xor_sync(0xffffffffu, l1, 1);
    l1 += __shfl_xor_sync(0xffffffffu, l1, 2);
    const float i0 = 1.0f / l0, i1 = 1.0f / l1;
    const int r0g = rowmin + (lane >> 2);
    float* O0 = O + ((size_t)(b * S_LEN + r0g) * NH + h) * HD;
    float* O1 = O0 + (size_t)8 * NH * HD;
#pragma unroll
    for (int dt = 0; dt < 16; dt++) {
        const int col = dt * 8 + (lane & 3) * 2;
        *(float2*)(O0 + col) = make_float2(out[dt][0] * i0, out[dt][1] * i0);
        *(float2*)(O1 + col) = make_float2(out[dt][2] * i1, out[dt][3] * i1);
    }
}

// ---------------------------------------------------------------------------
// Launch
// ---------------------------------------------------------------------------
extern "C" void kernel_launch(void* const* d_in, const int* in_sizes, int n_in,
                              void* d_out, int out_size)
{
    const float* hs = (const float*)d_in[0];
    const float* wq = (const float*)d_in[1];
    const float* wk = (const float*)d_in[2];
    const float* wv = (const float*)d_in[3];
    const float* wo = (const float*)d_in[4];
    const int*  pos = (const int*)  d_in[6];
    float*      out = (float*)d_out;

    float *q, *k, *v, *ao;
    cudaGetSymbolAddress((void**)&q,  g_q);
    cudaGetSymbolAddress((void**)&k,  g_k);
    cudaGetSymbolAddress((void**)&v,  g_v);
    cudaGetSymbolAddress((void**)&ao, g_ao);

    __nv_bfloat16 *hsh, *hsl, *wqh, *wql, *wkh, *wkl, *wvh, *wvl, *woh, *wol, *aoh, *aol;
    __nv_bfloat16 *qh, *ql, *kh, *kl, *vh, *vl;
    cudaGetSymbolAddress((void**)&hsh, g_hs_h); cudaGetSymbolAddress((void**)&hsl, g_hs_l);
    cudaGetSymbolAddress((void**)&wqh, g_wq_h); cudaGetSymbolAddress((void**)&wql, g_wq_l);
    cudaGetSymbolAddress((void**)&wkh, g_wk_h); cudaGetSymbolAddress((void**)&wkl, g_wk_l);
    cudaGetSymbolAddress((void**)&wvh, g_wv_h); cudaGetSymbolAddress((void**)&wvl, g_wv_l);
    cudaGetSymbolAddress((void**)&woh, g_wo_h); cudaGetSymbolAddress((void**)&wol, g_wo_l);
    cudaGetSymbolAddress((void**)&aoh, g_ao_h); cudaGetSymbolAddress((void**)&aol, g_ao_l);
    cudaGetSymbolAddress((void**)&qh,  g_q_h);  cudaGetSymbolAddress((void**)&ql,  g_q_l);
    cudaGetSymbolAddress((void**)&kh,  g_k_h);  cudaGetSymbolAddress((void**)&kl,  g_k_l);
    cudaGetSymbolAddress((void**)&vh,  g_v_h);  cudaGetSymbolAddress((void**)&vl,  g_v_l);

    cudaFuncSetAttribute(gemm_mma_kernel, cudaFuncAttributeMaxDynamicSharedMemorySize, GEMM_SMEM);
    cudaFuncSetAttribute(attn_mma_kernel, cudaFuncAttributeMaxDynamicSharedMemorySize, ATTN_SMEM);

    auto cvt = [&](const float* x, __nv_bfloat16* hi, __nv_bfloat16* lo, int n) {
        int n4 = n / 4;
        cvt_kernel<<<(n4 + 255) / 256, 256>>>((const float4*)x, (uint2*)hi, (uint2*)lo, n4);
    };

    // pre-convert inputs to bf16 hi/lo
    cvt(hs, hsh, hsl, MROWS * HID);
    cvt(wq, wqh, wql, NH * HD * HID);
    cvt(wk, wkh, wkl, NKV * HD * HID);
    cvt(wv, wvh, wvl, NKV * HD * HID);
    cvt(wo, woh, wol, HID * NH * HD);

    // Q/K/V projections
    gemm_mma_kernel<<<dim3((NH  * HD) / TBN, MROWS / TBM), 256, GEMM_SMEM>>>(hsh, hsl, wqh, wql, q, MROWS, NH  * HD, HID);
    gemm_mma_kernel<<<dim3((NKV * HD) / TBN, MROWS / TBM), 256, GEMM_SMEM>>>(hsh, hsl, wkh, wkl, k, MROWS, NKV * HD, HID);
    gemm_mma_kernel<<<dim3((NKV * HD) / TBN, MROWS / TBM), 256, GEMM_SMEM>>>(hsh, hsl, wvh, wvl, v, MROWS, NKV * HD, HID);

    // RoPE + hi/lo conversion for attention operands
    rope_cvt_kernel<<<MROWS, 256>>>(q, k, v, pos, qh, ql, kh, kl, vh, vl);

    // Causal flash attention (mma.sync, cp.async pipelined)
    attn_mma_kernel<<<dim3(S_LEN / ABQ, NH, B_SZ), 256, ATTN_SMEM>>>(qh, ql, kh, kl, vh, vl, ao);

    // Convert attention output, then output projection
    cvt(ao, aoh, aol, MROWS * NH * HD);
    gemm_mma_kernel<<<dim3(HID / TBN, MROWS / TBM), 256, GEMM_SMEM>>>(aoh, aol, woh, wol, out, MROWS, HID, NH * HD);
}

// round 7
// speedup vs baseline: 2.7042x; 1.0190x over previous
#include <cuda_runtime.h>
#include <cuda_bf16.h>
#include <cstdint>

// Problem constants (fixed shapes)
#define NH    32
#define NKV   8
#define HD    128
#define S_LEN 2048
#define B_SZ  2
#define HID   4096
#define MROWS (B_SZ * S_LEN)   // 4096
#define NREP  (NH / NKV)       // 4

#define E16M (16u * 1024u * 1024u)
#define E4M  (4u  * 1024u * 1024u)
#define WQKV_E (6144u * 4096u)   // combined q|k|v weight rows

// ---------------------------------------------------------------------------
// Scratch (device globals; allocation-free per harness rules)
// ---------------------------------------------------------------------------
__device__ float g_q [(size_t)MROWS * NH  * HD];
__device__ float g_k [(size_t)MROWS * NKV * HD];
__device__ float g_v [(size_t)MROWS * NKV * HD];
__device__ float g_ao[(size_t)MROWS * NH  * HD];

// bf16 hi/lo copies
__device__ __nv_bfloat16 g_hs_h[E16M],  g_hs_l[E16M];
__device__ __nv_bfloat16 g_w_h[WQKV_E], g_w_l[WQKV_E];   // wq|wk|wv combined
__device__ __nv_bfloat16 g_wo_h[E16M],  g_wo_l[E16M];
__device__ __nv_bfloat16 g_ao_h[E16M],  g_ao_l[E16M];
// post-rope bf16 hi/lo q/k/v for attention
__device__ __nv_bfloat16 g_q_h[E16M], g_q_l[E16M];
__device__ __nv_bfloat16 g_k_h[E4M],  g_k_l[E4M];
__device__ __nv_bfloat16 g_v_h[E4M],  g_v_l[E4M];

// ---------------------------------------------------------------------------
// Common helpers (sm_80-level PTX only; no 'a'-suffix features)
// ---------------------------------------------------------------------------
__device__ __forceinline__ uint32_t smem_u32(const void* p) {
    uint32_t a;
    asm("{ .reg .u64 t; cvta.to.shared.u64 t, %1; cvt.u32.u64 %0, t; }"
        : "=r"(a) : "l"(p));
    return a;
}
__device__ __forceinline__ uint32_t pack_bf16x2(float a, float b) {
    __nv_bfloat162 h = __floats2bfloat162_rn(a, b);
    return *reinterpret_cast<uint32_t*>(&h);
}
__device__ __forceinline__ void cp16(uint32_t saddr, const void* gptr) {
    asm volatile("cp.async.cg.shared.global [%0], [%1], 16;"
                 :: "r"(saddr), "l"(gptr));
}
__device__ __forceinline__ void cp_commit() {
    asm volatile("cp.async.commit_group;" ::: "memory");
}
template <int N>
__device__ __forceinline__ void cp_wait() {
    asm volatile("cp.async.wait_group %0;" :: "n"(N) : "memory");
}
// ldmatrix.x4, 128B-wide rows (GEMM tiles)
__device__ __forceinline__ void ldm_x4(uint32_t* r, uint32_t base, int row0, int c0) {
    const int l  = (int)(threadIdx.x & 31);
    const int rr = row0 + (l & 15);
    const int cc = (c0 + (l >> 4)) ^ (rr & 7);
    const uint32_t addr = base + (uint32_t)(rr * 128 + cc * 16);
    asm volatile("ldmatrix.sync.aligned.m8n8.x4.shared.b16 {%0,%1,%2,%3}, [%4];"
                 : "=r"(r[0]), "=r"(r[1]), "=r"(r[2]), "=r"(r[3]) : "r"(addr));
}
// ldmatrix.x4, 256B-wide rows (attention tiles, HD=128 bf16 per row)
__device__ __forceinline__ void ldm_x4_256(uint32_t* r, uint32_t base, int row0, int c0) {
    const int l  = (int)(threadIdx.x & 31);
    const int rr = row0 + (l & 15);
    const int cc = (c0 + (l >> 4)) ^ (rr & 7);
    const uint32_t addr = base + (uint32_t)(rr * 256 + cc * 16);
    asm volatile("ldmatrix.sync.aligned.m8n8.x4.shared.b16 {%0,%1,%2,%3}, [%4];"
                 : "=r"(r[0]), "=r"(r[1]), "=r"(r[2]), "=r"(r[3]) : "r"(addr));
}
__device__ __forceinline__ void ldm_x4t_256(uint32_t* r, uint32_t base, int row0, int c0) {
    const int l  = (int)(threadIdx.x & 31);
    const int rr = row0 + (l & 15);
    const int cc = (c0 + (l >> 4)) ^ (rr & 7);
    const uint32_t addr = base + (uint32_t)(rr * 256 + cc * 16);
    asm volatile("ldmatrix.sync.aligned.m8n8.x4.trans.shared.b16 {%0,%1,%2,%3}, [%4];"
                 : "=r"(r[0]), "=r"(r[1]), "=r"(r[2]), "=r"(r[3]) : "r"(addr));
}
__device__ __forceinline__ void mma_bf16(float* d, const uint32_t* a,
                                         uint32_t b0, uint32_t b1) {
    asm volatile(
        "mma.sync.aligned.m16n8k16.row.col.f32.bf16.bf16.f32 "
        "{%0,%1,%2,%3}, {%4,%5,%6,%7}, {%8,%9}, {%0,%1,%2,%3};"
        : "+f"(d[0]), "+f"(d[1]), "+f"(d[2]), "+f"(d[3])
        : "r"(a[0]), "r"(a[1]), "r"(a[2]), "r"(a[3]), "r"(b0), "r"(b1));
}
__device__ __forceinline__ void pack_hilo(float p0, float p1, uint32_t& hi, uint32_t& lo) {
    float h0 = __bfloat162float(__float2bfloat16(p0));
    float h1 = __bfloat162float(__float2bfloat16(p1));
    hi = pack_bf16x2(h0, h1);
    lo = pack_bf16x2(p0 - h0, p1 - h1);
}
__device__ __forceinline__ void store_hilo(__nv_bfloat16* H, __nv_bfloat16* L,
                                           size_t idx, float val) {
    __nv_bfloat16 hb = __float2bfloat16(val);
    H[idx] = hb;
    L[idx] = __float2bfloat16(val - __bfloat162float(hb));
}

// ---------------------------------------------------------------------------
// fp32 -> bf16 hi/lo conversion (elementwise)
// ---------------------------------------------------------------------------
__global__ __launch_bounds__(256) void cvt_kernel(
    const float4* __restrict__ x, uint2* __restrict__ hi,
    uint2* __restrict__ lo, int n4)
{
    int i = blockIdx.x * blockDim.x + threadIdx.x;
    if (i >= n4) return;
    float4 f = x[i];
    float xs[4] = {f.x, f.y, f.z, f.w};
    float hf[4], lf[4];
#pragma unroll
    for (int t = 0; t < 4; t++) {
        __nv_bfloat16 h = __float2bfloat16(xs[t]);
        hf[t] = __bfloat162float(h);
        lf[t] = xs[t] - hf[t];
    }
    uint2 H, L;
    H.x = pack_bf16x2(hf[0], hf[1]); H.y = pack_bf16x2(hf[2], hf[3]);
    L.x = pack_bf16x2(lf[0], lf[1]); L.y = pack_bf16x2(lf[2], lf[3]);
    hi[i] = H;
    lo[i] = L;
}

// ---------------------------------------------------------------------------
// GEMM: C[M,N] = A[M,K] * B[N,K]^T  (bf16 hi/lo x3 MMAs, fp32 out)
// Tile 128x256x64, 256 threads = 8 warps (2 M x 4 N), warp tile 64x64.
// Epilogue routes columns to up to 3 destinations (merged QKV support).
// ---------------------------------------------------------------------------
#define TBM 128
#define TBN 256
#define TBK 64
#define OFF_AH 0
#define OFF_AL 16384
#define OFF_BH 32768
#define OFF_BL 65536
#define STAGE_BYTES 98304
#define GEMM_SMEM (2 * STAGE_BYTES)   // 192 KB

__global__ __launch_bounds__(256) void gemm_mma_kernel(
    const __nv_bfloat16* __restrict__ Ah, const __nv_bfloat16* __restrict__ Al,
    const __nv_bfloat16* __restrict__ Bh, const __nv_bfloat16* __restrict__ Bl,
    float* __restrict__ C0, float* __restrict__ C1, float* __restrict__ C2,
    int ns1, int ns2, int ldc0, int ldc1, int ldc2,
    int M, int N, int K)
{
    extern __shared__ __align__(1024) char smem[];
    const uint32_t sbase = smem_u32(smem);
    const int tid  = threadIdx.x;
    const int lane = tid & 31;
    const int wid  = tid >> 5;
    const int wm   = wid & 1;        // warp rows [wm*64,+64)
    const int wn   = wid >> 1;       // warp cols [wn*64,+64)
    const int m0   = blockIdx.y * TBM;
    const int n0   = blockIdx.x * TBN;
    const int lr4  = lane >> 3;      // 0..3 row within 4-row group
    const int lc   = lane & 7;       // 16B chunk 0..7 within 128B row

    float acc[4][8][4];
#pragma unroll
    for (int i = 0; i < 4; i++)
#pragma unroll
        for (int j = 0; j < 8; j++)
#pragma unroll
            for (int t = 0; t < 4; t++) acc[i][j][t] = 0.0f;

    const int nch = K / TBK;

    auto issue = [&](int s, int k0) {
        const uint32_t st = sbase + s * STAGE_BYTES;
#pragma unroll
        for (int i = 0; i < 4; i++) {           // A: warp owns 16 rows
            const int row = wid * 16 + i * 4 + lr4;
            const uint32_t off = (uint32_t)(row * 128 + ((lc ^ (row & 7)) * 16));
            const size_t gp = (size_t)(m0 + row) * K + k0 + lc * 8;
            cp16(st + OFF_AH + off, Ah + gp);
            cp16(st + OFF_AL + off, Al + gp);
        }
#pragma unroll
        for (int i = 0; i < 8; i++) {           // B: warp owns 32 rows
            const int row = wid * 32 + i * 4 + lr4;
            const uint32_t off = (uint32_t)(row * 128 + ((lc ^ (row & 7)) * 16));
            const size_t gp = (size_t)(n0 + row) * K + k0 + lc * 8;
            cp16(st + OFF_BH + off, Bh + gp);
            cp16(st + OFF_BL + off, Bl + gp);
        }
        cp_commit();
    };

    issue(0, 0);

    for (int ch = 0; ch < nch; ch++) {
        const int s = ch & 1;
        if (ch + 1 < nch) {
            issue(1 - s, (ch + 1) * TBK);
            cp_wait<1>();
        } else {
            cp_wait<0>();
        }
        __syncthreads();

        const uint32_t stAh = sbase + s * STAGE_BYTES + OFF_AH;
        const uint32_t stAl = sbase + s * STAGE_BYTES + OFF_AL;
        const uint32_t stBh = sbase + s * STAGE_BYTES + OFF_BH;
        const uint32_t stBl = sbase + s * STAGE_BYTES + OFF_BL;
#pragma unroll
        for (int kt = 0; kt < 4; kt++) {
            uint32_t ah[4][4], al[4][4], bh[4][4], bl[4][4];
#pragma unroll
            for (int mt = 0; mt < 4; mt++) {
                ldm_x4(ah[mt], stAh, wm * 64 + mt * 16, kt * 2);
                ldm_x4(al[mt], stAl, wm * 64 + mt * 16, kt * 2);
            }
#pragma unroll
            for (int bp = 0; bp < 4; bp++) {
                ldm_x4(bh[bp], stBh, wn * 64 + bp * 16, kt * 2);
                ldm_x4(bl[bp], stBl, wn * 64 + bp * 16, kt * 2);
            }
#pragma unroll
            for (int mt = 0; mt < 4; mt++)
#pragma unroll
                for (int nt = 0; nt < 8; nt++) {
                    const int bp = nt >> 1, o = nt & 1;
                    mma_bf16(acc[mt][nt], ah[mt], bh[bp][o], bh[bp][o + 2]);
                    mma_bf16(acc[mt][nt], ah[mt], bl[bp][o], bl[bp][o + 2]);
                    mma_bf16(acc[mt][nt], al[mt], bh[bp][o], bh[bp][o + 2]);
                }
        }
        __syncthreads();
    }

    // epilogue with column routing (CTA tile never straddles a split)
    float* Cb; int ldc, nc0;
    if (n0 < ns1)      { Cb = C0; ldc = ldc0; nc0 = n0; }
    else if (n0 < ns2) { Cb = C1; ldc = ldc1; nc0 = n0 - ns1; }
    else               { Cb = C2; ldc = ldc2; nc0 = n0 - ns2; }
#pragma unroll
    for (int mt = 0; mt < 4; mt++) {
        const int row = m0 + wm * 64 + mt * 16 + (lane >> 2);
#pragma unroll
        for (int nt = 0; nt < 8; nt++) {
            const int col = nc0 + wn * 64 + nt * 8 + (lane & 3) * 2;
            float2 v0 = make_float2(acc[mt][nt][0], acc[mt][nt][1]);
            float2 v1 = make_float2(acc[mt][nt][2], acc[mt][nt][3]);
            *(float2*)(Cb + (size_t)row * ldc + col)       = v0;
            *(float2*)(Cb + (size_t)(row + 8) * ldc + col) = v1;
        }
    }
}

// ---------------------------------------------------------------------------
// RoPE + fp32 -> bf16 hi/lo for q, k; straight hi/lo split for v
// ---------------------------------------------------------------------------
__global__ __launch_bounds__(256) void rope_cvt_kernel(
    const float* __restrict__ q, const float* __restrict__ k,
    const float* __restrict__ v, const int* __restrict__ pos,
    __nv_bfloat16* __restrict__ qh, __nv_bfloat16* __restrict__ ql,
    __nv_bfloat16* __restrict__ kh, __nv_bfloat16* __restrict__ kl,
    __nv_bfloat16* __restrict__ vh, __nv_bfloat16* __restrict__ vl)
{
    const int bs = blockIdx.x;
    const float p = (float)pos[bs];
    const float c1 = -0.2076205059304601f;        // -log2(10000)/64
    for (int i = threadIdx.x; i < 3072; i += 256) {
        if (i < 2560) {
            const float* base; size_t idx; int d;
            __nv_bfloat16 *H, *L;
            if (i < 2048) {
                int hh = i >> 6; d = i & 63;
                idx = ((size_t)bs * NH + hh) * HD;
                base = q + idx; H = qh; L = ql;
            } else {
                int j = i - 2048;
                int hh = j >> 6; d = j & 63;
                idx = ((size_t)bs * NKV + hh) * HD;
                base = k + idx; H = kh; L = kl;
            }
            float inv = exp2f(c1 * (float)d);
            float ang = p * inv;
            float sv, cv;
            sincosf(ang, &sv, &cv);
            float x1 = base[d], x2 = base[d + 64];
            store_hilo(H, L, idx + d,      x1 * cv - x2 * sv);
            store_hilo(H, L, idx + d + 64, x2 * cv + x1 * sv);
        } else {
            int j = i - 2560;                     // 0..511
            size_t idx = (size_t)bs * NKV * HD + j * 2;
            float2 f = *(const float2*)(v + idx);
            store_hilo(vh, vl, idx,     f.x);
            store_hilo(vh, vl, idx + 1, f.y);
        }
    }
}

// ---------------------------------------------------------------------------
// Flash attention via mma.sync (bf16 hi/lo x3), fp32 softmax, causal.
// CTA: 64 q-rows x 1 head, 4 warps, 96KB smem -> 2 CTAs/SM (pipe overlap).
// ---------------------------------------------------------------------------
#define ABQ  64
#define ABKV 32
#define AQH 0
#define AQL 16384
#define KV0 32768          // per-stage: KH 0, KL 8K, VH 16K, VL 24K
#define SKH 0
#define SKL 8192
#define SVH 16384
#define SVL 24576
#define KVSTAGE 32768
#define ATTN_SMEM (32768 + 2 * KVSTAGE)   // 96 KB

__global__ __launch_bounds__(128, 2) void attn_mma_kernel(
    const __nv_bfloat16* __restrict__ Qh, const __nv_bfloat16* __restrict__ Ql,
    const __nv_bfloat16* __restrict__ Kh, const __nv_bfloat16* __restrict__ Kl,
    const __nv_bfloat16* __restrict__ Vh, const __nv_bfloat16* __restrict__ Vl,
    float* __restrict__ O)
{
    extern __shared__ __align__(1024) char smem[];
    const uint32_t sbase = smem_u32(smem);
    const int tid  = threadIdx.x;
    const int lane = tid & 31;
    const int wq   = tid >> 5;                              // 0..3
    const int qb   = (int)gridDim.x - 1 - (int)blockIdx.x;  // big tiles first
    const int h    = blockIdx.y, b = blockIdx.z;
    const int g    = h / NREP;
    const int q0   = qb * ABQ;
    const int rowmin = q0 + wq * 16;
    const int lr8 = tid >> 4;      // 0..7 row within 8-row pass
    const int lc  = tid & 15;      // 16B chunk within 256B row

    // ---- Q tile: cp.async (8 rows x 256B per pass) ----
#pragma unroll
    for (int i = 0; i < 8; i++) {
        const int row = i * 8 + lr8;
        const uint32_t off = (uint32_t)(row * 256 + ((lc ^ (row & 7)) * 16));
        const size_t gp = ((size_t)(b * S_LEN + q0 + row) * NH + h) * HD + lc * 8;
        cp16(sbase + AQH + off, Qh + gp);
        cp16(sbase + AQL + off, Ql + gp);
    }

    auto issue_kv = [&](int s, int k0) {
        const uint32_t st = sbase + KV0 + s * KVSTAGE;
#pragma unroll
        for (int i = 0; i < 4; i++) {
            const int row = i * 8 + lr8;
            const uint32_t off = (uint32_t)(row * 256 + ((lc ^ (row & 7)) * 16));
            const size_t gp = ((size_t)(b * S_LEN + k0 + row) * NKV + g) * HD + lc * 8;
            cp16(st + SKH + off, Kh + gp);
            cp16(st + SKL + off, Kl + gp);
            cp16(st + SVH + off, Vh + gp);
            cp16(st + SVL + off, Vl + gp);
        }
    };
    issue_kv(0, 0);
    cp_commit();   // group0 = Q + kv0

    float out[16][4];
#pragma unroll
    for (int i = 0; i < 16; i++)
#pragma unroll
        for (int j = 0; j < 4; j++) out[i][j] = 0.0f;
    float m0 = -1e30f, m1 = -1e30f, l0 = 0.0f, l1 = 0.0f;
    const float scale = 0.08838834764831845f;   // 1/sqrt(128)
    const int ntile = 2 * qb + 2;

    for (int kb = 0; kb < ntile; kb++) {
        const int s = kb & 1;
        const int k0 = kb * ABKV;
        if (kb + 1 < ntile) {
            issue_kv(1 - s, (kb + 1) * ABKV);
            cp_commit();
            cp_wait<1>();
        } else {
            cp_wait<0>();
        }
        __syncthreads();

        if (k0 <= rowmin + 15) {   // else tile fully masked for this warp
            const uint32_t stK = sbase + KV0 + s * KVSTAGE;

            // ---- S = Q K^T  (16 x 32 x 128) ----
            float sc[4][4];
#pragma unroll
            for (int nt = 0; nt < 4; nt++)
#pragma unroll
                for (int j = 0; j < 4; j++) sc[nt][j] = 0.0f;
#pragma unroll
            for (int kt = 0; kt < 8; kt++) {
                uint32_t aqh[4], aql[4];
                ldm_x4_256(aqh, sbase + AQH, wq * 16, kt * 2);
                ldm_x4_256(aql, sbase + AQL, wq * 16, kt * 2);
#pragma unroll
                for (int bp = 0; bp < 2; bp++) {
                    uint32_t bkh[4], bkl[4];
                    ldm_x4_256(bkh, stK + SKH, bp * 16, kt * 2);
                    ldm_x4_256(bkl, stK + SKL, bp * 16, kt * 2);
#pragma unroll
                    for (int o = 0; o < 2; o++) {
                        const int nt = bp * 2 + o;
                        mma_bf16(sc[nt], aqh, bkh[o], bkh[o + 2]);
                        mma_bf16(sc[nt], aqh, bkl[o], bkl[o + 2]);
                        mma_bf16(sc[nt], aql, bkh[o], bkh[o + 2]);
                    }
                }
            }

            // ---- scale + causal mask + online softmax ----
            const int r0g = rowmin + (lane >> 2);
            const bool domask = (k0 + ABKV - 1) > rowmin;
            float mx0 = -1e30f, mx1 = -1e30f;
#pragma unroll
            for (int nt = 0; nt < 4; nt++) {
#pragma unroll
                for (int j = 0; j < 4; j++) {
                    float v = sc[nt][j] * scale;
                    if (domask) {
                        int cg = k0 + nt * 8 + (lane & 3) * 2 + (j & 1);
                        int rg = r0g + ((j >> 1) << 3);
                        if (cg > rg) v = -1e30f;
                    }
                    sc[nt][j] = v;
                }
                mx0 = fmaxf(mx0, fmaxf(sc[nt][0], sc[nt][1]));
                mx1 = fmaxf(mx1, fmaxf(sc[nt][2], sc[nt][3]));
            }
            mx0 = fmaxf(mx0, __shfl_xor_sync(0xffffffffu, mx0, 1));
            mx0 = fmaxf(mx0, __shfl_xor_sync(0xffffffffu, mx0, 2));
            mx1 = fmaxf(mx1, __shfl_xor_sync(0xffffffffu, mx1, 1));
            mx1 = fmaxf(mx1, __shfl_xor_sync(0xffffffffu, mx1, 2));
            const float mn0 = fmaxf(m0, mx0), mn1 = fmaxf(m1, mx1);
            const float a0 = __expf(m0 - mn0), a1 = __expf(m1 - mn1);
            m0 = mn0; m1 = mn1;
            float ps0 = 0.0f, ps1 = 0.0f;
#pragma unroll
            for (int nt = 0; nt < 4; nt++) {
                sc[nt][0] = __expf(sc[nt][0] - mn0); ps0 += sc[nt][0];
                sc[nt][1] = __expf(sc[nt][1] - mn0); ps0 += sc[nt][1];
                sc[nt][2] = __expf(sc[nt][2] - mn1); ps1 += sc[nt][2];
                sc[nt][3] = __expf(sc[nt][3] - mn1); ps1 += sc[nt][3];
            }
            l0 = l0 * a0 + ps0;
            l1 = l1 * a1 + ps1;
#pragma unroll
            for (int dt = 0; dt < 16; dt++) {
                out[dt][0] *= a0; out[dt][1] *= a0;
                out[dt][2] *= a1; out[dt][3] *= a1;
            }

            // ---- O += P V  (16 x 128 x 32) ----
#pragma unroll
            for (int ktp = 0; ktp < 2; ktp++) {
                uint32_t aph[4], apl[4];
                const int t0 = ktp * 2, t1 = t0 + 1;
                pack_hilo(sc[t0][0], sc[t0][1], aph[0], apl[0]);
                pack_hilo(sc[t0][2], sc[t0][3], aph[1], apl[1]);
                pack_hilo(sc[t1][0], sc[t1][1], aph[2], apl[2]);
                pack_hilo(sc[t1][2], sc[t1][3], aph[3], apl[3]);
#pragma unroll
                for (int dt = 0; dt < 8; dt++) {
                    uint32_t bvh[4], bvl[4];
                    ldm_x4t_256(bvh, stK + SVH, ktp * 16, dt * 2);
                    ldm_x4t_256(bvl, stK + SVL, ktp * 16, dt * 2);
                    mma_bf16(out[dt * 2],     aph, bvh[0], bvh[1]);
                    mma_bf16(out[dt * 2],     aph, bvl[0], bvl[1]);
                    mma_bf16(out[dt * 2],     apl, bvh[0], bvh[1]);
                    mma_bf16(out[dt * 2 + 1], aph, bvh[2], bvh[3]);
                    mma_bf16(out[dt * 2 + 1], aph, bvl[2], bvl[3]);
                    mma_bf16(out[dt * 2 + 1], apl, bvh[2], bvh[3]);
                }
            }
        }
        __syncthreads();   // all warps done with stage s before it is refilled
    }

    // ---- finalize ----
    l0 += __shfl_xor_sync(0xffffffffu, l0, 1);
    l0 += __shfl_xor_sync(0xffffffffu, l0, 2);
    l1 += __shfl_xor_sync(0xffffffffu, l1, 1);
    l1 += __shfl_xor_sync(0xffffffffu, l1, 2);
    const float i0 = 1.0f / l0, i1 = 1.0f / l1;
    const int r0g = rowmin + (lane >> 2);
    float* O0 = O + ((size_t)(b * S_LEN + r0g) * NH + h) * HD;
    float* O1 = O0 + (size_t)8 * NH * HD;
#pragma unroll
    for (int dt = 0; dt < 16; dt++) {
        const int col = dt * 8 + (lane & 3) * 2;
        *(float2*)(O0 + col) = make_float2(out[dt][0] * i0, out[dt][1] * i0);
        *(float2*)(O1 + col) = make_float2(out[dt][2] * i1, out[dt][3] * i1);
    }
}

// ---------------------------------------------------------------------------
// Launch
// ---------------------------------------------------------------------------
extern "C" void kernel_launch(void* const* d_in, const int* in_sizes, int n_in,
                              void* d_out, int out_size)
{
    const float* hs = (const float*)d_in[0];
    const float* wq = (const float*)d_in[1];
    const float* wk = (const float*)d_in[2];
    const float* wv = (const float*)d_in[3];
    const float* wo = (const float*)d_in[4];
    const int*  pos = (const int*)  d_in[6];
    float*      out = (float*)d_out;

    float *q, *k, *v, *ao;
    cudaGetSymbolAddress((void**)&q,  g_q);
    cudaGetSymbolAddress((void**)&k,  g_k);
    cudaGetSymbolAddress((void**)&v,  g_v);
    cudaGetSymbolAddress((void**)&ao, g_ao);

    __nv_bfloat16 *hsh, *hsl, *wh, *wl, *woh, *wol, *aoh, *aol;
    __nv_bfloat16 *qh, *ql, *kh, *kl, *vh, *vl;
    cudaGetSymbolAddress((void**)&hsh, g_hs_h); cudaGetSymbolAddress((void**)&hsl, g_hs_l);
    cudaGetSymbolAddress((void**)&wh,  g_w_h);  cudaGetSymbolAddress((void**)&wl,  g_w_l);
    cudaGetSymbolAddress((void**)&woh, g_wo_h); cudaGetSymbolAddress((void**)&wol, g_wo_l);
    cudaGetSymbolAddress((void**)&aoh, g_ao_h); cudaGetSymbolAddress((void**)&aol, g_ao_l);
    cudaGetSymbolAddress((void**)&qh,  g_q_h);  cudaGetSymbolAddress((void**)&ql,  g_q_l);
    cudaGetSymbolAddress((void**)&kh,  g_k_h);  cudaGetSymbolAddress((void**)&kl,  g_k_l);
    cudaGetSymbolAddress((void**)&vh,  g_v_h);  cudaGetSymbolAddress((void**)&vl,  g_v_l);

    cudaFuncSetAttribute(gemm_mma_kernel, cudaFuncAttributeMaxDynamicSharedMemorySize, GEMM_SMEM);
    cudaFuncSetAttribute(attn_mma_kernel, cudaFuncAttributeMaxDynamicSharedMemorySize, ATTN_SMEM);

    auto cvt = [&](const float* x, __nv_bfloat16* hi, __nv_bfloat16* lo, int n) {
        int n4 = n / 4;
        cvt_kernel<<<(n4 + 255) / 256, 256>>>((const float4*)x, (uint2*)hi, (uint2*)lo, n4);
    };

    // pre-convert inputs; wq|wk|wv go into one combined [6144,4096] buffer
    cvt(hs, hsh, hsl, MROWS * HID);
    cvt(wq, wh,                 wl,                 NH  * HD * HID);
    cvt(wk, wh + 16777216u,     wl + 16777216u,     NKV * HD * HID);
    cvt(wv, wh + 20971520u,     wl + 20971520u,     NKV * HD * HID);
    cvt(wo, woh, wol, HID * NH * HD);

    // Merged QKV projection: N = 6144, columns routed to q / k / v
    gemm_mma_kernel<<<dim3(6144 / TBN, MROWS / TBM), 256, GEMM_SMEM>>>(
        hsh, hsl, wh, wl, q, k, v,
        4096, 5120, NH * HD, NKV * HD, NKV * HD,
        MROWS, 6144, HID);

    // RoPE + hi/lo conversion for attention operands
    rope_cvt_kernel<<<MROWS, 256>>>(q, k, v, pos, qh, ql, kh, kl, vh, vl);

    // Causal flash attention (mma.sync, 2 CTAs/SM)
    attn_mma_kernel<<<dim3(S_LEN / ABQ, NH, B_SZ), 128, ATTN_SMEM>>>(qh, ql, kh, kl, vh, vl, ao);

    // Convert attention output, then output projection
    cvt(ao, aoh, aol, MROWS * NH * HD);
    gemm_mma_kernel<<<dim3(HID / TBN, MROWS / TBM), 256, GEMM_SMEM>>>(
        aoh, aol, woh, wol, out, out, out,
        HID, HID, HID, HID, HID,
        MROWS, HID, NH * HD);
}

// round 8
// speedup vs baseline: 2.7316x; 1.0101x over previous
#include <cuda_runtime.h>
#include <cuda_bf16.h>
#include <cstdint>

// Problem constants (fixed shapes)
#define NH    32
#define NKV   8
#define HD    128
#define S_LEN 2048
#define B_SZ  2
#define HID   4096
#define MROWS (B_SZ * S_LEN)   // 4096
#define NREP  (NH / NKV)       // 4

#define E16M (16u * 1024u * 1024u)
#define E4M  (4u  * 1024u * 1024u)
#define WQKV_E (6144u * 4096u)   // combined q|k|v weight rows

// ---------------------------------------------------------------------------
// Scratch (device globals; allocation-free per harness rules)
// ---------------------------------------------------------------------------
__device__ float g_q [(size_t)MROWS * NH  * HD];
__device__ float g_k [(size_t)MROWS * NKV * HD];

// bf16 hi/lo copies
__device__ __nv_bfloat16 g_hs_h[E16M],  g_hs_l[E16M];
__device__ __nv_bfloat16 g_w_h[WQKV_E], g_w_l[WQKV_E];   // wq|wk|wv combined
__device__ __nv_bfloat16 g_wo_h[E16M],  g_wo_l[E16M];
__device__ __nv_bfloat16 g_ao_h[E16M],  g_ao_l[E16M];
// post-rope bf16 hi/lo q/k, direct-split v for attention
__device__ __nv_bfloat16 g_q_h[E16M], g_q_l[E16M];
__device__ __nv_bfloat16 g_k_h[E4M],  g_k_l[E4M];
__device__ __nv_bfloat16 g_v_h[E4M],  g_v_l[E4M];

// ---------------------------------------------------------------------------
// Common helpers (sm_80-level PTX only; no 'a'-suffix features)
// ---------------------------------------------------------------------------
__device__ __forceinline__ uint32_t smem_u32(const void* p) {
    uint32_t a;
    asm("{ .reg .u64 t; cvta.to.shared.u64 t, %1; cvt.u32.u64 %0, t; }"
        : "=r"(a) : "l"(p));
    return a;
}
__device__ __forceinline__ uint32_t pack_bf16x2(float a, float b) {
    __nv_bfloat162 h = __floats2bfloat162_rn(a, b);
    return *reinterpret_cast<uint32_t*>(&h);
}
__device__ __forceinline__ void cp16(uint32_t saddr, const void* gptr) {
    asm volatile("cp.async.cg.shared.global [%0], [%1], 16;"
                 :: "r"(saddr), "l"(gptr));
}
__device__ __forceinline__ void cp_commit() {
    asm volatile("cp.async.commit_group;" ::: "memory");
}
template <int N>
__device__ __forceinline__ void cp_wait() {
    asm volatile("cp.async.wait_group %0;" :: "n"(N) : "memory");
}
// ldmatrix.x4, 128B-wide rows (GEMM tiles)
__device__ __forceinline__ void ldm_x4(uint32_t* r, uint32_t base, int row0, int c0) {
    const int l  = (int)(threadIdx.x & 31);
    const int rr = row0 + (l & 15);
    const int cc = (c0 + (l >> 4)) ^ (rr & 7);
    const uint32_t addr = base + (uint32_t)(rr * 128 + cc * 16);
    asm volatile("ldmatrix.sync.aligned.m8n8.x4.shared.b16 {%0,%1,%2,%3}, [%4];"
                 : "=r"(r[0]), "=r"(r[1]), "=r"(r[2]), "=r"(r[3]) : "r"(addr));
}
// ldmatrix.x4, 256B-wide rows (attention tiles, HD=128 bf16 per row)
__device__ __forceinline__ void ldm_x4_256(uint32_t* r, uint32_t base, int row0, int c0) {
    const int l  = (int)(threadIdx.x & 31);
    const int rr = row0 + (l & 15);
    const int cc = (c0 + (l >> 4)) ^ (rr & 7);
    const uint32_t addr = base + (uint32_t)(rr * 256 + cc * 16);
    asm volatile("ldmatrix.sync.aligned.m8n8.x4.shared.b16 {%0,%1,%2,%3}, [%4];"
                 : "=r"(r[0]), "=r"(r[1]), "=r"(r[2]), "=r"(r[3]) : "r"(addr));
}
__device__ __forceinline__ void ldm_x4t_256(uint32_t* r, uint32_t base, int row0, int c0) {
    const int l  = (int)(threadIdx.x & 31);
    const int rr = row0 + (l & 15);
    const int cc = (c0 + (l >> 4)) ^ (rr & 7);
    const uint32_t addr = base + (uint32_t)(rr * 256 + cc * 16);
    asm volatile("ldmatrix.sync.aligned.m8n8.x4.trans.shared.b16 {%0,%1,%2,%3}, [%4];"
                 : "=r"(r[0]), "=r"(r[1]), "=r"(r[2]), "=r"(r[3]) : "r"(addr));
}
__device__ __forceinline__ void mma_bf16(float* d, const uint32_t* a,
                                         uint32_t b0, uint32_t b1) {
    asm volatile(
        "mma.sync.aligned.m16n8k16.row.col.f32.bf16.bf16.f32 "
        "{%0,%1,%2,%3}, {%4,%5,%6,%7}, {%8,%9}, {%0,%1,%2,%3};"
        : "+f"(d[0]), "+f"(d[1]), "+f"(d[2]), "+f"(d[3])
        : "r"(a[0]), "r"(a[1]), "r"(a[2]), "r"(a[3]), "r"(b0), "r"(b1));
}
__device__ __forceinline__ void pack_hilo(float p0, float p1, uint32_t& hi, uint32_t& lo) {
    float h0 = __bfloat162float(__float2bfloat16(p0));
    float h1 = __bfloat162float(__float2bfloat16(p1));
    hi = pack_bf16x2(h0, h1);
    lo = pack_bf16x2(p0 - h0, p1 - h1);
}
__device__ __forceinline__ void store_hilo(__nv_bfloat16* H, __nv_bfloat16* L,
                                           size_t idx, float val) {
    __nv_bfloat16 hb = __float2bfloat16(val);
    H[idx] = hb;
    L[idx] = __float2bfloat16(val - __bfloat162float(hb));
}

// ---------------------------------------------------------------------------
// fp32 -> bf16 hi/lo conversion (elementwise)
// ---------------------------------------------------------------------------
__global__ __launch_bounds__(256) void cvt_kernel(
    const float4* __restrict__ x, uint2* __restrict__ hi,
    uint2* __restrict__ lo, int n4)
{
    int i = blockIdx.x * blockDim.x + threadIdx.x;
    if (i >= n4) return;
    float4 f = x[i];
    float xs[4] = {f.x, f.y, f.z, f.w};
    float hf[4], lf[4];
#pragma unroll
    for (int t = 0; t < 4; t++) {
        __nv_bfloat16 h = __float2bfloat16(xs[t]);
        hf[t] = __bfloat162float(h);
        lf[t] = xs[t] - hf[t];
    }
    uint2 H, L;
    H.x = pack_bf16x2(hf[0], hf[1]); H.y = pack_bf16x2(hf[2], hf[3]);
    L.x = pack_bf16x2(lf[0], lf[1]); L.y = pack_bf16x2(lf[2], lf[3]);
    hi[i] = H;
    lo[i] = L;
}

// ---------------------------------------------------------------------------
// GEMM: C[M,N] = A[M,K] * B[N,K]^T  (bf16 hi/lo x3 MMAs, fp32 out)
// Tile 128x256x64, 256 threads = 8 warps (2 M x 4 N), warp tile 64x64.
// Epilogue routes columns to up to 3 destinations; dest 2 may emit bf16 hi/lo.
// ---------------------------------------------------------------------------
#define TBM 128
#define TBN 256
#define TBK 64
#define OFF_AH 0
#define OFF_AL 16384
#define OFF_BH 32768
#define OFF_BL 65536
#define STAGE_BYTES 98304
#define GEMM_SMEM (2 * STAGE_BYTES)   // 192 KB

__global__ __launch_bounds__(256) void gemm_mma_kernel(
    const __nv_bfloat16* __restrict__ Ah, const __nv_bfloat16* __restrict__ Al,
    const __nv_bfloat16* __restrict__ Bh, const __nv_bfloat16* __restrict__ Bl,
    float* __restrict__ C0, float* __restrict__ C1,
    __nv_bfloat16* __restrict__ C2h, __nv_bfloat16* __restrict__ C2l,
    int ns1, int ns2, int ldc0, int ldc1, int ldc2,
    int M, int N, int K)
{
    extern __shared__ __align__(1024) char smem[];
    const uint32_t sbase = smem_u32(smem);
    const int tid  = threadIdx.x;
    const int lane = tid & 31;
    const int wid  = tid >> 5;
    const int wm   = wid & 1;        // warp rows [wm*64,+64)
    const int wn   = wid >> 1;       // warp cols [wn*64,+64)
    const int m0   = blockIdx.y * TBM;
    const int n0   = blockIdx.x * TBN;
    const int lr4  = lane >> 3;      // 0..3 row within 4-row group
    const int lc   = lane & 7;       // 16B chunk 0..7 within 128B row

    float acc[4][8][4];
#pragma unroll
    for (int i = 0; i < 4; i++)
#pragma unroll
        for (int j = 0; j < 8; j++)
#pragma unroll
            for (int t = 0; t < 4; t++) acc[i][j][t] = 0.0f;

    const int nch = K / TBK;

    auto issue = [&](int s, int k0) {
        const uint32_t st = sbase + s * STAGE_BYTES;
#pragma unroll
        for (int i = 0; i < 4; i++) {           // A: warp owns 16 rows
            const int row = wid * 16 + i * 4 + lr4;
            const uint32_t off = (uint32_t)(row * 128 + ((lc ^ (row & 7)) * 16));
            const size_t gp = (size_t)(m0 + row) * K + k0 + lc * 8;
            cp16(st + OFF_AH + off, Ah + gp);
            cp16(st + OFF_AL + off, Al + gp);
        }
#pragma unroll
        for (int i = 0; i < 8; i++) {           // B: warp owns 32 rows
            const int row = wid * 32 + i * 4 + lr4;
            const uint32_t off = (uint32_t)(row * 128 + ((lc ^ (row & 7)) * 16));
            const size_t gp = (size_t)(n0 + row) * K + k0 + lc * 8;
            cp16(st + OFF_BH + off, Bh + gp);
            cp16(st + OFF_BL + off, Bl + gp);
        }
        cp_commit();
    };

    issue(0, 0);

    for (int ch = 0; ch < nch; ch++) {
        const int s = ch & 1;
        if (ch + 1 < nch) {
            issue(1 - s, (ch + 1) * TBK);
            cp_wait<1>();
        } else {
            cp_wait<0>();
        }
        __syncthreads();

        const uint32_t stAh = sbase + s * STAGE_BYTES + OFF_AH;
        const uint32_t stAl = sbase + s * STAGE_BYTES + OFF_AL;
        const uint32_t stBh = sbase + s * STAGE_BYTES + OFF_BH;
        const uint32_t stBl = sbase + s * STAGE_BYTES + OFF_BL;
#pragma unroll
        for (int kt = 0; kt < 4; kt++) {
            uint32_t ah[4][4], al[4][4], bh[4][4], bl[4][4];
#pragma unroll
            for (int mt = 0; mt < 4; mt++) {
                ldm_x4(ah[mt], stAh, wm * 64 + mt * 16, kt * 2);
                ldm_x4(al[mt], stAl, wm * 64 + mt * 16, kt * 2);
            }
#pragma unroll
            for (int bp = 0; bp < 4; bp++) {
                ldm_x4(bh[bp], stBh, wn * 64 + bp * 16, kt * 2);
                ldm_x4(bl[bp], stBl, wn * 64 + bp * 16, kt * 2);
            }
#pragma unroll
            for (int mt = 0; mt < 4; mt++)
#pragma unroll
                for (int nt = 0; nt < 8; nt++) {
                    const int bp = nt >> 1, o = nt & 1;
                    mma_bf16(acc[mt][nt], ah[mt], bh[bp][o], bh[bp][o + 2]);
                    mma_bf16(acc[mt][nt], ah[mt], bl[bp][o], bl[bp][o + 2]);
                    mma_bf16(acc[mt][nt], al[mt], bh[bp][o], bh[bp][o + 2]);
                }
        }
        __syncthreads();
    }

    // epilogue with column routing (CTA tile never straddles a split)
    if (n0 >= ns2 && C2h != nullptr) {
        // dest 2: emit bf16 hi/lo directly (v path, no rope needed)
        const int nc0 = n0 - ns2;
#pragma unroll
        for (int mt = 0; mt < 4; mt++) {
            const int row = m0 + wm * 64 + mt * 16 + (lane >> 2);
#pragma unroll
            for (int nt = 0; nt < 8; nt++) {
                const int col = nc0 + wn * 64 + nt * 8 + (lane & 3) * 2;
                uint32_t h0, l0v, h1, l1v;
                pack_hilo(acc[mt][nt][0], acc[mt][nt][1], h0, l0v);
                pack_hilo(acc[mt][nt][2], acc[mt][nt][3], h1, l1v);
                *(uint32_t*)(C2h + (size_t)row * ldc2 + col)       = h0;
                *(uint32_t*)(C2l + (size_t)row * ldc2 + col)       = l0v;
                *(uint32_t*)(C2h + (size_t)(row + 8) * ldc2 + col) = h1;
                *(uint32_t*)(C2l + (size_t)(row + 8) * ldc2 + col) = l1v;
            }
        }
        return;
    }
    float* Cb; int ldc, nc0;
    if (n0 < ns1) { Cb = C0; ldc = ldc0; nc0 = n0; }
    else          { Cb = C1; ldc = ldc1; nc0 = n0 - ns1; }
#pragma unroll
    for (int mt = 0; mt < 4; mt++) {
        const int row = m0 + wm * 64 + mt * 16 + (lane >> 2);
#pragma unroll
        for (int nt = 0; nt < 8; nt++) {
            const int col = nc0 + wn * 64 + nt * 8 + (lane & 3) * 2;
            float2 v0 = make_float2(acc[mt][nt][0], acc[mt][nt][1]);
            float2 v1 = make_float2(acc[mt][nt][2], acc[mt][nt][3]);
            *(float2*)(Cb + (size_t)row * ldc + col)       = v0;
            *(float2*)(Cb + (size_t)(row + 8) * ldc + col) = v1;
        }
    }
}

// ---------------------------------------------------------------------------
// RoPE + fp32 -> bf16 hi/lo for q, k (v handled by GEMM epilogue)
// ---------------------------------------------------------------------------
__global__ __launch_bounds__(256) void rope_cvt_kernel(
    const float* __restrict__ q, const float* __restrict__ k,
    const int* __restrict__ pos,
    __nv_bfloat16* __restrict__ qh, __nv_bfloat16* __restrict__ ql,
    __nv_bfloat16* __restrict__ kh, __nv_bfloat16* __restrict__ kl)
{
    const int bs = blockIdx.x;
    const float p = (float)pos[bs];
    const float c1 = -0.2076205059304601f;        // -log2(10000)/64
    for (int i = threadIdx.x; i < 2560; i += 256) {
        const float* base; size_t idx; int d;
        __nv_bfloat16 *H, *L;
        if (i < 2048) {
            int hh = i >> 6; d = i & 63;
            idx = ((size_t)bs * NH + hh) * HD;
            base = q + idx; H = qh; L = ql;
        } else {
            int j = i - 2048;
            int hh = j >> 6; d = j & 63;
            idx = ((size_t)bs * NKV + hh) * HD;
            base = k + idx; H = kh; L = kl;
        }
        float inv = exp2f(c1 * (float)d);
        float ang = p * inv;
        float sv, cv;
        sincosf(ang, &sv, &cv);
        float x1 = base[d], x2 = base[d + 64];
        store_hilo(H, L, idx + d,      x1 * cv - x2 * sv);
        store_hilo(H, L, idx + d + 64, x2 * cv + x1 * sv);
    }
}

// ---------------------------------------------------------------------------
// Flash attention via mma.sync (bf16 hi/lo x3), fp32 softmax (exp2), causal.
// CTA: 64 q-rows x 1 head, 4 warps, 96KB smem -> 2 CTAs/SM.
// Q fragments hoisted out of the KV loop; output written as bf16 hi/lo.
// ---------------------------------------------------------------------------
#define ABQ  64
#define ABKV 32
#define AQH 0
#define AQL 16384
#define KV0 32768          // per-stage: KH 0, KL 8K, VH 16K, VL 24K
#define SKH 0
#define SKL 8192
#define SVH 16384
#define SVL 24576
#define KVSTAGE 32768
#define ATTN_SMEM (32768 + 2 * KVSTAGE)   // 96 KB

__global__ __launch_bounds__(128, 2) void attn_mma_kernel(
    const __nv_bfloat16* __restrict__ Qh, const __nv_bfloat16* __restrict__ Ql,
    const __nv_bfloat16* __restrict__ Kh, const __nv_bfloat16* __restrict__ Kl,
    const __nv_bfloat16* __restrict__ Vh, const __nv_bfloat16* __restrict__ Vl,
    __nv_bfloat16* __restrict__ AOh, __nv_bfloat16* __restrict__ AOl)
{
    extern __shared__ __align__(1024) char smem[];
    const uint32_t sbase = smem_u32(smem);
    const int tid  = threadIdx.x;
    const int lane = tid & 31;
    const int wq   = tid >> 5;                              // 0..3
    const int qb   = (int)gridDim.x - 1 - (int)blockIdx.x;  // big tiles first
    const int h    = blockIdx.y, b = blockIdx.z;
    const int g    = h / NREP;
    const int q0   = qb * ABQ;
    const int rowmin = q0 + wq * 16;
    const int lr8 = tid >> 4;      // 0..7 row within 8-row pass
    const int lc  = tid & 15;      // 16B chunk within 256B row

    // ---- Q tile: cp.async, own commit group ----
#pragma unroll
    for (int i = 0; i < 8; i++) {
        const int row = i * 8 + lr8;
        const uint32_t off = (uint32_t)(row * 256 + ((lc ^ (row & 7)) * 16));
        const size_t gp = ((size_t)(b * S_LEN + q0 + row) * NH + h) * HD + lc * 8;
        cp16(sbase + AQH + off, Qh + gp);
        cp16(sbase + AQL + off, Ql + gp);
    }
    cp_commit();   // group: Q

    auto issue_kv = [&](int s, int k0) {
        const uint32_t st = sbase + KV0 + s * KVSTAGE;
#pragma unroll
        for (int i = 0; i < 4; i++) {
            const int row = i * 8 + lr8;
            const uint32_t off = (uint32_t)(row * 256 + ((lc ^ (row & 7)) * 16));
            const size_t gp = ((size_t)(b * S_LEN + k0 + row) * NKV + g) * HD + lc * 8;
            cp16(st + SKH + off, Kh + gp);
            cp16(st + SKL + off, Kl + gp);
            cp16(st + SVH + off, Vh + gp);
            cp16(st + SVL + off, Vl + gp);
        }
        cp_commit();
    };
    issue_kv(0, 0);   // group: KV0

    // ---- hoist Q fragments (tile-invariant) ----
    cp_wait<1>();     // Q group complete
    __syncthreads();
    uint32_t aqh_r[8][4], aql_r[8][4];
#pragma unroll
    for (int kt = 0; kt < 8; kt++) {
        ldm_x4_256(aqh_r[kt], sbase + AQH, wq * 16, kt * 2);
        ldm_x4_256(aql_r[kt], sbase + AQL, wq * 16, kt * 2);
    }

    float out[16][4];
#pragma unroll
    for (int i = 0; i < 16; i++)
#pragma unroll
        for (int j = 0; j < 4; j++) out[i][j] = 0.0f;
    float m0 = -1e30f, m1 = -1e30f, l0 = 0.0f, l1 = 0.0f;
    // scale folded with log2(e): softmax runs in exp2 domain
    const float scl2 = 0.08838834764831845f * 1.4426950408889634f;
    const int ntile = 2 * qb + 2;

    for (int kb = 0; kb < ntile; kb++) {
        const int s = kb & 1;
        const int k0 = kb * ABKV;
        if (kb + 1 < ntile) {
            issue_kv(1 - s, (kb + 1) * ABKV);
            cp_wait<1>();
        } else {
            cp_wait<0>();
        }
        __syncthreads();

        if (k0 <= rowmin + 15) {   // else tile fully masked for this warp
            const uint32_t stK = sbase + KV0 + s * KVSTAGE;

            // ---- S = Q K^T  (16 x 32 x 128) ----
            float sc[4][4];
#pragma unroll
            for (int nt = 0; nt < 4; nt++)
#pragma unroll
                for (int j = 0; j < 4; j++) sc[nt][j] = 0.0f;
#pragma unroll
            for (int kt = 0; kt < 8; kt++) {
#pragma unroll
                for (int bp = 0; bp < 2; bp++) {
                    uint32_t bkh[4], bkl[4];
                    ldm_x4_256(bkh, stK + SKH, bp * 16, kt * 2);
                    ldm_x4_256(bkl, stK + SKL, bp * 16, kt * 2);
#pragma unroll
                    for (int o = 0; o < 2; o++) {
                        const int nt = bp * 2 + o;
                        mma_bf16(sc[nt], aqh_r[kt], bkh[o], bkh[o + 2]);
                        mma_bf16(sc[nt], aqh_r[kt], bkl[o], bkl[o + 2]);
                        mma_bf16(sc[nt], aql_r[kt], bkh[o], bkh[o + 2]);
                    }
                }
            }

            // ---- scale + causal mask + online softmax (exp2 domain) ----
            const int r0g = rowmin + (lane >> 2);
            const bool domask = (k0 + ABKV - 1) > rowmin;
            float mx0 = -1e30f, mx1 = -1e30f;
#pragma unroll
            for (int nt = 0; nt < 4; nt++) {
#pragma unroll
                for (int j = 0; j < 4; j++) {
                    float v = sc[nt][j] * scl2;
                    if (domask) {
                        int cg = k0 + nt * 8 + (lane & 3) * 2 + (j & 1);
                        int rg = r0g + ((j >> 1) << 3);
                        if (cg > rg) v = -1e30f;
                    }
                    sc[nt][j] = v;
                }
                mx0 = fmaxf(mx0, fmaxf(sc[nt][0], sc[nt][1]));
                mx1 = fmaxf(mx1, fmaxf(sc[nt][2], sc[nt][3]));
            }
            mx0 = fmaxf(mx0, __shfl_xor_sync(0xffffffffu, mx0, 1));
            mx0 = fmaxf(mx0, __shfl_xor_sync(0xffffffffu, mx0, 2));
            mx1 = fmaxf(mx1, __shfl_xor_sync(0xffffffffu, mx1, 1));
            mx1 = fmaxf(mx1, __shfl_xor_sync(0xffffffffu, mx1, 2));
            const float mn0 = fmaxf(m0, mx0), mn1 = fmaxf(m1, mx1);
            const float a0 = exp2f(m0 - mn0), a1 = exp2f(m1 - mn1);
            m0 = mn0; m1 = mn1;
            float ps0 = 0.0f, ps1 = 0.0f;
#pragma unroll
            for (int nt = 0; nt < 4; nt++) {
                sc[nt][0] = exp2f(sc[nt][0] - mn0); ps0 += sc[nt][0];
                sc[nt][1] = exp2f(sc[nt][1] - mn0); ps0 += sc[nt][1];
                sc[nt][2] = exp2f(sc[nt][2] - mn1); ps1 += sc[nt][2];
                sc[nt][3] = exp2f(sc[nt][3] - mn1); ps1 += sc[nt][3];
            }
            l0 = l0 * a0 + ps0;
            l1 = l1 * a1 + ps1;
#pragma unroll
            for (int dt = 0; dt < 16; dt++) {
                out[dt][0] *= a0; out[dt][1] *= a0;
                out[dt][2] *= a1; out[dt][3] *= a1;
            }

            // ---- O += P V  (16 x 128 x 32) ----
#pragma unroll
            for (int ktp = 0; ktp < 2; ktp++) {
                uint32_t aph[4], apl[4];
                const int t0 = ktp * 2, t1 = t0 + 1;
                pack_hilo(sc[t0][0], sc[t0][1], aph[0], apl[0]);
                pack_hilo(sc[t0][2], sc[t0][3], aph[1], apl[1]);
                pack_hilo(sc[t1][0], sc[t1][1], aph[2], apl[2]);
                pack_hilo(sc[t1][2], sc[t1][3], aph[3], apl[3]);
#pragma unroll
                for (int dt = 0; dt < 8; dt++) {
                    uint32_t bvh[4], bvl[4];
                    ldm_x4t_256(bvh, stK + SVH, ktp * 16, dt * 2);
                    ldm_x4t_256(bvl, stK + SVL, ktp * 16, dt * 2);
                    mma_bf16(out[dt * 2],     aph, bvh[0], bvh[1]);
                    mma_bf16(out[dt * 2],     aph, bvl[0], bvl[1]);
                    mma_bf16(out[dt * 2],     apl, bvh[0], bvh[1]);
                    mma_bf16(out[dt * 2 + 1], aph, bvh[2], bvh[3]);
                    mma_bf16(out[dt * 2 + 1], aph, bvl[2], bvl[3]);
                    mma_bf16(out[dt * 2 + 1], apl, bvh[2], bvh[3]);
                }
            }
        }
        __syncthreads();   // all warps done with stage s before it is refilled
    }

    // ---- finalize: write bf16 hi/lo directly (feeds O-projection GEMM) ----
    l0 += __shfl_xor_sync(0xffffffffu, l0, 1);
    l0 += __shfl_xor_sync(0xffffffffu, l0, 2);
    l1 += __shfl_xor_sync(0xffffffffu, l1, 1);
    l1 += __shfl_xor_sync(0xffffffffu, l1, 2);
    const float i0 = 1.0f / l0, i1 = 1.0f / l1;
    const int r0g = rowmin + (lane >> 2);
    const size_t base0 = ((size_t)(b * S_LEN + r0g) * NH + h) * HD;
    const size_t base1 = base0 + (size_t)8 * NH * HD;
#pragma unroll
    for (int dt = 0; dt < 16; dt++) {
        const int col = dt * 8 + (lane & 3) * 2;
        uint32_t h0, l0p, h1, l1p;
        pack_hilo(out[dt][0] * i0, out[dt][1] * i0, h0, l0p);
        pack_hilo(out[dt][2] * i1, out[dt][3] * i1, h1, l1p);
        *(uint32_t*)(AOh + base0 + col) = h0;
        *(uint32_t*)(AOl + base0 + col) = l0p;
        *(uint32_t*)(AOh + base1 + col) = h1;
        *(uint32_t*)(AOl + base1 + col) = l1p;
    }
}

// ---------------------------------------------------------------------------
// Launch
// ---------------------------------------------------------------------------
extern "C" void kernel_launch(void* const* d_in, const int* in_sizes, int n_in,
                              void* d_out, int out_size)
{
    const float* hs = (const float*)d_in[0];
    const float* wq = (const float*)d_in[1];
    const float* wk = (const float*)d_in[2];
    const float* wv = (const float*)d_in[3];
    const float* wo = (const float*)d_in[4];
    const int*  pos = (const int*)  d_in[6];
    float*      out = (float*)d_out;

    float *q, *k;
    cudaGetSymbolAddress((void**)&q,  g_q);
    cudaGetSymbolAddress((void**)&k,  g_k);

    __nv_bfloat16 *hsh, *hsl, *wh, *wl, *woh, *wol, *aoh, *aol;
    __nv_bfloat16 *qh, *ql, *kh, *kl, *vh, *vl;
    cudaGetSymbolAddress((void**)&hsh, g_hs_h); cudaGetSymbolAddress((void**)&hsl, g_hs_l);
    cudaGetSymbolAddress((void**)&wh,  g_w_h);  cudaGetSymbolAddress((void**)&wl,  g_w_l);
    cudaGetSymbolAddress((void**)&woh, g_wo_h); cudaGetSymbolAddress((void**)&wol, g_wo_l);
    cudaGetSymbolAddress((void**)&aoh, g_ao_h); cudaGetSymbolAddress((void**)&aol, g_ao_l);
    cudaGetSymbolAddress((void**)&qh,  g_q_h);  cudaGetSymbolAddress((void**)&ql,  g_q_l);
    cudaGetSymbolAddress((void**)&kh,  g_k_h);  cudaGetSymbolAddress((void**)&kl,  g_k_l);
    cudaGetSymbolAddress((void**)&vh,  g_v_h);  cudaGetSymbolAddress((void**)&vl,  g_v_l);

    cudaFuncSetAttribute(gemm_mma_kernel, cudaFuncAttributeMaxDynamicSharedMemorySize, GEMM_SMEM);
    cudaFuncSetAttribute(attn_mma_kernel, cudaFuncAttributeMaxDynamicSharedMemorySize, ATTN_SMEM);

    auto cvt = [&](const float* x, __nv_bfloat16* hi, __nv_bfloat16* lo, int n) {
        int n4 = n / 4;
        cvt_kernel<<<(n4 + 255) / 256, 256>>>((const float4*)x, (uint2*)hi, (uint2*)lo, n4);
    };

    // pre-convert inputs; wq|wk|wv go into one combined [6144,4096] buffer
    cvt(hs, hsh, hsl, MROWS * HID);
    cvt(wq, wh,             wl,             NH  * HD * HID);
    cvt(wk, wh + 16777216u, wl + 16777216u, NKV * HD * HID);
    cvt(wv, wh + 20971520u, wl + 20971520u, NKV * HD * HID);
    cvt(wo, woh, wol, HID * NH * HD);

    // Merged QKV projection: N = 6144; q,k -> fp32, v -> bf16 hi/lo directly
    gemm_mma_kernel<<<dim3(6144 / TBN, MROWS / TBM), 256, GEMM_SMEM>>>(
        hsh, hsl, wh, wl, q, k, vh, vl,
        4096, 5120, NH * HD, NKV * HD, NKV * HD,
        MROWS, 6144, HID);

    // RoPE + hi/lo conversion for q, k
    rope_cvt_kernel<<<MROWS, 256>>>(q, k, pos, qh, ql, kh, kl);

    // Causal flash attention (mma.sync, 2 CTAs/SM); writes ao hi/lo directly
    attn_mma_kernel<<<dim3(S_LEN / ABQ, NH, B_SZ), 128, ATTN_SMEM>>>(
        qh, ql, kh, kl, vh, vl, aoh, aol);

    // Output projection
    gemm_mma_kernel<<<dim3(HID / TBN, MROWS / TBM), 256, GEMM_SMEM>>>(
        aoh, aol, woh, wol, out, out, nullptr, nullptr,
        HID, HID, HID, HID, HID,
        MROWS, HID, NH * HD);
}

// round 9
// speedup vs baseline: 2.8669x; 1.0495x over previous
#include <cuda_runtime.h>
#include <cuda_bf16.h>
#include <cstdint>

// Problem constants (fixed shapes)
#define NH    32
#define NKV   8
#define HD    128
#define S_LEN 2048
#define B_SZ  2
#define HID   4096
#define MROWS (B_SZ * S_LEN)   // 4096
#define NREP  (NH / NKV)       // 4

#define E16M (16u * 1024u * 1024u)
#define E4M  (4u  * 1024u * 1024u)
#define WQKV_E (6144u * 4096u)   // combined q|k|v weight rows

// ---------------------------------------------------------------------------
// Scratch (device globals; allocation-free per harness rules)
// ---------------------------------------------------------------------------
__device__ float g_q [(size_t)MROWS * NH  * HD];
__device__ float g_k [(size_t)MROWS * NKV * HD];

// bf16 hi/lo copies
__device__ __nv_bfloat16 g_hs_h[E16M],  g_hs_l[E16M];
__device__ __nv_bfloat16 g_w_h[WQKV_E], g_w_l[WQKV_E];   // wq|wk|wv combined
__device__ __nv_bfloat16 g_wo_h[E16M],  g_wo_l[E16M];
__device__ __nv_bfloat16 g_ao_h[E16M],  g_ao_l[E16M];
// post-rope bf16 hi/lo q/k, direct-split v for attention
__device__ __nv_bfloat16 g_q_h[E16M], g_q_l[E16M];
__device__ __nv_bfloat16 g_k_h[E4M],  g_k_l[E4M];
__device__ __nv_bfloat16 g_v_h[E4M],  g_v_l[E4M];

// ---------------------------------------------------------------------------
// Common helpers (sm_80-level PTX only; no 'a'-suffix features)
// ---------------------------------------------------------------------------
__device__ __forceinline__ uint32_t smem_u32(const void* p) {
    uint32_t a;
    asm("{ .reg .u64 t; cvta.to.shared.u64 t, %1; cvt.u32.u64 %0, t; }"
        : "=r"(a) : "l"(p));
    return a;
}
__device__ __forceinline__ uint32_t pack_bf16x2(float a, float b) {
    __nv_bfloat162 h = __floats2bfloat162_rn(a, b);
    return *reinterpret_cast<uint32_t*>(&h);
}
__device__ __forceinline__ void cp16(uint32_t saddr, const void* gptr) {
    asm volatile("cp.async.cg.shared.global [%0], [%1], 16;"
                 :: "r"(saddr), "l"(gptr));
}
__device__ __forceinline__ void cp_commit() {
    asm volatile("cp.async.commit_group;" ::: "memory");
}
template <int N>
__device__ __forceinline__ void cp_wait() {
    asm volatile("cp.async.wait_group %0;" :: "n"(N) : "memory");
}
// ldmatrix.x4 over macro-row layout: logical rows of 32 bf16 (64B) are packed
// in pairs into 128B macro-rows with the standard XOR-8 swizzle.
// off(r, kc) = (r>>1)*128 + ((((r&1)<<2)|kc) ^ ((r>>1)&7))*16,  kc = 16B chunk 0..3
__device__ __forceinline__ void ldm_x4_k32(uint32_t* r, uint32_t base, int row0, int kt) {
    const int l  = (int)(threadIdx.x & 31);
    const int rr = row0 + (l & 15);
    const int kc = 2 * kt + (l >> 4);
    const int mr = rr >> 1;
    const int ch = (((rr & 1) << 2) | kc) ^ (mr & 7);
    const uint32_t addr = base + (uint32_t)(mr * 128 + ch * 16);
    asm volatile("ldmatrix.sync.aligned.m8n8.x4.shared.b16 {%0,%1,%2,%3}, [%4];"
                 : "=r"(r[0]), "=r"(r[1]), "=r"(r[2]), "=r"(r[3]) : "r"(addr));
}
// ldmatrix.x4, 256B-wide rows (attention tiles, HD=128 bf16 per row)
__device__ __forceinline__ void ldm_x4_256(uint32_t* r, uint32_t base, int row0, int c0) {
    const int l  = (int)(threadIdx.x & 31);
    const int rr = row0 + (l & 15);
    const int cc = (c0 + (l >> 4)) ^ (rr & 7);
    const uint32_t addr = base + (uint32_t)(rr * 256 + cc * 16);
    asm volatile("ldmatrix.sync.aligned.m8n8.x4.shared.b16 {%0,%1,%2,%3}, [%4];"
                 : "=r"(r[0]), "=r"(r[1]), "=r"(r[2]), "=r"(r[3]) : "r"(addr));
}
__device__ __forceinline__ void ldm_x4t_256(uint32_t* r, uint32_t base, int row0, int c0) {
    const int l  = (int)(threadIdx.x & 31);
    const int rr = row0 + (l & 15);
    const int cc = (c0 + (l >> 4)) ^ (rr & 7);
    const uint32_t addr = base + (uint32_t)(rr * 256 + cc * 16);
    asm volatile("ldmatrix.sync.aligned.m8n8.x4.trans.shared.b16 {%0,%1,%2,%3}, [%4];"
                 : "=r"(r[0]), "=r"(r[1]), "=r"(r[2]), "=r"(r[3]) : "r"(addr));
}
__device__ __forceinline__ void mma_bf16(float* d, const uint32_t* a,
                                         uint32_t b0, uint32_t b1) {
    asm volatile(
        "mma.sync.aligned.m16n8k16.row.col.f32.bf16.bf16.f32 "
        "{%0,%1,%2,%3}, {%4,%5,%6,%7}, {%8,%9}, {%0,%1,%2,%3};"
        : "+f"(d[0]), "+f"(d[1]), "+f"(d[2]), "+f"(d[3])
        : "r"(a[0]), "r"(a[1]), "r"(a[2]), "r"(a[3]), "r"(b0), "r"(b1));
}
__device__ __forceinline__ void pack_hilo(float p0, float p1, uint32_t& hi, uint32_t& lo) {
    float h0 = __bfloat162float(__float2bfloat16(p0));
    float h1 = __bfloat162float(__float2bfloat16(p1));
    hi = pack_bf16x2(h0, h1);
    lo = pack_bf16x2(p0 - h0, p1 - h1);
}
__device__ __forceinline__ void store_hilo(__nv_bfloat16* H, __nv_bfloat16* L,
                                           size_t idx, float val) {
    __nv_bfloat16 hb = __float2bfloat16(val);
    H[idx] = hb;
    L[idx] = __float2bfloat16(val - __bfloat162float(hb));
}

// ---------------------------------------------------------------------------
// fp32 -> bf16 hi/lo conversion (elementwise)
// ---------------------------------------------------------------------------
__global__ __launch_bounds__(256) void cvt_kernel(
    const float4* __restrict__ x, uint2* __restrict__ hi,
    uint2* __restrict__ lo, int n4)
{
    int i = blockIdx.x * blockDim.x + threadIdx.x;
    if (i >= n4) return;
    float4 f = x[i];
    float xs[4] = {f.x, f.y, f.z, f.w};
    float hf[4], lf[4];
#pragma unroll
    for (int t = 0; t < 4; t++) {
        __nv_bfloat16 h = __float2bfloat16(xs[t]);
        hf[t] = __bfloat162float(h);
        lf[t] = xs[t] - hf[t];
    }
    uint2 H, L;
    H.x = pack_bf16x2(hf[0], hf[1]); H.y = pack_bf16x2(hf[2], hf[3]);
    L.x = pack_bf16x2(lf[0], lf[1]); L.y = pack_bf16x2(lf[2], lf[3]);
    hi[i] = H;
    lo[i] = L;
}

// ---------------------------------------------------------------------------
// GEMM: C[M,N] = A[M,K] * B[N,K]^T  (bf16 hi/lo x3 MMAs, fp32 out)
// Tile 128x128x32, 3-stage cp.async, 96KB smem -> 2 CTAs/SM.
// 256 threads = 8 warps (2 M x 4 N), warp tile 64x32. One sync per stage.
// Epilogue routes columns to up to 3 destinations; dest 2 emits bf16 hi/lo.
// ---------------------------------------------------------------------------
#define TBM 128
#define TBN 128
#define TBK 32
#define OFF_AH 0
#define OFF_AL 8192
#define OFF_BH 16384
#define OFF_BL 24576
#define STAGE_BYTES 32768
#define GEMM_SMEM (3 * STAGE_BYTES)   // 96 KB

// macro-row smem offset for (row, 16B-chunk kc) in a 128x32-bf16 tile
__device__ __forceinline__ uint32_t mrow_off(int r, int kc) {
    const int mr = r >> 1;
    const int ch = (((r & 1) << 2) | kc) ^ (mr & 7);
    return (uint32_t)(mr * 128 + ch * 16);
}

__global__ __launch_bounds__(256, 2) void gemm_mma_kernel(
    const __nv_bfloat16* __restrict__ Ah, const __nv_bfloat16* __restrict__ Al,
    const __nv_bfloat16* __restrict__ Bh, const __nv_bfloat16* __restrict__ Bl,
    float* __restrict__ C0, float* __restrict__ C1,
    __nv_bfloat16* __restrict__ C2h, __nv_bfloat16* __restrict__ C2l,
    int ns1, int ns2, int ldc0, int ldc1, int ldc2,
    int M, int N, int K)
{
    extern __shared__ __align__(1024) char smem[];
    const uint32_t sbase = smem_u32(smem);
    const int tid  = threadIdx.x;
    const int lane = tid & 31;
    const int wid  = tid >> 5;
    const int wm   = wid & 1;        // warp rows [wm*64,+64)
    const int wn   = wid >> 1;       // warp cols [wn*32,+32)
    const int m0   = blockIdx.y * TBM;
    const int n0   = blockIdx.x * TBN;
    // copy coords: idx -> (row = idx>>2, 16B chunk = idx&3); thread does idx, idx+256
    const int r0c = tid >> 2, c0c = tid & 3;

    float acc[4][4][4];
#pragma unroll
    for (int i = 0; i < 4; i++)
#pragma unroll
        for (int j = 0; j < 4; j++)
#pragma unroll
            for (int t = 0; t < 4; t++) acc[i][j][t] = 0.0f;

    const int nch = K / TBK;   // 128 for K=4096

    auto issue = [&](int s, int k0) {
        const uint32_t st = sbase + s * STAGE_BYTES;
#pragma unroll
        for (int half = 0; half < 2; half++) {
            const int r = r0c + half * 64;
            const uint32_t off = mrow_off(r, c0c);
            const size_t ga = (size_t)(m0 + r) * K + k0 + c0c * 8;
            const size_t gb = (size_t)(n0 + r) * K + k0 + c0c * 8;
            cp16(st + OFF_AH + off, Ah + ga);
            cp16(st + OFF_AL + off, Al + ga);
            cp16(st + OFF_BH + off, Bh + gb);
            cp16(st + OFF_BL + off, Bl + gb);
        }
        cp_commit();
    };

    issue(0, 0);
    issue(1, TBK);

    for (int ch = 0; ch < nch; ch++) {
        if (ch < nch - 1) cp_wait<1>();
        else              cp_wait<0>();
        __syncthreads();

        const int s = ch % 3;
        const uint32_t stAh = sbase + s * STAGE_BYTES + OFF_AH;
        const uint32_t stAl = sbase + s * STAGE_BYTES + OFF_AL;
        const uint32_t stBh = sbase + s * STAGE_BYTES + OFF_BH;
        const uint32_t stBl = sbase + s * STAGE_BYTES + OFF_BL;
#pragma unroll
        for (int kt = 0; kt < 2; kt++) {
            uint32_t ah[4][4], al[4][4], bh[2][4], bl[2][4];
#pragma unroll
            for (int mt = 0; mt < 4; mt++) {
                ldm_x4_k32(ah[mt], stAh, wm * 64 + mt * 16, kt);
                ldm_x4_k32(al[mt], stAl, wm * 64 + mt * 16, kt);
            }
#pragma unroll
            for (int bp = 0; bp < 2; bp++) {
                ldm_x4_k32(bh[bp], stBh, wn * 32 + bp * 16, kt);
                ldm_x4_k32(bl[bp], stBl, wn * 32 + bp * 16, kt);
            }
#pragma unroll
            for (int mt = 0; mt < 4; mt++)
#pragma unroll
                for (int nt = 0; nt < 4; nt++) {
                    const int bp = nt >> 1, o = nt & 1;
                    mma_bf16(acc[mt][nt], ah[mt], bh[bp][o], bh[bp][o + 2]);
                    mma_bf16(acc[mt][nt], ah[mt], bl[bp][o], bl[bp][o + 2]);
                    mma_bf16(acc[mt][nt], al[mt], bh[bp][o], bh[bp][o + 2]);
                }
        }

        if (ch + 2 < nch) issue((ch + 2) % 3, (ch + 2) * TBK);
    }

    // epilogue with column routing (CTA tile never straddles a split)
    if (n0 >= ns2 && C2h != nullptr) {
        const int nc0 = n0 - ns2;
#pragma unroll
        for (int mt = 0; mt < 4; mt++) {
            const int row = m0 + wm * 64 + mt * 16 + (lane >> 2);
#pragma unroll
            for (int nt = 0; nt < 4; nt++) {
                const int col = nc0 + wn * 32 + nt * 8 + (lane & 3) * 2;
                uint32_t h0, l0v, h1, l1v;
                pack_hilo(acc[mt][nt][0], acc[mt][nt][1], h0, l0v);
                pack_hilo(acc[mt][nt][2], acc[mt][nt][3], h1, l1v);
                *(uint32_t*)(C2h + (size_t)row * ldc2 + col)       = h0;
                *(uint32_t*)(C2l + (size_t)row * ldc2 + col)       = l0v;
                *(uint32_t*)(C2h + (size_t)(row + 8) * ldc2 + col) = h1;
                *(uint32_t*)(C2l + (size_t)(row + 8) * ldc2 + col) = l1v;
            }
        }
        return;
    }
    float* Cb; int ldc, nc0;
    if (n0 < ns1) { Cb = C0; ldc = ldc0; nc0 = n0; }
    else          { Cb = C1; ldc = ldc1; nc0 = n0 - ns1; }
#pragma unroll
    for (int mt = 0; mt < 4; mt++) {
        const int row = m0 + wm * 64 + mt * 16 + (lane >> 2);
#pragma unroll
        for (int nt = 0; nt < 4; nt++) {
            const int col = nc0 + wn * 32 + nt * 8 + (lane & 3) * 2;
            float2 v0 = make_float2(acc[mt][nt][0], acc[mt][nt][1]);
            float2 v1 = make_float2(acc[mt][nt][2], acc[mt][nt][3]);
            *(float2*)(Cb + (size_t)row * ldc + col)       = v0;
            *(float2*)(Cb + (size_t)(row + 8) * ldc + col) = v1;
        }
    }
}

// ---------------------------------------------------------------------------
// RoPE + fp32 -> bf16 hi/lo for q, k (v handled by GEMM epilogue)
// ---------------------------------------------------------------------------
__global__ __launch_bounds__(256) void rope_cvt_kernel(
    const float* __restrict__ q, const float* __restrict__ k,
    const int* __restrict__ pos,
    __nv_bfloat16* __restrict__ qh, __nv_bfloat16* __restrict__ ql,
    __nv_bfloat16* __restrict__ kh, __nv_bfloat16* __restrict__ kl)
{
    const int bs = blockIdx.x;
    const float p = (float)pos[bs];
    const float c1 = -0.2076205059304601f;        // -log2(10000)/64
    for (int i = threadIdx.x; i < 2560; i += 256) {
        const float* base; size_t idx; int d;
        __nv_bfloat16 *H, *L;
        if (i < 2048) {
            int hh = i >> 6; d = i & 63;
            idx = ((size_t)bs * NH + hh) * HD;
            base = q + idx; H = qh; L = ql;
        } else {
            int j = i - 2048;
            int hh = j >> 6; d = j & 63;
            idx = ((size_t)bs * NKV + hh) * HD;
            base = k + idx; H = kh; L = kl;
        }
        float inv = exp2f(c1 * (float)d);
        float ang = p * inv;
        float sv, cv;
        sincosf(ang, &sv, &cv);
        float x1 = base[d], x2 = base[d + 64];
        store_hilo(H, L, idx + d,      x1 * cv - x2 * sv);
        store_hilo(H, L, idx + d + 64, x2 * cv + x1 * sv);
    }
}

// ---------------------------------------------------------------------------
// Flash attention via mma.sync (bf16 hi/lo x3), fp32 softmax (exp2), causal.
// CTA: 64 q-rows x 1 head, 4 warps, 96KB smem -> 2 CTAs/SM.
// Q fragments hoisted out of the KV loop; output written as bf16 hi/lo.
// ---------------------------------------------------------------------------
#define ABQ  64
#define ABKV 32
#define AQH 0
#define AQL 16384
#define KV0 32768          // per-stage: KH 0, KL 8K, VH 16K, VL 24K
#define SKH 0
#define SKL 8192
#define SVH 16384
#define SVL 24576
#define KVSTAGE 32768
#define ATTN_SMEM (32768 + 2 * KVSTAGE)   // 96 KB

__global__ __launch_bounds__(128, 2) void attn_mma_kernel(
    const __nv_bfloat16* __restrict__ Qh, const __nv_bfloat16* __restrict__ Ql,
    const __nv_bfloat16* __restrict__ Kh, const __nv_bfloat16* __restrict__ Kl,
    const __nv_bfloat16* __restrict__ Vh, const __nv_bfloat16* __restrict__ Vl,
    __nv_bfloat16* __restrict__ AOh, __nv_bfloat16* __restrict__ AOl)
{
    extern __shared__ __align__(1024) char smem[];
    const uint32_t sbase = smem_u32(smem);
    const int tid  = threadIdx.x;
    const int lane = tid & 31;
    const int wq   = tid >> 5;                              // 0..3
    const int qb   = (int)gridDim.x - 1 - (int)blockIdx.x;  // big tiles first
    const int h    = blockIdx.y, b = blockIdx.z;
    const int g    = h / NREP;
    const int q0   = qb * ABQ;
    const int rowmin = q0 + wq * 16;
    const int lr8 = tid >> 4;      // 0..7 row within 8-row pass
    const int lc  = tid & 15;      // 16B chunk within 256B row

    // ---- Q tile: cp.async, own commit group ----
#pragma unroll
    for (int i = 0; i < 8; i++) {
        const int row = i * 8 + lr8;
        const uint32_t off = (uint32_t)(row * 256 + ((lc ^ (row & 7)) * 16));
        const size_t gp = ((size_t)(b * S_LEN + q0 + row) * NH + h) * HD + lc * 8;
        cp16(sbase + AQH + off, Qh + gp);
        cp16(sbase + AQL + off, Ql + gp);
    }
    cp_commit();   // group: Q

    auto issue_kv = [&](int s, int k0) {
        const uint32_t st = sbase + KV0 + s * KVSTAGE;
#pragma unroll
        for (int i = 0; i < 4; i++) {
            const int row = i * 8 + lr8;
            const uint32_t off = (uint32_t)(row * 256 + ((lc ^ (row & 7)) * 16));
            const size_t gp = ((size_t)(b * S_LEN + k0 + row) * NKV + g) * HD + lc * 8;
            cp16(st + SKH + off, Kh + gp);
            cp16(st + SKL + off, Kl + gp);
            cp16(st + SVH + off, Vh + gp);
            cp16(st + SVL + off, Vl + gp);
        }
        cp_commit();
    };
    issue_kv(0, 0);   // group: KV0

    // ---- hoist Q fragments (tile-invariant) ----
    cp_wait<1>();     // Q group complete
    __syncthreads();
    uint32_t aqh_r[8][4], aql_r[8][4];
#pragma unroll
    for (int kt = 0; kt < 8; kt++) {
        ldm_x4_256(aqh_r[kt], sbase + AQH, wq * 16, kt * 2);
        ldm_x4_256(aql_r[kt], sbase + AQL, wq * 16, kt * 2);
    }

    float out[16][4];
#pragma unroll
    for (int i = 0; i < 16; i++)
#pragma unroll
        for (int j = 0; j < 4; j++) out[i][j] = 0.0f;
    float m0 = -1e30f, m1 = -1e30f, l0 = 0.0f, l1 = 0.0f;
    // scale folded with log2(e): softmax runs in exp2 domain
    const float scl2 = 0.08838834764831845f * 1.4426950408889634f;
    const int ntile = 2 * qb + 2;

    for (int kb = 0; kb < ntile; kb++) {
        const int s = kb & 1;
        const int k0 = kb * ABKV;
        if (kb + 1 < ntile) {
            issue_kv(1 - s, (kb + 1) * ABKV);
            cp_wait<1>();
        } else {
            cp_wait<0>();
        }
        __syncthreads();

        if (k0 <= rowmin + 15) {   // else tile fully masked for this warp
            const uint32_t stK = sbase + KV0 + s * KVSTAGE;

            // ---- S = Q K^T  (16 x 32 x 128) ----
            float sc[4][4];
#pragma unroll
            for (int nt = 0; nt < 4; nt++)
#pragma unroll
                for (int j = 0; j < 4; j++) sc[nt][j] = 0.0f;
#pragma unroll
            for (int kt = 0; kt < 8; kt++) {
#pragma unroll
                for (int bp = 0; bp < 2; bp++) {
                    uint32_t bkh[4], bkl[4];
                    ldm_x4_256(bkh, stK + SKH, bp * 16, kt * 2);
                    ldm_x4_256(bkl, stK + SKL, bp * 16, kt * 2);
#pragma unroll
                    for (int o = 0; o < 2; o++) {
                        const int nt = bp * 2 + o;
                        mma_bf16(sc[nt], aqh_r[kt], bkh[o], bkh[o + 2]);
                        mma_bf16(sc[nt], aqh_r[kt], bkl[o], bkl[o + 2]);
                        mma_bf16(sc[nt], aql_r[kt], bkh[o], bkh[o + 2]);
                    }
                }
            }

            // ---- scale + causal mask + online softmax (exp2 domain) ----
            const int r0g = rowmin + (lane >> 2);
            const bool domask = (k0 + ABKV - 1) > rowmin;
            float mx0 = -1e30f, mx1 = -1e30f;
#pragma unroll
            for (int nt = 0; nt < 4; nt++) {
#pragma unroll
                for (int j = 0; j < 4; j++) {
                    float v = sc[nt][j] * scl2;
                    if (domask) {
                        int cg = k0 + nt * 8 + (lane & 3) * 2 + (j & 1);
                        int rg = r0g + ((j >> 1) << 3);
                        if (cg > rg) v = -1e30f;
                    }
                    sc[nt][j] = v;
                }
                mx0 = fmaxf(mx0, fmaxf(sc[nt][0], sc[nt][1]));
                mx1 = fmaxf(mx1, fmaxf(sc[nt][2], sc[nt][3]));
            }
            mx0 = fmaxf(mx0, __shfl_xor_sync(0xffffffffu, mx0, 1));
            mx0 = fmaxf(mx0, __shfl_xor_sync(0xffffffffu, mx0, 2));
            mx1 = fmaxf(mx1, __shfl_xor_sync(0xffffffffu, mx1, 1));
            mx1 = fmaxf(mx1, __shfl_xor_sync(0xffffffffu, mx1, 2));
            const float mn0 = fmaxf(m0, mx0), mn1 = fmaxf(m1, mx1);
            const float a0 = exp2f(m0 - mn0), a1 = exp2f(m1 - mn1);
            m0 = mn0; m1 = mn1;
            float ps0 = 0.0f, ps1 = 0.0f;
#pragma unroll
            for (int nt = 0; nt < 4; nt++) {
                sc[nt][0] = exp2f(sc[nt][0] - mn0); ps0 += sc[nt][0];
                sc[nt][1] = exp2f(sc[nt][1] - mn0); ps0 += sc[nt][1];
                sc[nt][2] = exp2f(sc[nt][2] - mn1); ps1 += sc[nt][2];
                sc[nt][3] = exp2f(sc[nt][3] - mn1); ps1 += sc[nt][3];
            }
            l0 = l0 * a0 + ps0;
            l1 = l1 * a1 + ps1;
#pragma unroll
            for (int dt = 0; dt < 16; dt++) {
                out[dt][0] *= a0; out[dt][1] *= a0;
                out[dt][2] *= a1; out[dt][3] *= a1;
            }

            // ---- O += P V  (16 x 128 x 32) ----
#pragma unroll
            for (int ktp = 0; ktp < 2; ktp++) {
                uint32_t aph[4], apl[4];
                const int t0 = ktp * 2, t1 = t0 + 1;
                pack_hilo(sc[t0][0], sc[t0][1], aph[0], apl[0]);
                pack_hilo(sc[t0][2], sc[t0][3], aph[1], apl[1]);
                pack_hilo(sc[t1][0], sc[t1][1], aph[2], apl[2]);
                pack_hilo(sc[t1][2], sc[t1][3], aph[3], apl[3]);
#pragma unroll
                for (int dt = 0; dt < 8; dt++) {
                    uint32_t bvh[4], bvl[4];
                    ldm_x4t_256(bvh, stK + SVH, ktp * 16, dt * 2);
                    ldm_x4t_256(bvl, stK + SVL, ktp * 16, dt * 2);
                    mma_bf16(out[dt * 2],     aph, bvh[0], bvh[1]);
                    mma_bf16(out[dt * 2],     aph, bvl[0], bvl[1]);
                    mma_bf16(out[dt * 2],     apl, bvh[0], bvh[1]);
                    mma_bf16(out[dt * 2 + 1], aph, bvh[2], bvh[3]);
                    mma_bf16(out[dt * 2 + 1], aph, bvl[2], bvl[3]);
                    mma_bf16(out[dt * 2 + 1], apl, bvh[2], bvh[3]);
                }
            }
        }
        __syncthreads();   // all warps done with stage s before it is refilled
    }

    // ---- finalize: write bf16 hi/lo directly (feeds O-projection GEMM) ----
    l0 += __shfl_xor_sync(0xffffffffu, l0, 1);
    l0 += __shfl_xor_sync(0xffffffffu, l0, 2);
    l1 += __shfl_xor_sync(0xffffffffu, l1, 1);
    l1 += __shfl_xor_sync(0xffffffffu, l1, 2);
    const float i0 = 1.0f / l0, i1 = 1.0f / l1;
    const int r0g = rowmin + (lane >> 2);
    const size_t base0 = ((size_t)(b * S_LEN + r0g) * NH + h) * HD;
    const size_t base1 = base0 + (size_t)8 * NH * HD;
#pragma unroll
    for (int dt = 0; dt < 16; dt++) {
        const int col = dt * 8 + (lane & 3) * 2;
        uint32_t h0, l0p, h1, l1p;
        pack_hilo(out[dt][0] * i0, out[dt][1] * i0, h0, l0p);
        pack_hilo(out[dt][2] * i1, out[dt][3] * i1, h1, l1p);
        *(uint32_t*)(AOh + base0 + col) = h0;
        *(uint32_t*)(AOl + base0 + col) = l0p;
        *(uint32_t*)(AOh + base1 + col) = h1;
        *(uint32_t*)(AOl + base1 + col) = l1p;
    }
}

// ---------------------------------------------------------------------------
// Launch
// ---------------------------------------------------------------------------
extern "C" void kernel_launch(void* const* d_in, const int* in_sizes, int n_in,
                              void* d_out, int out_size)
{
    const float* hs = (const float*)d_in[0];
    const float* wq = (const float*)d_in[1];
    const float* wk = (const float*)d_in[2];
    const float* wv = (const float*)d_in[3];
    const float* wo = (const float*)d_in[4];
    const int*  pos = (const int*)  d_in[6];
    float*      out = (float*)d_out;

    float *q, *k;
    cudaGetSymbolAddress((void**)&q,  g_q);
    cudaGetSymbolAddress((void**)&k,  g_k);

    __nv_bfloat16 *hsh, *hsl, *wh, *wl, *woh, *wol, *aoh, *aol;
    __nv_bfloat16 *qh, *ql, *kh, *kl, *vh, *vl;
    cudaGetSymbolAddress((void**)&hsh, g_hs_h); cudaGetSymbolAddress((void**)&hsl, g_hs_l);
    cudaGetSymbolAddress((void**)&wh,  g_w_h);  cudaGetSymbolAddress((void**)&wl,  g_w_l);
    cudaGetSymbolAddress((void**)&woh, g_wo_h); cudaGetSymbolAddress((void**)&wol, g_wo_l);
    cudaGetSymbolAddress((void**)&aoh, g_ao_h); cudaGetSymbolAddress((void**)&aol, g_ao_l);
    cudaGetSymbolAddress((void**)&qh,  g_q_h);  cudaGetSymbolAddress((void**)&ql,  g_q_l);
    cudaGetSymbolAddress((void**)&kh,  g_k_h);  cudaGetSymbolAddress((void**)&kl,  g_k_l);
    cudaGetSymbolAddress((void**)&vh,  g_v_h);  cudaGetSymbolAddress((void**)&vl,  g_v_l);

    cudaFuncSetAttribute(gemm_mma_kernel, cudaFuncAttributeMaxDynamicSharedMemorySize, GEMM_SMEM);
    cudaFuncSetAttribute(attn_mma_kernel, cudaFuncAttributeMaxDynamicSharedMemorySize, ATTN_SMEM);

    auto cvt = [&](const float* x, __nv_bfloat16* hi, __nv_bfloat16* lo, int n) {
        int n4 = n / 4;
        cvt_kernel<<<(n4 + 255) / 256, 256>>>((const float4*)x, (uint2*)hi, (uint2*)lo, n4);
    };

    // pre-convert inputs; wq|wk|wv go into one combined [6144,4096] buffer
    cvt(hs, hsh, hsl, MROWS * HID);
    cvt(wq, wh,             wl,             NH  * HD * HID);
    cvt(wk, wh + 16777216u, wl + 16777216u, NKV * HD * HID);
    cvt(wv, wh + 20971520u, wl + 20971520u, NKV * HD * HID);
    cvt(wo, woh, wol, HID * NH * HD);

    // Merged QKV projection: N = 6144; q,k -> fp32, v -> bf16 hi/lo directly
    gemm_mma_kernel<<<dim3(6144 / TBN, MROWS / TBM), 256, GEMM_SMEM>>>(
        hsh, hsl, wh, wl, q, k, vh, vl,
        4096, 5120, NH * HD, NKV * HD, NKV * HD,
        MROWS, 6144, HID);

    // RoPE + hi/lo conversion for q, k
    rope_cvt_kernel<<<MROWS, 256>>>(q, k, pos, qh, ql, kh, kl);

    // Causal flash attention (mma.sync, 2 CTAs/SM); writes ao hi/lo directly
    attn_mma_kernel<<<dim3(S_LEN / ABQ, NH, B_SZ), 128, ATTN_SMEM>>>(
        qh, ql, kh, kl, vh, vl, aoh, aol);

    // Output projection
    gemm_mma_kernel<<<dim3(HID / TBN, MROWS / TBM), 256, GEMM_SMEM>>>(
        aoh, aol, woh, wol, out, out, nullptr, nullptr,
        HID, HID, HID, HID, HID,
        MROWS, HID, NH * HD);
}

// round 10
// speedup vs baseline: 2.8738x; 1.0024x over previous
#include <cuda_runtime.h>
#include <cuda_bf16.h>
#include <cstdint>

// Problem constants (fixed shapes)
#define NH    32
#define NKV   8
#define HD    128
#define S_LEN 2048
#define B_SZ  2
#define HID   4096
#define MROWS (B_SZ * S_LEN)   // 4096
#define NREP  (NH / NKV)       // 4

#define E16M (16u * 1024u * 1024u)
#define E4M  (4u  * 1024u * 1024u)
#define WQKV_E (6144u * 4096u)   // combined q|k|v weight rows

// ---------------------------------------------------------------------------
// Scratch (device globals; allocation-free per harness rules)
// ---------------------------------------------------------------------------
__device__ float g_q [(size_t)MROWS * NH  * HD];
__device__ float g_k [(size_t)MROWS * NKV * HD];

// bf16 hi/lo copies
__device__ __nv_bfloat16 g_hs_h[E16M],  g_hs_l[E16M];
__device__ __nv_bfloat16 g_w_h[WQKV_E], g_w_l[WQKV_E];   // wq|wk|wv combined
__device__ __nv_bfloat16 g_wo_h[E16M],  g_wo_l[E16M];
__device__ __nv_bfloat16 g_ao_h[E16M],  g_ao_l[E16M];
// post-rope bf16 hi/lo q/k, direct-split v for attention
__device__ __nv_bfloat16 g_q_h[E16M], g_q_l[E16M];
__device__ __nv_bfloat16 g_k_h[E4M],  g_k_l[E4M];
__device__ __nv_bfloat16 g_v_h[E4M],  g_v_l[E4M];

// ---------------------------------------------------------------------------
// Common helpers (sm_80-level PTX only; no 'a'-suffix features)
// ---------------------------------------------------------------------------
__device__ __forceinline__ uint32_t smem_u32(const void* p) {
    uint32_t a;
    asm("{ .reg .u64 t; cvta.to.shared.u64 t, %1; cvt.u32.u64 %0, t; }"
        : "=r"(a) : "l"(p));
    return a;
}
__device__ __forceinline__ uint32_t pack_bf16x2(float a, float b) {
    __nv_bfloat162 h = __floats2bfloat162_rn(a, b);
    return *reinterpret_cast<uint32_t*>(&h);
}
__device__ __forceinline__ void cp16(uint32_t saddr, const void* gptr) {
    asm volatile("cp.async.cg.shared.global [%0], [%1], 16;"
                 :: "r"(saddr), "l"(gptr));
}
__device__ __forceinline__ void cp_commit() {
    asm volatile("cp.async.commit_group;" ::: "memory");
}
template <int N>
__device__ __forceinline__ void cp_wait() {
    asm volatile("cp.async.wait_group %0;" :: "n"(N) : "memory");
}
// ldmatrix.x4 over macro-row layout: logical rows of 32 bf16 (64B) are packed
// in pairs into 128B macro-rows with the standard XOR-8 swizzle.
__device__ __forceinline__ void ldm_x4_k32(uint32_t* r, uint32_t base, int row0, int kt) {
    const int l  = (int)(threadIdx.x & 31);
    const int rr = row0 + (l & 15);
    const int kc = 2 * kt + (l >> 4);
    const int mr = rr >> 1;
    const int ch = (((rr & 1) << 2) | kc) ^ (mr & 7);
    const uint32_t addr = base + (uint32_t)(mr * 128 + ch * 16);
    asm volatile("ldmatrix.sync.aligned.m8n8.x4.shared.b16 {%0,%1,%2,%3}, [%4];"
                 : "=r"(r[0]), "=r"(r[1]), "=r"(r[2]), "=r"(r[3]) : "r"(addr));
}
// ldmatrix.x4, 256B-wide rows (attention tiles, HD=128 bf16 per row)
__device__ __forceinline__ void ldm_x4_256(uint32_t* r, uint32_t base, int row0, int c0) {
    const int l  = (int)(threadIdx.x & 31);
    const int rr = row0 + (l & 15);
    const int cc = (c0 + (l >> 4)) ^ (rr & 7);
    const uint32_t addr = base + (uint32_t)(rr * 256 + cc * 16);
    asm volatile("ldmatrix.sync.aligned.m8n8.x4.shared.b16 {%0,%1,%2,%3}, [%4];"
                 : "=r"(r[0]), "=r"(r[1]), "=r"(r[2]), "=r"(r[3]) : "r"(addr));
}
__device__ __forceinline__ void ldm_x4t_256(uint32_t* r, uint32_t base, int row0, int c0) {
    const int l  = (int)(threadIdx.x & 31);
    const int rr = row0 + (l & 15);
    const int cc = (c0 + (l >> 4)) ^ (rr & 7);
    const uint32_t addr = base + (uint32_t)(rr * 256 + cc * 16);
    asm volatile("ldmatrix.sync.aligned.m8n8.x4.trans.shared.b16 {%0,%1,%2,%3}, [%4];"
                 : "=r"(r[0]), "=r"(r[1]), "=r"(r[2]), "=r"(r[3]) : "r"(addr));
}
__device__ __forceinline__ void mma_bf16(float* d, const uint32_t* a,
                                         uint32_t b0, uint32_t b1) {
    asm volatile(
        "mma.sync.aligned.m16n8k16.row.col.f32.bf16.bf16.f32 "
        "{%0,%1,%2,%3}, {%4,%5,%6,%7}, {%8,%9}, {%0,%1,%2,%3};"
        : "+f"(d[0]), "+f"(d[1]), "+f"(d[2]), "+f"(d[3])
        : "r"(a[0]), "r"(a[1]), "r"(a[2]), "r"(a[3]), "r"(b0), "r"(b1));
}
__device__ __forceinline__ void pack_hilo(float p0, float p1, uint32_t& hi, uint32_t& lo) {
    float h0 = __bfloat162float(__float2bfloat16(p0));
    float h1 = __bfloat162float(__float2bfloat16(p1));
    hi = pack_bf16x2(h0, h1);
    lo = pack_bf16x2(p0 - h0, p1 - h1);
}

// ---------------------------------------------------------------------------
// fp32 -> bf16 hi/lo conversion (elementwise, MLP=4)
// ---------------------------------------------------------------------------
__global__ __launch_bounds__(256) void cvt_kernel(
    const float4* __restrict__ x, uint2* __restrict__ hi,
    uint2* __restrict__ lo, int n4)
{
    const int q = n4 >> 2;
    const int i = blockIdx.x * blockDim.x + threadIdx.x;
    if (i >= q) return;
    float4 f[4];
    f[0] = x[i]; f[1] = x[i + q]; f[2] = x[i + 2 * q]; f[3] = x[i + 3 * q];
#pragma unroll
    for (int u = 0; u < 4; u++) {
        float xs[4] = {f[u].x, f[u].y, f[u].z, f[u].w};
        float hf[4], lf[4];
#pragma unroll
        for (int t = 0; t < 4; t++) {
            __nv_bfloat16 h = __float2bfloat16(xs[t]);
            hf[t] = __bfloat162float(h);
            lf[t] = xs[t] - hf[t];
        }
        uint2 H, L;
        H.x = pack_bf16x2(hf[0], hf[1]); H.y = pack_bf16x2(hf[2], hf[3]);
        L.x = pack_bf16x2(lf[0], lf[1]); L.y = pack_bf16x2(lf[2], lf[3]);
        hi[i + u * q] = H;
        lo[i + u * q] = L;
    }
}

// ---------------------------------------------------------------------------
// GEMM: C[M,N] = A[M,K] * B[N,K]^T  (bf16 hi/lo x3 MMAs, fp32 out)
// Tile 128x128x32, 3-stage cp.async, 96KB smem -> 2 CTAs/SM. (R9 proven)
// ---------------------------------------------------------------------------
#define TBM 128
#define TBN 128
#define TBK 32
#define OFF_AH 0
#define OFF_AL 8192
#define OFF_BH 16384
#define OFF_BL 24576
#define STAGE_BYTES 32768
#define GEMM_SMEM (3 * STAGE_BYTES)   // 96 KB

__device__ __forceinline__ uint32_t mrow_off(int r, int kc) {
    const int mr = r >> 1;
    const int ch = (((r & 1) << 2) | kc) ^ (mr & 7);
    return (uint32_t)(mr * 128 + ch * 16);
}

__global__ __launch_bounds__(256, 2) void gemm_mma_kernel(
    const __nv_bfloat16* __restrict__ Ah, const __nv_bfloat16* __restrict__ Al,
    const __nv_bfloat16* __restrict__ Bh, const __nv_bfloat16* __restrict__ Bl,
    float* __restrict__ C0, float* __restrict__ C1,
    __nv_bfloat16* __restrict__ C2h, __nv_bfloat16* __restrict__ C2l,
    int ns1, int ns2, int ldc0, int ldc1, int ldc2,
    int M, int N, int K)
{
    extern __shared__ __align__(1024) char smem[];
    const uint32_t sbase = smem_u32(smem);
    const int tid  = threadIdx.x;
    const int lane = tid & 31;
    const int wid  = tid >> 5;
    const int wm   = wid & 1;
    const int wn   = wid >> 1;
    const int m0   = blockIdx.y * TBM;
    const int n0   = blockIdx.x * TBN;
    const int r0c = tid >> 2, c0c = tid & 3;

    float acc[4][4][4];
#pragma unroll
    for (int i = 0; i < 4; i++)
#pragma unroll
        for (int j = 0; j < 4; j++)
#pragma unroll
            for (int t = 0; t < 4; t++) acc[i][j][t] = 0.0f;

    const int nch = K / TBK;

    auto issue = [&](int s, int k0) {
        const uint32_t st = sbase + s * STAGE_BYTES;
#pragma unroll
        for (int half = 0; half < 2; half++) {
            const int r = r0c + half * 64;
            const uint32_t off = mrow_off(r, c0c);
            const size_t ga = (size_t)(m0 + r) * K + k0 + c0c * 8;
            const size_t gb = (size_t)(n0 + r) * K + k0 + c0c * 8;
            cp16(st + OFF_AH + off, Ah + ga);
            cp16(st + OFF_AL + off, Al + ga);
            cp16(st + OFF_BH + off, Bh + gb);
            cp16(st + OFF_BL + off, Bl + gb);
        }
        cp_commit();
    };

    issue(0, 0);
    issue(1, TBK);

    for (int ch = 0; ch < nch; ch++) {
        if (ch < nch - 1) cp_wait<1>();
        else              cp_wait<0>();
        __syncthreads();

        const int s = ch % 3;
        const uint32_t stAh = sbase + s * STAGE_BYTES + OFF_AH;
        const uint32_t stAl = sbase + s * STAGE_BYTES + OFF_AL;
        const uint32_t stBh = sbase + s * STAGE_BYTES + OFF_BH;
        const uint32_t stBl = sbase + s * STAGE_BYTES + OFF_BL;
#pragma unroll
        for (int kt = 0; kt < 2; kt++) {
            uint32_t ah[4][4], al[4][4], bh[2][4], bl[2][4];
#pragma unroll
            for (int mt = 0; mt < 4; mt++) {
                ldm_x4_k32(ah[mt], stAh, wm * 64 + mt * 16, kt);
                ldm_x4_k32(al[mt], stAl, wm * 64 + mt * 16, kt);
            }
#pragma unroll
            for (int bp = 0; bp < 2; bp++) {
                ldm_x4_k32(bh[bp], stBh, wn * 32 + bp * 16, kt);
                ldm_x4_k32(bl[bp], stBl, wn * 32 + bp * 16, kt);
            }
#pragma unroll
            for (int mt = 0; mt < 4; mt++)
#pragma unroll
                for (int nt = 0; nt < 4; nt++) {
                    const int bp = nt >> 1, o = nt & 1;
                    mma_bf16(acc[mt][nt], ah[mt], bh[bp][o], bh[bp][o + 2]);
                    mma_bf16(acc[mt][nt], ah[mt], bl[bp][o], bl[bp][o + 2]);
                    mma_bf16(acc[mt][nt], al[mt], bh[bp][o], bh[bp][o + 2]);
                }
        }

        if (ch + 2 < nch) issue((ch + 2) % 3, (ch + 2) * TBK);
    }

    // epilogue with column routing (CTA tile never straddles a split)
    if (n0 >= ns2 && C2h != nullptr) {
        const int nc0 = n0 - ns2;
#pragma unroll
        for (int mt = 0; mt < 4; mt++) {
            const int row = m0 + wm * 64 + mt * 16 + (lane >> 2);
#pragma unroll
            for (int nt = 0; nt < 4; nt++) {
                const int col = nc0 + wn * 32 + nt * 8 + (lane & 3) * 2;
                uint32_t h0, l0v, h1, l1v;
                pack_hilo(acc[mt][nt][0], acc[mt][nt][1], h0, l0v);
                pack_hilo(acc[mt][nt][2], acc[mt][nt][3], h1, l1v);
                *(uint32_t*)(C2h + (size_t)row * ldc2 + col)       = h0;
                *(uint32_t*)(C2l + (size_t)row * ldc2 + col)       = l0v;
                *(uint32_t*)(C2h + (size_t)(row + 8) * ldc2 + col) = h1;
                *(uint32_t*)(C2l + (size_t)(row + 8) * ldc2 + col) = l1v;
            }
        }
        return;
    }
    float* Cb; int ldc, nc0;
    if (n0 < ns1) { Cb = C0; ldc = ldc0; nc0 = n0; }
    else          { Cb = C1; ldc = ldc1; nc0 = n0 - ns1; }
#pragma unroll
    for (int mt = 0; mt < 4; mt++) {
        const int row = m0 + wm * 64 + mt * 16 + (lane >> 2);
#pragma unroll
        for (int nt = 0; nt < 4; nt++) {
            const int col = nc0 + wn * 32 + nt * 8 + (lane & 3) * 2;
            float2 v0 = make_float2(acc[mt][nt][0], acc[mt][nt][1]);
            float2 v1 = make_float2(acc[mt][nt][2], acc[mt][nt][3]);
            *(float2*)(Cb + (size_t)row * ldc + col)       = v0;
            *(float2*)(Cb + (size_t)(row + 8) * ldc + col) = v1;
        }
    }
}

// ---------------------------------------------------------------------------
// RoPE + fp32 -> bf16 hi/lo for q, k (vectorized float2 / bf16x2)
// ---------------------------------------------------------------------------
__global__ __launch_bounds__(256) void rope_cvt_kernel(
    const float* __restrict__ q, const float* __restrict__ k,
    const int* __restrict__ pos,
    __nv_bfloat16* __restrict__ qh, __nv_bfloat16* __restrict__ ql,
    __nv_bfloat16* __restrict__ kh, __nv_bfloat16* __restrict__ kl)
{
    const int bs = blockIdx.x;
    const float p = (float)pos[bs];
    const float c1 = -0.2076205059304601f;        // -log2(10000)/64
    for (int i = threadIdx.x; i < 1280; i += 256) {
        const float* base; size_t idx; int dp;
        __nv_bfloat16 *H, *L;
        if (i < 1024) {
            int hh = i >> 5; dp = (i & 31) * 2;
            idx = ((size_t)bs * NH + hh) * HD;
            base = q + idx; H = qh; L = ql;
        } else {
            int j = i - 1024;
            int hh = j >> 5; dp = (j & 31) * 2;
            idx = ((size_t)bs * NKV + hh) * HD;
            base = k + idx; H = kh; L = kl;
        }
        float2 x1 = *(const float2*)(base + dp);
        float2 x2 = *(const float2*)(base + dp + 64);
        float o1[2], o2[2];
#pragma unroll
        for (int t = 0; t < 2; t++) {
            float inv = exp2f(c1 * (float)(dp + t));
            float ang = p * inv;
            float sv, cv;
            sincosf(ang, &sv, &cv);
            float a  = t ? x1.y : x1.x;
            float b2 = t ? x2.y : x2.x;
            o1[t] = a * cv - b2 * sv;
            o2[t] = b2 * cv + a * sv;
        }
        uint32_t hA, lA, hB, lB;
        pack_hilo(o1[0], o1[1], hA, lA);
        pack_hilo(o2[0], o2[1], hB, lB);
        *(uint32_t*)(H + idx + dp)      = hA;
        *(uint32_t*)(L + idx + dp)      = lA;
        *(uint32_t*)(H + idx + dp + 64) = hB;
        *(uint32_t*)(L + idx + dp + 64) = lB;
    }
}

// ---------------------------------------------------------------------------
// Flash attention via mma.sync (bf16 hi/lo x3), fp32 softmax (exp2), causal.
// CTA: 64 q-rows x 1 head, 4 warps, 96KB smem -> 2 CTAs/SM.
// 3-stage KV ring; Q parked in slot 2 until fragments are hoisted.
// ONE __syncthreads per tile (reuse distance 3 makes the bottom sync redundant).
// ---------------------------------------------------------------------------
#define ABQ  64
#define ABKV 32
#define KVSTAGE 32768      // per-stage: KH 0, KL 8K, VH 16K, VL 24K
#define SKH 0
#define SKL 8192
#define SVH 16384
#define SVL 24576
#define AQH (2 * KVSTAGE)            // Q parked in slot 2
#define AQL (AQH + 16384)
#define ATTN_SMEM (3 * KVSTAGE)      // 96 KB

__global__ __launch_bounds__(128, 2) void attn_mma_kernel(
    const __nv_bfloat16* __restrict__ Qh, const __nv_bfloat16* __restrict__ Ql,
    const __nv_bfloat16* __restrict__ Kh, const __nv_bfloat16* __restrict__ Kl,
    const __nv_bfloat16* __restrict__ Vh, const __nv_bfloat16* __restrict__ Vl,
    __nv_bfloat16* __restrict__ AOh, __nv_bfloat16* __restrict__ AOl)
{
    extern __shared__ __align__(1024) char smem[];
    const uint32_t sbase = smem_u32(smem);
    const int tid  = threadIdx.x;
    const int lane = tid & 31;
    const int wq   = tid >> 5;                              // 0..3
    const int qb   = (int)gridDim.x - 1 - (int)blockIdx.x;  // big tiles first
    const int h    = blockIdx.y, b = blockIdx.z;
    const int g    = h / NREP;
    const int q0   = qb * ABQ;
    const int rowmin = q0 + wq * 16;
    const int lr8 = tid >> 4;      // 0..7 row within 8-row pass
    const int lc  = tid & 15;      // 16B chunk within 256B row

    // ---- Q tile into slot 2 (group: Q) ----
#pragma unroll
    for (int i = 0; i < 8; i++) {
        const int row = i * 8 + lr8;
        const uint32_t off = (uint32_t)(row * 256 + ((lc ^ (row & 7)) * 16));
        const size_t gp = ((size_t)(b * S_LEN + q0 + row) * NH + h) * HD + lc * 8;
        cp16(sbase + AQH + off, Qh + gp);
        cp16(sbase + AQL + off, Ql + gp);
    }
    cp_commit();

    auto issue_kv = [&](int s, int k0) {
        const uint32_t st = sbase + s * KVSTAGE;
#pragma unroll
        for (int i = 0; i < 4; i++) {
            const int row = i * 8 + lr8;
            const uint32_t off = (uint32_t)(row * 256 + ((lc ^ (row & 7)) * 16));
            const size_t gp = ((size_t)(b * S_LEN + k0 + row) * NKV + g) * HD + lc * 8;
            cp16(st + SKH + off, Kh + gp);
            cp16(st + SKL + off, Kl + gp);
            cp16(st + SVH + off, Vh + gp);
            cp16(st + SVL + off, Vl + gp);
        }
        cp_commit();
    };
    const int ntile = 2 * qb + 2;   // always >= 2
    issue_kv(0, 0);                 // group: KV0
    issue_kv(1, ABKV);              // group: KV1

    // ---- hoist Q fragments (tile-invariant); slot 2 is free afterwards ----
    cp_wait<2>();    // Q group complete (KV0/KV1 may still be in flight)
    __syncthreads();
    uint32_t aqh_r[8][4], aql_r[8][4];
#pragma unroll
    for (int kt = 0; kt < 8; kt++) {
        ldm_x4_256(aqh_r[kt], sbase + AQH, wq * 16, kt * 2);
        ldm_x4_256(aql_r[kt], sbase + AQL, wq * 16, kt * 2);
    }
    // slot 2 first rewritten by issue at end of kb=0, which is after the
    // kb=0 top-of-loop sync -> all warps have hoisted by then.

    float out[16][4];
#pragma unroll
    for (int i = 0; i < 16; i++)
#pragma unroll
        for (int j = 0; j < 4; j++) out[i][j] = 0.0f;
    float m0 = -1e30f, m1 = -1e30f, l0 = 0.0f, l1 = 0.0f;
    const float scl2 = 0.08838834764831845f * 1.4426950408889634f;  // /sqrt(128)*log2(e)

    for (int kb = 0; kb < ntile; kb++) {
        const int s = kb % 3;
        const int k0 = kb * ABKV;
        if (kb + 1 < ntile) cp_wait<1>();   // kv_kb done; kv_{kb+1} in flight
        else                cp_wait<0>();
        __syncthreads();   // also proves all warps done reading slot written next

        if (k0 <= rowmin + 15) {   // else tile fully masked for this warp
            const uint32_t stK = sbase + s * KVSTAGE;

            // ---- S = Q K^T  (16 x 32 x 128) ----
            float sc[4][4];
#pragma unroll
            for (int nt = 0; nt < 4; nt++)
#pragma unroll
                for (int j = 0; j < 4; j++) sc[nt][j] = 0.0f;
#pragma unroll
            for (int kt = 0; kt < 8; kt++) {
#pragma unroll
                for (int bp = 0; bp < 2; bp++) {
                    uint32_t bkh[4], bkl[4];
                    ldm_x4_256(bkh, stK + SKH, bp * 16, kt * 2);
                    ldm_x4_256(bkl, stK + SKL, bp * 16, kt * 2);
#pragma unroll
                    for (int o = 0; o < 2; o++) {
                        const int nt = bp * 2 + o;
                        mma_bf16(sc[nt], aqh_r[kt], bkh[o], bkh[o + 2]);
                        mma_bf16(sc[nt], aqh_r[kt], bkl[o], bkl[o + 2]);
                        mma_bf16(sc[nt], aql_r[kt], bkh[o], bkh[o + 2]);
                    }
                }
            }

            // ---- scale + causal mask + online softmax (exp2 domain) ----
            const int r0g = rowmin + (lane >> 2);
            const bool domask = (k0 + ABKV - 1) > rowmin;
            float mx0 = -1e30f, mx1 = -1e30f;
#pragma unroll
            for (int nt = 0; nt < 4; nt++) {
#pragma unroll
                for (int j = 0; j < 4; j++) {
                    float v = sc[nt][j] * scl2;
                    if (domask) {
                        int cg = k0 + nt * 8 + (lane & 3) * 2 + (j & 1);
                        int rg = r0g + ((j >> 1) << 3);
                        if (cg > rg) v = -1e30f;
                    }
                    sc[nt][j] = v;
                }
                mx0 = fmaxf(mx0, fmaxf(sc[nt][0], sc[nt][1]));
                mx1 = fmaxf(mx1, fmaxf(sc[nt][2], sc[nt][3]));
            }
            mx0 = fmaxf(mx0, __shfl_xor_sync(0xffffffffu, mx0, 1));
            mx0 = fmaxf(mx0, __shfl_xor_sync(0xffffffffu, mx0, 2));
            mx1 = fmaxf(mx1, __shfl_xor_sync(0xffffffffu, mx1, 1));
            mx1 = fmaxf(mx1, __shfl_xor_sync(0xffffffffu, mx1, 2));
            const float mn0 = fmaxf(m0, mx0), mn1 = fmaxf(m1, mx1);
            const float a0 = exp2f(m0 - mn0), a1 = exp2f(m1 - mn1);
            m0 = mn0; m1 = mn1;
            float ps0 = 0.0f, ps1 = 0.0f;
#pragma unroll
            for (int nt = 0; nt < 4; nt++) {
                sc[nt][0] = exp2f(sc[nt][0] - mn0); ps0 += sc[nt][0];
                sc[nt][1] = exp2f(sc[nt][1] - mn0); ps0 += sc[nt][1];
                sc[nt][2] = exp2f(sc[nt][2] - mn1); ps1 += sc[nt][2];
                sc[nt][3] = exp2f(sc[nt][3] - mn1); ps1 += sc[nt][3];
            }
            l0 = l0 * a0 + ps0;
            l1 = l1 * a1 + ps1;
#pragma unroll
            for (int dt = 0; dt < 16; dt++) {
                out[dt][0] *= a0; out[dt][1] *= a0;
                out[dt][2] *= a1; out[dt][3] *= a1;
            }

            // ---- O += P V  (16 x 128 x 32) ----
#pragma unroll
            for (int ktp = 0; ktp < 2; ktp++) {
                uint32_t aph[4], apl[4];
                const int t0 = ktp * 2, t1 = t0 + 1;
                pack_hilo(sc[t0][0], sc[t0][1], aph[0], apl[0]);
                pack_hilo(sc[t0][2], sc[t0][3], aph[1], apl[1]);
                pack_hilo(sc[t1][0], sc[t1][1], aph[2], apl[2]);
                pack_hilo(sc[t1][2], sc[t1][3], aph[3], apl[3]);
#pragma unroll
                for (int dt = 0; dt < 8; dt++) {
                    uint32_t bvh[4], bvl[4];
                    ldm_x4t_256(bvh, stK + SVH, ktp * 16, dt * 2);
                    ldm_x4t_256(bvl, stK + SVL, ktp * 16, dt * 2);
                    mma_bf16(out[dt * 2],     aph, bvh[0], bvh[1]);
                    mma_bf16(out[dt * 2],     aph, bvl[0], bvl[1]);
                    mma_bf16(out[dt * 2],     apl, bvh[0], bvh[1]);
                    mma_bf16(out[dt * 2 + 1], aph, bvh[2], bvh[3]);
                    mma_bf16(out[dt * 2 + 1], aph, bvl[2], bvl[3]);
                    mma_bf16(out[dt * 2 + 1], apl, bvh[2], bvh[3]);
                }
            }
        }

        if (kb + 2 < ntile) issue_kv((kb + 2) % 3, (kb + 2) * ABKV);
    }

    // ---- finalize: write bf16 hi/lo directly (feeds O-projection GEMM) ----
    l0 += __shfl_xor_sync(0xffffffffu, l0, 1);
    l0 += __shfl_xor_sync(0xffffffffu, l0, 2);
    l1 += __shfl_xor_sync(0xffffffffu, l1, 1);
    l1 += __shfl_xor_sync(0xffffffffu, l1, 2);
    const float i0 = 1.0f / l0, i1 = 1.0f / l1;
    const int r0g = rowmin + (lane >> 2);
    const size_t base0 = ((size_t)(b * S_LEN + r0g) * NH + h) * HD;
    const size_t base1 = base0 + (size_t)8 * NH * HD;
#pragma unroll
    for (int dt = 0; dt < 16; dt++) {
        const int col = dt * 8 + (lane & 3) * 2;
        uint32_t h0, l0p, h1, l1p;
        pack_hilo(out[dt][0] * i0, out[dt][1] * i0, h0, l0p);
        pack_hilo(out[dt][2] * i1, out[dt][3] * i1, h1, l1p);
        *(uint32_t*)(AOh + base0 + col) = h0;
        *(uint32_t*)(AOl + base0 + col) = l0p;
        *(uint32_t*)(AOh + base1 + col) = h1;
        *(uint32_t*)(AOl + base1 + col) = l1p;
    }
}

// ---------------------------------------------------------------------------
// Launch
// ---------------------------------------------------------------------------
extern "C" void kernel_launch(void* const* d_in, const int* in_sizes, int n_in,
                              void* d_out, int out_size)
{
    const float* hs = (const float*)d_in[0];
    const float* wq = (const float*)d_in[1];
    const float* wk = (const float*)d_in[2];
    const float* wv = (const float*)d_in[3];
    const float* wo = (const float*)d_in[4];
    const int*  pos = (const int*)  d_in[6];
    float*      out = (float*)d_out;

    float *q, *k;
    cudaGetSymbolAddress((void**)&q,  g_q);
    cudaGetSymbolAddress((void**)&k,  g_k);

    __nv_bfloat16 *hsh, *hsl, *wh, *wl, *woh, *wol, *aoh, *aol;
    __nv_bfloat16 *qh, *ql, *kh, *kl, *vh, *vl;
    cudaGetSymbolAddress((void**)&hsh, g_hs_h); cudaGetSymbolAddress((void**)&hsl, g_hs_l);
    cudaGetSymbolAddress((void**)&wh,  g_w_h);  cudaGetSymbolAddress((void**)&wl,  g_w_l);
    cudaGetSymbolAddress((void**)&woh, g_wo_h); cudaGetSymbolAddress((void**)&wol, g_wo_l);
    cudaGetSymbolAddress((void**)&aoh, g_ao_h); cudaGetSymbolAddress((void**)&aol, g_ao_l);
    cudaGetSymbolAddress((void**)&qh,  g_q_h);  cudaGetSymbolAddress((void**)&ql,  g_q_l);
    cudaGetSymbolAddress((void**)&kh,  g_k_h);  cudaGetSymbolAddress((void**)&kl,  g_k_l);
    cudaGetSymbolAddress((void**)&vh,  g_v_h);  cudaGetSymbolAddress((void**)&vl,  g_v_l);

    cudaFuncSetAttribute(gemm_mma_kernel, cudaFuncAttributeMaxDynamicSharedMemorySize, GEMM_SMEM);
    cudaFuncSetAttribute(attn_mma_kernel, cudaFuncAttributeMaxDynamicSharedMemorySize, ATTN_SMEM);

    auto cvt = [&](const float* x, __nv_bfloat16* hi, __nv_bfloat16* lo, int n) {
        int n4 = n / 4;
        int qn = n4 / 4;
        cvt_kernel<<<(qn + 255) / 256, 256>>>((const float4*)x, (uint2*)hi, (uint2*)lo, n4);
    };

    // pre-convert inputs; wq|wk|wv go into one combined [6144,4096] buffer
    cvt(hs, hsh, hsl, MROWS * HID);
    cvt(wq, wh,             wl,             NH  * HD * HID);
    cvt(wk, wh + 16777216u, wl + 16777216u, NKV * HD * HID);
    cvt(wv, wh + 20971520u, wl + 20971520u, NKV * HD * HID);
    cvt(wo, woh, wol, HID * NH * HD);

    // Merged QKV projection: N = 6144; q,k -> fp32, v -> bf16 hi/lo directly
    gemm_mma_kernel<<<dim3(6144 / TBN, MROWS / TBM), 256, GEMM_SMEM>>>(
        hsh, hsl, wh, wl, q, k, vh, vl,
        4096, 5120, NH * HD, NKV * HD, NKV * HD,
        MROWS, 6144, HID);

    // RoPE + hi/lo conversion for q, k
    rope_cvt_kernel<<<MROWS, 256>>>(q, k, pos, qh, ql, kh, kl);

    // Causal flash attention (mma.sync, 2 CTAs/SM, 3-stage ring, 1 sync/tile)
    attn_mma_kernel<<<dim3(S_LEN / ABQ, NH, B_SZ), 128, ATTN_SMEM>>>(
        qh, ql, kh, kl, vh, vl, aoh, aol);

    // Output projection
    gemm_mma_kernel<<<dim3(HID / TBN, MROWS / TBM), 256, GEMM_SMEM>>>(
        aoh, aol, woh, wol, out, out, nullptr, nullptr,
        HID, HID, HID, HID, HID,
        MROWS, HID, NH * HD);
}

// round 11
// speedup vs baseline: 2.9694x; 1.0333x over previous
#include <cuda_runtime.h>
#include <cuda_bf16.h>
#include <cstdint>

// Problem constants (fixed shapes)
#define NH    32
#define NKV   8
#define HD    128
#define S_LEN 2048
#define B_SZ  2
#define HID   4096
#define MROWS (B_SZ * S_LEN)   // 4096
#define NREP  (NH / NKV)       // 4

#define E16M (16u * 1024u * 1024u)
#define E4M  (4u  * 1024u * 1024u)
#define WQKV_E (6144u * 4096u)   // combined q|k|v weight rows

// ---------------------------------------------------------------------------
// Scratch (device globals; allocation-free per harness rules)
// ---------------------------------------------------------------------------
__device__ float g_q [(size_t)MROWS * NH  * HD];
__device__ float g_k [(size_t)MROWS * NKV * HD];

// bf16 hi/lo copies
__device__ __nv_bfloat16 g_hs_h[E16M],  g_hs_l[E16M];
__device__ __nv_bfloat16 g_w_h[WQKV_E], g_w_l[WQKV_E];   // wq|wk|wv combined
__device__ __nv_bfloat16 g_wo_h[E16M],  g_wo_l[E16M];
__device__ __nv_bfloat16 g_ao_h[E16M],  g_ao_l[E16M];
// post-rope bf16 hi/lo q/k, direct-split v for attention
__device__ __nv_bfloat16 g_q_h[E16M], g_q_l[E16M];
__device__ __nv_bfloat16 g_k_h[E4M],  g_k_l[E4M];
__device__ __nv_bfloat16 g_v_h[E4M],  g_v_l[E4M];

// ---------------------------------------------------------------------------
// Common helpers (sm_80-level PTX only; no 'a'-suffix features)
// ---------------------------------------------------------------------------
__device__ __forceinline__ uint32_t smem_u32(const void* p) {
    uint32_t a;
    asm("{ .reg .u64 t; cvta.to.shared.u64 t, %1; cvt.u32.u64 %0, t; }"
        : "=r"(a) : "l"(p));
    return a;
}
__device__ __forceinline__ uint32_t pack_bf16x2(float a, float b) {
    __nv_bfloat162 h = __floats2bfloat162_rn(a, b);
    return *reinterpret_cast<uint32_t*>(&h);
}
__device__ __forceinline__ void cp16(uint32_t saddr, const void* gptr) {
    asm volatile("cp.async.cg.shared.global [%0], [%1], 16;"
                 :: "r"(saddr), "l"(gptr));
}
__device__ __forceinline__ void cp_commit() {
    asm volatile("cp.async.commit_group;" ::: "memory");
}
template <int N>
__device__ __forceinline__ void cp_wait() {
    asm volatile("cp.async.wait_group %0;" :: "n"(N) : "memory");
}
// ldmatrix.x4 over macro-row layout: logical rows of 32 bf16 (64B) are packed
// in pairs into 128B macro-rows with the standard XOR-8 swizzle.
__device__ __forceinline__ void ldm_x4_k32(uint32_t* r, uint32_t base, int row0, int kt) {
    const int l  = (int)(threadIdx.x & 31);
    const int rr = row0 + (l & 15);
    const int kc = 2 * kt + (l >> 4);
    const int mr = rr >> 1;
    const int ch = (((rr & 1) << 2) | kc) ^ (mr & 7);
    const uint32_t addr = base + (uint32_t)(mr * 128 + ch * 16);
    asm volatile("ldmatrix.sync.aligned.m8n8.x4.shared.b16 {%0,%1,%2,%3}, [%4];"
                 : "=r"(r[0]), "=r"(r[1]), "=r"(r[2]), "=r"(r[3]) : "r"(addr));
}
// ldmatrix.x4, 256B-wide rows (attention tiles, HD=128 bf16 per row)
__device__ __forceinline__ void ldm_x4_256(uint32_t* r, uint32_t base, int row0, int c0) {
    const int l  = (int)(threadIdx.x & 31);
    const int rr = row0 + (l & 15);
    const int cc = (c0 + (l >> 4)) ^ (rr & 7);
    const uint32_t addr = base + (uint32_t)(rr * 256 + cc * 16);
    asm volatile("ldmatrix.sync.aligned.m8n8.x4.shared.b16 {%0,%1,%2,%3}, [%4];"
                 : "=r"(r[0]), "=r"(r[1]), "=r"(r[2]), "=r"(r[3]) : "r"(addr));
}
__device__ __forceinline__ void ldm_x4t_256(uint32_t* r, uint32_t base, int row0, int c0) {
    const int l  = (int)(threadIdx.x & 31);
    const int rr = row0 + (l & 15);
    const int cc = (c0 + (l >> 4)) ^ (rr & 7);
    const uint32_t addr = base + (uint32_t)(rr * 256 + cc * 16);
    asm volatile("ldmatrix.sync.aligned.m8n8.x4.trans.shared.b16 {%0,%1,%2,%3}, [%4];"
                 : "=r"(r[0]), "=r"(r[1]), "=r"(r[2]), "=r"(r[3]) : "r"(addr));
}
__device__ __forceinline__ void mma_bf16(float* d, const uint32_t* a,
                                         uint32_t b0, uint32_t b1) {
    asm volatile(
        "mma.sync.aligned.m16n8k16.row.col.f32.bf16.bf16.f32 "
        "{%0,%1,%2,%3}, {%4,%5,%6,%7}, {%8,%9}, {%0,%1,%2,%3};"
        : "+f"(d[0]), "+f"(d[1]), "+f"(d[2]), "+f"(d[3])
        : "r"(a[0]), "r"(a[1]), "r"(a[2]), "r"(a[3]), "r"(b0), "r"(b1));
}
__device__ __forceinline__ void pack_hilo(float p0, float p1, uint32_t& hi, uint32_t& lo) {
    float h0 = __bfloat162float(__float2bfloat16(p0));
    float h1 = __bfloat162float(__float2bfloat16(p1));
    hi = pack_bf16x2(h0, h1);
    lo = pack_bf16x2(p0 - h0, p1 - h1);
}

// ---------------------------------------------------------------------------
// fp32 -> bf16 hi/lo conversion (elementwise, MLP=4)
// ---------------------------------------------------------------------------
__global__ __launch_bounds__(256) void cvt_kernel(
    const float4* __restrict__ x, uint2* __restrict__ hi,
    uint2* __restrict__ lo, int n4)
{
    const int q = n4 >> 2;
    const int i = blockIdx.x * blockDim.x + threadIdx.x;
    if (i >= q) return;
    float4 f[4];
    f[0] = x[i]; f[1] = x[i + q]; f[2] = x[i + 2 * q]; f[3] = x[i + 3 * q];
#pragma unroll
    for (int u = 0; u < 4; u++) {
        float xs[4] = {f[u].x, f[u].y, f[u].z, f[u].w};
        float hf[4], lf[4];
#pragma unroll
        for (int t = 0; t < 4; t++) {
            __nv_bfloat16 h = __float2bfloat16(xs[t]);
            hf[t] = __bfloat162float(h);
            lf[t] = xs[t] - hf[t];
        }
        uint2 H, L;
        H.x = pack_bf16x2(hf[0], hf[1]); H.y = pack_bf16x2(hf[2], hf[3]);
        L.x = pack_bf16x2(lf[0], lf[1]); L.y = pack_bf16x2(lf[2], lf[3]);
        hi[i + u * q] = H;
        lo[i + u * q] = L;
    }
}

// ---------------------------------------------------------------------------
// GEMM: C[M,N] = A[M,K] * B[N,K]^T  (bf16 hi/lo x3 MMAs, fp32 out)
// Tile 128x64x32, 128 threads = 4 warps (2 M x 2 N), warp tile 64x32.
// 3-stage cp.async ring, 72KB smem -> 3 CTAs/SM (finer tiles: small tails).
// Epilogue routes columns to up to 3 destinations; dest 2 emits bf16 hi/lo.
// ---------------------------------------------------------------------------
#define TBM 128
#define TBN 64
#define TBK 32
#define OFF_AH 0
#define OFF_AL 8192
#define OFF_BH 16384
#define OFF_BL 20480
#define STAGE_BYTES 24576
#define GEMM_SMEM (3 * STAGE_BYTES)   // 72 KB

__device__ __forceinline__ uint32_t mrow_off(int r, int kc) {
    const int mr = r >> 1;
    const int ch = (((r & 1) << 2) | kc) ^ (mr & 7);
    return (uint32_t)(mr * 128 + ch * 16);
}

__global__ __launch_bounds__(128, 3) void gemm_mma_kernel(
    const __nv_bfloat16* __restrict__ Ah, const __nv_bfloat16* __restrict__ Al,
    const __nv_bfloat16* __restrict__ Bh, const __nv_bfloat16* __restrict__ Bl,
    float* __restrict__ C0, float* __restrict__ C1,
    __nv_bfloat16* __restrict__ C2h, __nv_bfloat16* __restrict__ C2l,
    int ns1, int ns2, int ldc0, int ldc1, int ldc2,
    int M, int N, int K)
{
    extern __shared__ __align__(1024) char smem[];
    const uint32_t sbase = smem_u32(smem);
    const int tid  = threadIdx.x;
    const int lane = tid & 31;
    const int wid  = tid >> 5;       // 0..3
    const int wm   = wid & 1;        // warp rows [wm*64,+64)
    const int wn   = wid >> 1;       // warp cols [wn*32,+32)
    const int m0   = blockIdx.y * TBM;
    const int n0   = blockIdx.x * TBN;
    const int r0c = tid >> 2, c0c = tid & 3;   // copy coords (row group, chunk)

    float acc[4][4][4];
#pragma unroll
    for (int i = 0; i < 4; i++)
#pragma unroll
        for (int j = 0; j < 4; j++)
#pragma unroll
            for (int t = 0; t < 4; t++) acc[i][j][t] = 0.0f;

    const int nch = K / TBK;

    auto issue = [&](int s, int k0) {
        const uint32_t st = sbase + s * STAGE_BYTES;
#pragma unroll
        for (int i = 0; i < 4; i++) {           // A: 128 rows
            const int r = r0c + i * 32;
            const uint32_t off = mrow_off(r, c0c);
            const size_t ga = (size_t)(m0 + r) * K + k0 + c0c * 8;
            cp16(st + OFF_AH + off, Ah + ga);
            cp16(st + OFF_AL + off, Al + ga);
        }
#pragma unroll
        for (int i = 0; i < 2; i++) {           // B: 64 rows
            const int r = r0c + i * 32;
            const uint32_t off = mrow_off(r, c0c);
            const size_t gb = (size_t)(n0 + r) * K + k0 + c0c * 8;
            cp16(st + OFF_BH + off, Bh + gb);
            cp16(st + OFF_BL + off, Bl + gb);
        }
        cp_commit();
    };

    issue(0, 0);
    issue(1, TBK);

    for (int ch = 0; ch < nch; ch++) {
        if (ch < nch - 1) cp_wait<1>();
        else              cp_wait<0>();
        __syncthreads();

        const int s = ch % 3;
        const uint32_t stAh = sbase + s * STAGE_BYTES + OFF_AH;
        const uint32_t stAl = sbase + s * STAGE_BYTES + OFF_AL;
        const uint32_t stBh = sbase + s * STAGE_BYTES + OFF_BH;
        const uint32_t stBl = sbase + s * STAGE_BYTES + OFF_BL;
#pragma unroll
        for (int kt = 0; kt < 2; kt++) {
            uint32_t ah[4][4], al[4][4], bh[2][4], bl[2][4];
#pragma unroll
            for (int mt = 0; mt < 4; mt++) {
                ldm_x4_k32(ah[mt], stAh, wm * 64 + mt * 16, kt);
                ldm_x4_k32(al[mt], stAl, wm * 64 + mt * 16, kt);
            }
#pragma unroll
            for (int bp = 0; bp < 2; bp++) {
                ldm_x4_k32(bh[bp], stBh, wn * 32 + bp * 16, kt);
                ldm_x4_k32(bl[bp], stBl, wn * 32 + bp * 16, kt);
            }
#pragma unroll
            for (int mt = 0; mt < 4; mt++)
#pragma unroll
                for (int nt = 0; nt < 4; nt++) {
                    const int bp = nt >> 1, o = nt & 1;
                    mma_bf16(acc[mt][nt], ah[mt], bh[bp][o], bh[bp][o + 2]);
                    mma_bf16(acc[mt][nt], ah[mt], bl[bp][o], bl[bp][o + 2]);
                    mma_bf16(acc[mt][nt], al[mt], bh[bp][o], bh[bp][o + 2]);
                }
        }

        if (ch + 2 < nch) issue((ch + 2) % 3, (ch + 2) * TBK);
    }

    // epilogue with column routing (CTA tile never straddles a split)
    if (n0 >= ns2 && C2h != nullptr) {
        const int nc0 = n0 - ns2;
#pragma unroll
        for (int mt = 0; mt < 4; mt++) {
            const int row = m0 + wm * 64 + mt * 16 + (lane >> 2);
#pragma unroll
            for (int nt = 0; nt < 4; nt++) {
                const int col = nc0 + wn * 32 + nt * 8 + (lane & 3) * 2;
                uint32_t h0, l0v, h1, l1v;
                pack_hilo(acc[mt][nt][0], acc[mt][nt][1], h0, l0v);
                pack_hilo(acc[mt][nt][2], acc[mt][nt][3], h1, l1v);
                *(uint32_t*)(C2h + (size_t)row * ldc2 + col)       = h0;
                *(uint32_t*)(C2l + (size_t)row * ldc2 + col)       = l0v;
                *(uint32_t*)(C2h + (size_t)(row + 8) * ldc2 + col) = h1;
                *(uint32_t*)(C2l + (size_t)(row + 8) * ldc2 + col) = l1v;
            }
        }
        return;
    }
    float* Cb; int ldc, nc0;
    if (n0 < ns1) { Cb = C0; ldc = ldc0; nc0 = n0; }
    else          { Cb = C1; ldc = ldc1; nc0 = n0 - ns1; }
#pragma unroll
    for (int mt = 0; mt < 4; mt++) {
        const int row = m0 + wm * 64 + mt * 16 + (lane >> 2);
#pragma unroll
        for (int nt = 0; nt < 4; nt++) {
            const int col = nc0 + wn * 32 + nt * 8 + (lane & 3) * 2;
            float2 v0 = make_float2(acc[mt][nt][0], acc[mt][nt][1]);
            float2 v1 = make_float2(acc[mt][nt][2], acc[mt][nt][3]);
            *(float2*)(Cb + (size_t)row * ldc + col)       = v0;
            *(float2*)(Cb + (size_t)(row + 8) * ldc + col) = v1;
        }
    }
}

// ---------------------------------------------------------------------------
// RoPE + fp32 -> bf16 hi/lo for q, k (vectorized float2 / bf16x2)
// ---------------------------------------------------------------------------
__global__ __launch_bounds__(256) void rope_cvt_kernel(
    const float* __restrict__ q, const float* __restrict__ k,
    const int* __restrict__ pos,
    __nv_bfloat16* __restrict__ qh, __nv_bfloat16* __restrict__ ql,
    __nv_bfloat16* __restrict__ kh, __nv_bfloat16* __restrict__ kl)
{
    const int bs = blockIdx.x;
    const float p = (float)pos[bs];
    const float c1 = -0.2076205059304601f;        // -log2(10000)/64
    for (int i = threadIdx.x; i < 1280; i += 256) {
        const float* base; size_t idx; int dp;
        __nv_bfloat16 *H, *L;
        if (i < 1024) {
            int hh = i >> 5; dp = (i & 31) * 2;
            idx = ((size_t)bs * NH + hh) * HD;
            base = q + idx; H = qh; L = ql;
        } else {
            int j = i - 1024;
            int hh = j >> 5; dp = (j & 31) * 2;
            idx = ((size_t)bs * NKV + hh) * HD;
            base = k + idx; H = kh; L = kl;
        }
        float2 x1 = *(const float2*)(base + dp);
        float2 x2 = *(const float2*)(base + dp + 64);
        float o1[2], o2[2];
#pragma unroll
        for (int t = 0; t < 2; t++) {
            float inv = exp2f(c1 * (float)(dp + t));
            float ang = p * inv;
            float sv, cv;
            sincosf(ang, &sv, &cv);
            float a  = t ? x1.y : x1.x;
            float b2 = t ? x2.y : x2.x;
            o1[t] = a * cv - b2 * sv;
            o2[t] = b2 * cv + a * sv;
        }
        uint32_t hA, lA, hB, lB;
        pack_hilo(o1[0], o1[1], hA, lA);
        pack_hilo(o2[0], o2[1], hB, lB);
        *(uint32_t*)(H + idx + dp)      = hA;
        *(uint32_t*)(L + idx + dp)      = lA;
        *(uint32_t*)(H + idx + dp + 64) = hB;
        *(uint32_t*)(L + idx + dp + 64) = lB;
    }
}

// ---------------------------------------------------------------------------
// Flash attention via mma.sync (bf16 hi/lo x3), fp32 softmax (exp2), causal.
// CTA: 64 q-rows x 1 head, 4 warps, 96KB smem -> 2 CTAs/SM.
// 3-stage KV ring; Q parked in slot 2 until fragments are hoisted.
// ONE __syncthreads per tile (reuse distance 3 makes the bottom sync redundant).
// ---------------------------------------------------------------------------
#define ABQ  64
#define ABKV 32
#define KVSTAGE 32768      // per-stage: KH 0, KL 8K, VH 16K, VL 24K
#define SKH 0
#define SKL 8192
#define SVH 16384
#define SVL 24576
#define AQH (2 * KVSTAGE)            // Q parked in slot 2
#define AQL (AQH + 16384)
#define ATTN_SMEM (3 * KVSTAGE)      // 96 KB

__global__ __launch_bounds__(128, 2) void attn_mma_kernel(
    const __nv_bfloat16* __restrict__ Qh, const __nv_bfloat16* __restrict__ Ql,
    const __nv_bfloat16* __restrict__ Kh, const __nv_bfloat16* __restrict__ Kl,
    const __nv_bfloat16* __restrict__ Vh, const __nv_bfloat16* __restrict__ Vl,
    __nv_bfloat16* __restrict__ AOh, __nv_bfloat16* __restrict__ AOl)
{
    extern __shared__ __align__(1024) char smem[];
    const uint32_t sbase = smem_u32(smem);
    const int tid  = threadIdx.x;
    const int lane = tid & 31;
    const int wq   = tid >> 5;                              // 0..3
    const int qb   = (int)gridDim.x - 1 - (int)blockIdx.x;  // big tiles first
    const int h    = blockIdx.y, b = blockIdx.z;
    const int g    = h / NREP;
    const int q0   = qb * ABQ;
    const int rowmin = q0 + wq * 16;
    const int lr8 = tid >> 4;      // 0..7 row within 8-row pass
    const int lc  = tid & 15;      // 16B chunk within 256B row

    // ---- Q tile into slot 2 (group: Q) ----
#pragma unroll
    for (int i = 0; i < 8; i++) {
        const int row = i * 8 + lr8;
        const uint32_t off = (uint32_t)(row * 256 + ((lc ^ (row & 7)) * 16));
        const size_t gp = ((size_t)(b * S_LEN + q0 + row) * NH + h) * HD + lc * 8;
        cp16(sbase + AQH + off, Qh + gp);
        cp16(sbase + AQL + off, Ql + gp);
    }
    cp_commit();

    auto issue_kv = [&](int s, int k0) {
        const uint32_t st = sbase + s * KVSTAGE;
#pragma unroll
        for (int i = 0; i < 4; i++) {
            const int row = i * 8 + lr8;
            const uint32_t off = (uint32_t)(row * 256 + ((lc ^ (row & 7)) * 16));
            const size_t gp = ((size_t)(b * S_LEN + k0 + row) * NKV + g) * HD + lc * 8;
            cp16(st + SKH + off, Kh + gp);
            cp16(st + SKL + off, Kl + gp);
            cp16(st + SVH + off, Vh + gp);
            cp16(st + SVL + off, Vl + gp);
        }
        cp_commit();
    };
    const int ntile = 2 * qb + 2;   // always >= 2
    issue_kv(0, 0);                 // group: KV0
    issue_kv(1, ABKV);              // group: KV1

    // ---- hoist Q fragments (tile-invariant); slot 2 is free afterwards ----
    cp_wait<2>();    // Q group complete (KV0/KV1 may still be in flight)
    __syncthreads();
    uint32_t aqh_r[8][4], aql_r[8][4];
#pragma unroll
    for (int kt = 0; kt < 8; kt++) {
        ldm_x4_256(aqh_r[kt], sbase + AQH, wq * 16, kt * 2);
        ldm_x4_256(aql_r[kt], sbase + AQL, wq * 16, kt * 2);
    }

    float out[16][4];
#pragma unroll
    for (int i = 0; i < 16; i++)
#pragma unroll
        for (int j = 0; j < 4; j++) out[i][j] = 0.0f;
    float m0 = -1e30f, m1 = -1e30f, l0 = 0.0f, l1 = 0.0f;
    const float scl2 = 0.08838834764831845f * 1.4426950408889634f;  // /sqrt(128)*log2(e)

    for (int kb = 0; kb < ntile; kb++) {
        const int s = kb % 3;
        const int k0 = kb * ABKV;
        if (kb + 1 < ntile) cp_wait<1>();
        else                cp_wait<0>();
        __syncthreads();

        if (k0 <= rowmin + 15) {   // else tile fully masked for this warp
            const uint32_t stK = sbase + s * KVSTAGE;

            // ---- S = Q K^T  (16 x 32 x 128) ----
            float sc[4][4];
#pragma unroll
            for (int nt = 0; nt < 4; nt++)
#pragma unroll
                for (int j = 0; j < 4; j++) sc[nt][j] = 0.0f;
#pragma unroll
            for (int kt = 0; kt < 8; kt++) {
#pragma unroll
                for (int bp = 0; bp < 2; bp++) {
                    uint32_t bkh[4], bkl[4];
                    ldm_x4_256(bkh, stK + SKH, bp * 16, kt * 2);
                    ldm_x4_256(bkl, stK + SKL, bp * 16, kt * 2);
#pragma unroll
                    for (int o = 0; o < 2; o++) {
                        const int nt = bp * 2 + o;
                        mma_bf16(sc[nt], aqh_r[kt], bkh[o], bkh[o + 2]);
                        mma_bf16(sc[nt], aqh_r[kt], bkl[o], bkl[o + 2]);
                        mma_bf16(sc[nt], aql_r[kt], bkh[o], bkh[o + 2]);
                    }
                }
            }

            // ---- scale + causal mask + online softmax (exp2 domain) ----
            const int r0g = rowmin + (lane >> 2);
            const bool domask = (k0 + ABKV - 1) > rowmin;
            float mx0 = -1e30f, mx1 = -1e30f;
#pragma unroll
            for (int nt = 0; nt < 4; nt++) {
#pragma unroll
                for (int j = 0; j < 4; j++) {
                    float v = sc[nt][j] * scl2;
                    if (domask) {
                        int cg = k0 + nt * 8 + (lane & 3) * 2 + (j & 1);
                        int rg = r0g + ((j >> 1) << 3);
                        if (cg > rg) v = -1e30f;
                    }
                    sc[nt][j] = v;
                }
                mx0 = fmaxf(mx0, fmaxf(sc[nt][0], sc[nt][1]));
                mx1 = fmaxf(mx1, fmaxf(sc[nt][2], sc[nt][3]));
            }
            mx0 = fmaxf(mx0, __shfl_xor_sync(0xffffffffu, mx0, 1));
            mx0 = fmaxf(mx0, __shfl_xor_sync(0xffffffffu, mx0, 2));
            mx1 = fmaxf(mx1, __shfl_xor_sync(0xffffffffu, mx1, 1));
            mx1 = fmaxf(mx1, __shfl_xor_sync(0xffffffffu, mx1, 2));
            const float mn0 = fmaxf(m0, mx0), mn1 = fmaxf(m1, mx1);
            const float a0 = exp2f(m0 - mn0), a1 = exp2f(m1 - mn1);
            m0 = mn0; m1 = mn1;
            float ps0 = 0.0f, ps1 = 0.0f;
#pragma unroll
            for (int nt = 0; nt < 4; nt++) {
                sc[nt][0] = exp2f(sc[nt][0] - mn0); ps0 += sc[nt][0];
                sc[nt][1] = exp2f(sc[nt][1] - mn0); ps0 += sc[nt][1];
                sc[nt][2] = exp2f(sc[nt][2] - mn1); ps1 += sc[nt][2];
                sc[nt][3] = exp2f(sc[nt][3] - mn1); ps1 += sc[nt][3];
            }
            l0 = l0 * a0 + ps0;
            l1 = l1 * a1 + ps1;
#pragma unroll
            for (int dt = 0; dt < 16; dt++) {
                out[dt][0] *= a0; out[dt][1] *= a0;
                out[dt][2] *= a1; out[dt][3] *= a1;
            }

            // ---- O += P V  (16 x 128 x 32) ----
#pragma unroll
            for (int ktp = 0; ktp < 2; ktp++) {
                uint32_t aph[4], apl[4];
                const int t0 = ktp * 2, t1 = t0 + 1;
                pack_hilo(sc[t0][0], sc[t0][1], aph[0], apl[0]);
                pack_hilo(sc[t0][2], sc[t0][3], aph[1], apl[1]);
                pack_hilo(sc[t1][0], sc[t1][1], aph[2], apl[2]);
                pack_hilo(sc[t1][2], sc[t1][3], aph[3], apl[3]);
#pragma unroll
                for (int dt = 0; dt < 8; dt++) {
                    uint32_t bvh[4], bvl[4];
                    ldm_x4t_256(bvh, stK + SVH, ktp * 16, dt * 2);
                    ldm_x4t_256(bvl, stK + SVL, ktp * 16, dt * 2);
                    mma_bf16(out[dt * 2],     aph, bvh[0], bvh[1]);
                    mma_bf16(out[dt * 2],     aph, bvl[0], bvl[1]);
                    mma_bf16(out[dt * 2],     apl, bvh[0], bvh[1]);
                    mma_bf16(out[dt * 2 + 1], aph, bvh[2], bvh[3]);
                    mma_bf16(out[dt * 2 + 1], aph, bvl[2], bvl[3]);
                    mma_bf16(out[dt * 2 + 1], apl, bvh[2], bvh[3]);
                }
            }
        }

        if (kb + 2 < ntile) issue_kv((kb + 2) % 3, (kb + 2) * ABKV);
    }

    // ---- finalize: write bf16 hi/lo directly (feeds O-projection GEMM) ----
    l0 += __shfl_xor_sync(0xffffffffu, l0, 1);
    l0 += __shfl_xor_sync(0xffffffffu, l0, 2);
    l1 += __shfl_xor_sync(0xffffffffu, l1, 1);
    l1 += __shfl_xor_sync(0xffffffffu, l1, 2);
    const float i0 = 1.0f / l0, i1 = 1.0f / l1;
    const int r0g = rowmin + (lane >> 2);
    const size_t base0 = ((size_t)(b * S_LEN + r0g) * NH + h) * HD;
    const size_t base1 = base0 + (size_t)8 * NH * HD;
#pragma unroll
    for (int dt = 0; dt < 16; dt++) {
        const int col = dt * 8 + (lane & 3) * 2;
        uint32_t h0, l0p, h1, l1p;
        pack_hilo(out[dt][0] * i0, out[dt][1] * i0, h0, l0p);
        pack_hilo(out[dt][2] * i1, out[dt][3] * i1, h1, l1p);
        *(uint32_t*)(AOh + base0 + col) = h0;
        *(uint32_t*)(AOl + base0 + col) = l0p;
        *(uint32_t*)(AOh + base1 + col) = h1;
        *(uint32_t*)(AOl + base1 + col) = l1p;
    }
}

// ---------------------------------------------------------------------------
// Launch
// ---------------------------------------------------------------------------
extern "C" void kernel_launch(void* const* d_in, const int* in_sizes, int n_in,
                              void* d_out, int out_size)
{
    const float* hs = (const float*)d_in[0];
    const float* wq = (const float*)d_in[1];
    const float* wk = (const float*)d_in[2];
    const float* wv = (const float*)d_in[3];
    const float* wo = (const float*)d_in[4];
    const int*  pos = (const int*)  d_in[6];
    float*      out = (float*)d_out;

    float *q, *k;
    cudaGetSymbolAddress((void**)&q,  g_q);
    cudaGetSymbolAddress((void**)&k,  g_k);

    __nv_bfloat16 *hsh, *hsl, *wh, *wl, *woh, *wol, *aoh, *aol;
    __nv_bfloat16 *qh, *ql, *kh, *kl, *vh, *vl;
    cudaGetSymbolAddress((void**)&hsh, g_hs_h); cudaGetSymbolAddress((void**)&hsl, g_hs_l);
    cudaGetSymbolAddress((void**)&wh,  g_w_h);  cudaGetSymbolAddress((void**)&wl,  g_w_l);
    cudaGetSymbolAddress((void**)&woh, g_wo_h); cudaGetSymbolAddress((void**)&wol, g_wo_l);
    cudaGetSymbolAddress((void**)&aoh, g_ao_h); cudaGetSymbolAddress((void**)&aol, g_ao_l);
    cudaGetSymbolAddress((void**)&qh,  g_q_h);  cudaGetSymbolAddress((void**)&ql,  g_q_l);
    cudaGetSymbolAddress((void**)&kh,  g_k_h);  cudaGetSymbolAddress((void**)&kl,  g_k_l);
    cudaGetSymbolAddress((void**)&vh,  g_v_h);  cudaGetSymbolAddress((void**)&vl,  g_v_l);

    cudaFuncSetAttribute(gemm_mma_kernel, cudaFuncAttributeMaxDynamicSharedMemorySize, GEMM_SMEM);
    cudaFuncSetAttribute(attn_mma_kernel, cudaFuncAttributeMaxDynamicSharedMemorySize, ATTN_SMEM);

    auto cvt = [&](const float* x, __nv_bfloat16* hi, __nv_bfloat16* lo, int n) {
        int n4 = n / 4;
        int qn = n4 / 4;
        cvt_kernel<<<(qn + 255) / 256, 256>>>((const float4*)x, (uint2*)hi, (uint2*)lo, n4);
    };

    // pre-convert inputs; wq|wk|wv go into one combined [6144,4096] buffer
    cvt(hs, hsh, hsl, MROWS * HID);
    cvt(wq, wh,             wl,             NH  * HD * HID);
    cvt(wk, wh + 16777216u, wl + 16777216u, NKV * HD * HID);
    cvt(wv, wh + 20971520u, wl + 20971520u, NKV * HD * HID);
    cvt(wo, woh, wol, HID * NH * HD);

    // Merged QKV projection: N = 6144; q,k -> fp32, v -> bf16 hi/lo directly
    gemm_mma_kernel<<<dim3(6144 / TBN, MROWS / TBM), 128, GEMM_SMEM>>>(
        hsh, hsl, wh, wl, q, k, vh, vl,
        4096, 5120, NH * HD, NKV * HD, NKV * HD,
        MROWS, 6144, HID);

    // RoPE + hi/lo conversion for q, k
    rope_cvt_kernel<<<MROWS, 256>>>(q, k, pos, qh, ql, kh, kl);

    // Causal flash attention (mma.sync, 2 CTAs/SM, 3-stage ring, 1 sync/tile)
    attn_mma_kernel<<<dim3(S_LEN / ABQ, NH, B_SZ), 128, ATTN_SMEM>>>(
        qh, ql, kh, kl, vh, vl, aoh, aol);

    // Output projection
    gemm_mma_kernel<<<dim3(HID / TBN, MROWS / TBM), 128, GEMM_SMEM>>>(
        aoh, aol, woh, wol, out, out, nullptr, nullptr,
        HID, HID, HID, HID, HID,
        MROWS, HID, NH * HD);
}

// round 12
// speedup vs baseline: 2.9775x; 1.0027x over previous
#include <cuda_runtime.h>
#include <cuda_bf16.h>
#include <cstdint>

// Problem constants (fixed shapes)
#define NH    32
#define NKV   8
#define HD    128
#define S_LEN 2048
#define B_SZ  2
#define HID   4096
#define MROWS (B_SZ * S_LEN)   // 4096
#define NREP  (NH / NKV)       // 4

#define E16M (16u * 1024u * 1024u)
#define E4M  (4u  * 1024u * 1024u)
#define WQKV_E (6144u * 4096u)   // combined q|k|v weight rows

// ---------------------------------------------------------------------------
// Scratch (device globals; allocation-free per harness rules)
// ---------------------------------------------------------------------------
__device__ float g_q [(size_t)MROWS * NH  * HD];
__device__ float g_k [(size_t)MROWS * NKV * HD];

// bf16 hi/lo copies
__device__ __nv_bfloat16 g_hs_h[E16M],  g_hs_l[E16M];
__device__ __nv_bfloat16 g_w_h[WQKV_E], g_w_l[WQKV_E];   // wq|wk|wv combined
__device__ __nv_bfloat16 g_wo_h[E16M],  g_wo_l[E16M];
__device__ __nv_bfloat16 g_ao_h[E16M],  g_ao_l[E16M];
// post-rope bf16 hi/lo q/k, direct-split v for attention
__device__ __nv_bfloat16 g_q_h[E16M], g_q_l[E16M];
__device__ __nv_bfloat16 g_k_h[E4M],  g_k_l[E4M];
__device__ __nv_bfloat16 g_v_h[E4M],  g_v_l[E4M];

// ---------------------------------------------------------------------------
// Common helpers (sm_80-level PTX only; no 'a'-suffix features)
// ---------------------------------------------------------------------------
__device__ __forceinline__ uint32_t smem_u32(const void* p) {
    uint32_t a;
    asm("{ .reg .u64 t; cvta.to.shared.u64 t, %1; cvt.u32.u64 %0, t; }"
        : "=r"(a) : "l"(p));
    return a;
}
__device__ __forceinline__ uint32_t pack_bf16x2(float a, float b) {
    __nv_bfloat162 h = __floats2bfloat162_rn(a, b);
    return *reinterpret_cast<uint32_t*>(&h);
}
__device__ __forceinline__ void cp16(uint32_t saddr, const void* gptr) {
    asm volatile("cp.async.cg.shared.global [%0], [%1], 16;"
                 :: "r"(saddr), "l"(gptr));
}
__device__ __forceinline__ void cp_commit() {
    asm volatile("cp.async.commit_group;" ::: "memory");
}
template <int N>
__device__ __forceinline__ void cp_wait() {
    asm volatile("cp.async.wait_group %0;" :: "n"(N) : "memory");
}
// ldmatrix.x4 over macro-row layout: logical rows of 32 bf16 (64B) are packed
// in pairs into 128B macro-rows with the standard XOR-8 swizzle.
__device__ __forceinline__ void ldm_x4_k32(uint32_t* r, uint32_t base, int row0, int kt) {
    const int l  = (int)(threadIdx.x & 31);
    const int rr = row0 + (l & 15);
    const int kc = 2 * kt + (l >> 4);
    const int mr = rr >> 1;
    const int ch = (((rr & 1) << 2) | kc) ^ (mr & 7);
    const uint32_t addr = base + (uint32_t)(mr * 128 + ch * 16);
    asm volatile("ldmatrix.sync.aligned.m8n8.x4.shared.b16 {%0,%1,%2,%3}, [%4];"
                 : "=r"(r[0]), "=r"(r[1]), "=r"(r[2]), "=r"(r[3]) : "r"(addr));
}
// ldmatrix.x4, 256B-wide rows (attention tiles, HD=128 bf16 per row)
__device__ __forceinline__ void ldm_x4_256(uint32_t* r, uint32_t base, int row0, int c0) {
    const int l  = (int)(threadIdx.x & 31);
    const int rr = row0 + (l & 15);
    const int cc = (c0 + (l >> 4)) ^ (rr & 7);
    const uint32_t addr = base + (uint32_t)(rr * 256 + cc * 16);
    asm volatile("ldmatrix.sync.aligned.m8n8.x4.shared.b16 {%0,%1,%2,%3}, [%4];"
                 : "=r"(r[0]), "=r"(r[1]), "=r"(r[2]), "=r"(r[3]) : "r"(addr));
}
__device__ __forceinline__ void ldm_x4t_256(uint32_t* r, uint32_t base, int row0, int c0) {
    const int l  = (int)(threadIdx.x & 31);
    const int rr = row0 + (l & 15);
    const int cc = (c0 + (l >> 4)) ^ (rr & 7);
    const uint32_t addr = base + (uint32_t)(rr * 256 + cc * 16);
    asm volatile("ldmatrix.sync.aligned.m8n8.x4.trans.shared.b16 {%0,%1,%2,%3}, [%4];"
                 : "=r"(r[0]), "=r"(r[1]), "=r"(r[2]), "=r"(r[3]) : "r"(addr));
}
__device__ __forceinline__ void mma_bf16(float* d, const uint32_t* a,
                                         uint32_t b0, uint32_t b1) {
    asm volatile(
        "mma.sync.aligned.m16n8k16.row.col.f32.bf16.bf16.f32 "
        "{%0,%1,%2,%3}, {%4,%5,%6,%7}, {%8,%9}, {%0,%1,%2,%3};"
        : "+f"(d[0]), "+f"(d[1]), "+f"(d[2]), "+f"(d[3])
        : "r"(a[0]), "r"(a[1]), "r"(a[2]), "r"(a[3]), "r"(b0), "r"(b1));
}
__device__ __forceinline__ void pack_hilo(float p0, float p1, uint32_t& hi, uint32_t& lo) {
    float h0 = __bfloat162float(__float2bfloat16(p0));
    float h1 = __bfloat162float(__float2bfloat16(p1));
    hi = pack_bf16x2(h0, h1);
    lo = pack_bf16x2(p0 - h0, p1 - h1);
}

// ---------------------------------------------------------------------------
// Merged fp32 -> bf16 hi/lo conversion for all 5 inputs, one launch, MLP=8.
// Segments (float4 units): hs 4M, wq 4M, wk 1M, wv 1M, wo 4M.
// Blocks: [0,2048) hs | [2048,4096) wq | [4096,4608) wk | [4608,5120) wv
//         | [5120,7168) wo.   Each thread: 8 strided float4.
// ---------------------------------------------------------------------------
#define CVT_BLOCKS 7168

__global__ __launch_bounds__(256) void cvt_all_kernel(
    const float4* __restrict__ s0, uint2* __restrict__ h0, uint2* __restrict__ l0,
    const float4* __restrict__ s1, uint2* __restrict__ h1, uint2* __restrict__ l1,
    const float4* __restrict__ s2, uint2* __restrict__ h2, uint2* __restrict__ l2,
    const float4* __restrict__ s3, uint2* __restrict__ h3, uint2* __restrict__ l3,
    const float4* __restrict__ s4, uint2* __restrict__ h4, uint2* __restrict__ l4)
{
    const int blk = blockIdx.x;
    const float4* x; uint2* hi; uint2* lo; int base; int q;
    if (blk < 2048)      { x = s0; hi = h0; lo = l0; base = blk;        q = 524288; }
    else if (blk < 4096) { x = s1; hi = h1; lo = l1; base = blk - 2048; q = 524288; }
    else if (blk < 4608) { x = s2; hi = h2; lo = l2; base = blk - 4096; q = 131072; }
    else if (blk < 5120) { x = s3; hi = h3; lo = l3; base = blk - 4608; q = 131072; }
    else                 { x = s4; hi = h4; lo = l4; base = blk - 5120; q = 524288; }

    const int i = base * 256 + (int)threadIdx.x;
    float4 f[8];
#pragma unroll
    for (int u = 0; u < 8; u++) f[u] = x[i + u * q];   // 8 independent LDGs
#pragma unroll
    for (int u = 0; u < 8; u++) {
        float xs[4] = {f[u].x, f[u].y, f[u].z, f[u].w};
        float hf[4], lf[4];
#pragma unroll
        for (int t = 0; t < 4; t++) {
            __nv_bfloat16 h = __float2bfloat16(xs[t]);
            hf[t] = __bfloat162float(h);
            lf[t] = xs[t] - hf[t];
        }
        uint2 H, L;
        H.x = pack_bf16x2(hf[0], hf[1]); H.y = pack_bf16x2(hf[2], hf[3]);
        L.x = pack_bf16x2(lf[0], lf[1]); L.y = pack_bf16x2(lf[2], lf[3]);
        hi[i + u * q] = H;
        lo[i + u * q] = L;
    }
}

// ---------------------------------------------------------------------------
// GEMM: C[M,N] = A[M,K] * B[N,K]^T  (bf16 hi/lo x3 MMAs, fp32 out)
// Tile 128x64x32, 128 threads = 4 warps (2 M x 2 N), warp tile 64x32.
// 3-stage cp.async ring, 72KB smem -> 3 CTAs/SM. (R11 proven)
// ---------------------------------------------------------------------------
#define TBM 128
#define TBN 64
#define TBK 32
#define OFF_AH 0
#define OFF_AL 8192
#define OFF_BH 16384
#define OFF_BL 20480
#define STAGE_BYTES 24576
#define GEMM_SMEM (3 * STAGE_BYTES)   // 72 KB

__device__ __forceinline__ uint32_t mrow_off(int r, int kc) {
    const int mr = r >> 1;
    const int ch = (((r & 1) << 2) | kc) ^ (mr & 7);
    return (uint32_t)(mr * 128 + ch * 16);
}

__global__ __launch_bounds__(128, 3) void gemm_mma_kernel(
    const __nv_bfloat16* __restrict__ Ah, const __nv_bfloat16* __restrict__ Al,
    const __nv_bfloat16* __restrict__ Bh, const __nv_bfloat16* __restrict__ Bl,
    float* __restrict__ C0, float* __restrict__ C1,
    __nv_bfloat16* __restrict__ C2h, __nv_bfloat16* __restrict__ C2l,
    int ns1, int ns2, int ldc0, int ldc1, int ldc2,
    int M, int N, int K)
{
    extern __shared__ __align__(1024) char smem[];
    const uint32_t sbase = smem_u32(smem);
    const int tid  = threadIdx.x;
    const int lane = tid & 31;
    const int wid  = tid >> 5;       // 0..3
    const int wm   = wid & 1;        // warp rows [wm*64,+64)
    const int wn   = wid >> 1;       // warp cols [wn*32,+32)
    const int m0   = blockIdx.y * TBM;
    const int n0   = blockIdx.x * TBN;
    const int r0c = tid >> 2, c0c = tid & 3;   // copy coords (row group, chunk)

    float acc[4][4][4];
#pragma unroll
    for (int i = 0; i < 4; i++)
#pragma unroll
        for (int j = 0; j < 4; j++)
#pragma unroll
            for (int t = 0; t < 4; t++) acc[i][j][t] = 0.0f;

    const int nch = K / TBK;

    auto issue = [&](int s, int k0) {
        const uint32_t st = sbase + s * STAGE_BYTES;
#pragma unroll
        for (int i = 0; i < 4; i++) {           // A: 128 rows
            const int r = r0c + i * 32;
            const uint32_t off = mrow_off(r, c0c);
            const size_t ga = (size_t)(m0 + r) * K + k0 + c0c * 8;
            cp16(st + OFF_AH + off, Ah + ga);
            cp16(st + OFF_AL + off, Al + ga);
        }
#pragma unroll
        for (int i = 0; i < 2; i++) {           // B: 64 rows
            const int r = r0c + i * 32;
            const uint32_t off = mrow_off(r, c0c);
            const size_t gb = (size_t)(n0 + r) * K + k0 + c0c * 8;
            cp16(st + OFF_BH + off, Bh + gb);
            cp16(st + OFF_BL + off, Bl + gb);
        }
        cp_commit();
    };

    issue(0, 0);
    issue(1, TBK);

    for (int ch = 0; ch < nch; ch++) {
        if (ch < nch - 1) cp_wait<1>();
        else              cp_wait<0>();
        __syncthreads();

        const int s = ch % 3;
        const uint32_t stAh = sbase + s * STAGE_BYTES + OFF_AH;
        const uint32_t stAl = sbase + s * STAGE_BYTES + OFF_AL;
        const uint32_t stBh = sbase + s * STAGE_BYTES + OFF_BH;
        const uint32_t stBl = sbase + s * STAGE_BYTES + OFF_BL;
#pragma unroll
        for (int kt = 0; kt < 2; kt++) {
            uint32_t ah[4][4], al[4][4], bh[2][4], bl[2][4];
#pragma unroll
            for (int mt = 0; mt < 4; mt++) {
                ldm_x4_k32(ah[mt], stAh, wm * 64 + mt * 16, kt);
                ldm_x4_k32(al[mt], stAl, wm * 64 + mt * 16, kt);
            }
#pragma unroll
            for (int bp = 0; bp < 2; bp++) {
                ldm_x4_k32(bh[bp], stBh, wn * 32 + bp * 16, kt);
                ldm_x4_k32(bl[bp], stBl, wn * 32 + bp * 16, kt);
            }
#pragma unroll
            for (int mt = 0; mt < 4; mt++)
#pragma unroll
                for (int nt = 0; nt < 4; nt++) {
                    const int bp = nt >> 1, o = nt & 1;
                    mma_bf16(acc[mt][nt], ah[mt], bh[bp][o], bh[bp][o + 2]);
                    mma_bf16(acc[mt][nt], ah[mt], bl[bp][o], bl[bp][o + 2]);
                    mma_bf16(acc[mt][nt], al[mt], bh[bp][o], bh[bp][o + 2]);
                }
        }

        if (ch + 2 < nch) issue((ch + 2) % 3, (ch + 2) * TBK);
    }

    // epilogue with column routing (CTA tile never straddles a split)
    if (n0 >= ns2 && C2h != nullptr) {
        const int nc0 = n0 - ns2;
#pragma unroll
        for (int mt = 0; mt < 4; mt++) {
            const int row = m0 + wm * 64 + mt * 16 + (lane >> 2);
#pragma unroll
            for (int nt = 0; nt < 4; nt++) {
                const int col = nc0 + wn * 32 + nt * 8 + (lane & 3) * 2;
                uint32_t h0, l0v, h1, l1v;
                pack_hilo(acc[mt][nt][0], acc[mt][nt][1], h0, l0v);
                pack_hilo(acc[mt][nt][2], acc[mt][nt][3], h1, l1v);
                *(uint32_t*)(C2h + (size_t)row * ldc2 + col)       = h0;
                *(uint32_t*)(C2l + (size_t)row * ldc2 + col)       = l0v;
                *(uint32_t*)(C2h + (size_t)(row + 8) * ldc2 + col) = h1;
                *(uint32_t*)(C2l + (size_t)(row + 8) * ldc2 + col) = l1v;
            }
        }
        return;
    }
    float* Cb; int ldc, nc0;
    if (n0 < ns1) { Cb = C0; ldc = ldc0; nc0 = n0; }
    else          { Cb = C1; ldc = ldc1; nc0 = n0 - ns1; }
#pragma unroll
    for (int mt = 0; mt < 4; mt++) {
        const int row = m0 + wm * 64 + mt * 16 + (lane >> 2);
#pragma unroll
        for (int nt = 0; nt < 4; nt++) {
            const int col = nc0 + wn * 32 + nt * 8 + (lane & 3) * 2;
            float2 v0 = make_float2(acc[mt][nt][0], acc[mt][nt][1]);
            float2 v1 = make_float2(acc[mt][nt][2], acc[mt][nt][3]);
            *(float2*)(Cb + (size_t)row * ldc + col)       = v0;
            *(float2*)(Cb + (size_t)(row + 8) * ldc + col) = v1;
        }
    }
}

// ---------------------------------------------------------------------------
// RoPE + fp32 -> bf16 hi/lo for q, k (vectorized float2 / bf16x2)
// ---------------------------------------------------------------------------
__global__ __launch_bounds__(256) void rope_cvt_kernel(
    const float* __restrict__ q, const float* __restrict__ k,
    const int* __restrict__ pos,
    __nv_bfloat16* __restrict__ qh, __nv_bfloat16* __restrict__ ql,
    __nv_bfloat16* __restrict__ kh, __nv_bfloat16* __restrict__ kl)
{
    const int bs = blockIdx.x;
    const float p = (float)pos[bs];
    const float c1 = -0.2076205059304601f;        // -log2(10000)/64
    for (int i = threadIdx.x; i < 1280; i += 256) {
        const float* base; size_t idx; int dp;
        __nv_bfloat16 *H, *L;
        if (i < 1024) {
            int hh = i >> 5; dp = (i & 31) * 2;
            idx = ((size_t)bs * NH + hh) * HD;
            base = q + idx; H = qh; L = ql;
        } else {
            int j = i - 1024;
            int hh = j >> 5; dp = (j & 31) * 2;
            idx = ((size_t)bs * NKV + hh) * HD;
            base = k + idx; H = kh; L = kl;
        }
        float2 x1 = *(const float2*)(base + dp);
        float2 x2 = *(const float2*)(base + dp + 64);
        float o1[2], o2[2];
#pragma unroll
        for (int t = 0; t < 2; t++) {
            float inv = exp2f(c1 * (float)(dp + t));
            float ang = p * inv;
            float sv, cv;
            sincosf(ang, &sv, &cv);
            float a  = t ? x1.y : x1.x;
            float b2 = t ? x2.y : x2.x;
            o1[t] = a * cv - b2 * sv;
            o2[t] = b2 * cv + a * sv;
        }
        uint32_t hA, lA, hB, lB;
        pack_hilo(o1[0], o1[1], hA, lA);
        pack_hilo(o2[0], o2[1], hB, lB);
        *(uint32_t*)(H + idx + dp)      = hA;
        *(uint32_t*)(L + idx + dp)      = lA;
        *(uint32_t*)(H + idx + dp + 64) = hB;
        *(uint32_t*)(L + idx + dp + 64) = lB;
    }
}

// ---------------------------------------------------------------------------
// Flash attention via mma.sync (bf16 hi/lo x3), fp32 softmax (exp2), causal.
// CTA: 64 q-rows x 1 head, 4 warps, 96KB smem -> 2 CTAs/SM.
// 3-stage KV ring; Q parked in slot 2 until fragments are hoisted.
// ONE __syncthreads per tile. (R10/R11 proven)
// ---------------------------------------------------------------------------
#define ABQ  64
#define ABKV 32
#define KVSTAGE 32768      // per-stage: KH 0, KL 8K, VH 16K, VL 24K
#define SKH 0
#define SKL 8192
#define SVH 16384
#define SVL 24576
#define AQH (2 * KVSTAGE)            // Q parked in slot 2
#define AQL (AQH + 16384)
#define ATTN_SMEM (3 * KVSTAGE)      // 96 KB

__global__ __launch_bounds__(128, 2) void attn_mma_kernel(
    const __nv_bfloat16* __restrict__ Qh, const __nv_bfloat16* __restrict__ Ql,
    const __nv_bfloat16* __restrict__ Kh, const __nv_bfloat16* __restrict__ Kl,
    const __nv_bfloat16* __restrict__ Vh, const __nv_bfloat16* __restrict__ Vl,
    __nv_bfloat16* __restrict__ AOh, __nv_bfloat16* __restrict__ AOl)
{
    extern __shared__ __align__(1024) char smem[];
    const uint32_t sbase = smem_u32(smem);
    const int tid  = threadIdx.x;
    const int lane = tid & 31;
    const int wq   = tid >> 5;                              // 0..3
    const int qb   = (int)gridDim.x - 1 - (int)blockIdx.x;  // big tiles first
    const int h    = blockIdx.y, b = blockIdx.z;
    const int g    = h / NREP;
    const int q0   = qb * ABQ;
    const int rowmin = q0 + wq * 16;
    const int lr8 = tid >> 4;      // 0..7 row within 8-row pass
    const int lc  = tid & 15;      // 16B chunk within 256B row

    // ---- Q tile into slot 2 (group: Q) ----
#pragma unroll
    for (int i = 0; i < 8; i++) {
        const int row = i * 8 + lr8;
        const uint32_t off = (uint32_t)(row * 256 + ((lc ^ (row & 7)) * 16));
        const size_t gp = ((size_t)(b * S_LEN + q0 + row) * NH + h) * HD + lc * 8;
        cp16(sbase + AQH + off, Qh + gp);
        cp16(sbase + AQL + off, Ql + gp);
    }
    cp_commit();

    auto issue_kv = [&](int s, int k0) {
        const uint32_t st = sbase + s * KVSTAGE;
#pragma unroll
        for (int i = 0; i < 4; i++) {
            const int row = i * 8 + lr8;
            const uint32_t off = (uint32_t)(row * 256 + ((lc ^ (row & 7)) * 16));
            const size_t gp = ((size_t)(b * S_LEN + k0 + row) * NKV + g) * HD + lc * 8;
            cp16(st + SKH + off, Kh + gp);
            cp16(st + SKL + off, Kl + gp);
            cp16(st + SVH + off, Vh + gp);
            cp16(st + SVL + off, Vl + gp);
        }
        cp_commit();
    };
    const int ntile = 2 * qb + 2;   // always >= 2
    issue_kv(0, 0);                 // group: KV0
    issue_kv(1, ABKV);              // group: KV1

    // ---- hoist Q fragments (tile-invariant); slot 2 is free afterwards ----
    cp_wait<2>();    // Q group complete (KV0/KV1 may still be in flight)
    __syncthreads();
    uint32_t aqh_r[8][4], aql_r[8][4];
#pragma unroll
    for (int kt = 0; kt < 8; kt++) {
        ldm_x4_256(aqh_r[kt], sbase + AQH, wq * 16, kt * 2);
        ldm_x4_256(aql_r[kt], sbase + AQL, wq * 16, kt * 2);
    }

    float out[16][4];
#pragma unroll
    for (int i = 0; i < 16; i++)
#pragma unroll
        for (int j = 0; j < 4; j++) out[i][j] = 0.0f;
    float m0 = -1e30f, m1 = -1e30f, l0 = 0.0f, l1 = 0.0f;
    const float scl2 = 0.08838834764831845f * 1.4426950408889634f;  // /sqrt(128)*log2(e)

    for (int kb = 0; kb < ntile; kb++) {
        const int s = kb % 3;
        const int k0 = kb * ABKV;
        if (kb + 1 < ntile) cp_wait<1>();
        else                cp_wait<0>();
        __syncthreads();

        if (k0 <= rowmin + 15) {   // else tile fully masked for this warp
            const uint32_t stK = sbase + s * KVSTAGE;

            // ---- S = Q K^T  (16 x 32 x 128) ----
            float sc[4][4];
#pragma unroll
            for (int nt = 0; nt < 4; nt++)
#pragma unroll
                for (int j = 0; j < 4; j++) sc[nt][j] = 0.0f;
#pragma unroll
            for (int kt = 0; kt < 8; kt++) {
#pragma unroll
                for (int bp = 0; bp < 2; bp++) {
                    uint32_t bkh[4], bkl[4];
                    ldm_x4_256(bkh, stK + SKH, bp * 16, kt * 2);
                    ldm_x4_256(bkl, stK + SKL, bp * 16, kt * 2);
#pragma unroll
                    for (int o = 0; o < 2; o++) {
                        const int nt = bp * 2 + o;
                        mma_bf16(sc[nt], aqh_r[kt], bkh[o], bkh[o + 2]);
                        mma_bf16(sc[nt], aqh_r[kt], bkl[o], bkl[o + 2]);
                        mma_bf16(sc[nt], aql_r[kt], bkh[o], bkh[o + 2]);
                    }
                }
            }

            // ---- scale + causal mask + online softmax (exp2 domain) ----
            const int r0g = rowmin + (lane >> 2);
            const bool domask = (k0 + ABKV - 1) > rowmin;
            float mx0 = -1e30f, mx1 = -1e30f;
#pragma unroll
            for (int nt = 0; nt < 4; nt++) {
#pragma unroll
                for (int j = 0; j < 4; j++) {
                    float v = sc[nt][j] * scl2;
                    if (domask) {
                        int cg = k0 + nt * 8 + (lane & 3) * 2 + (j & 1);
                        int rg = r0g + ((j >> 1) << 3);
                        if (cg > rg) v = -1e30f;
                    }
                    sc[nt][j] = v;
                }
                mx0 = fmaxf(mx0, fmaxf(sc[nt][0], sc[nt][1]));
                mx1 = fmaxf(mx1, fmaxf(sc[nt][2], sc[nt][3]));
            }
            mx0 = fmaxf(mx0, __shfl_xor_sync(0xffffffffu, mx0, 1));
            mx0 = fmaxf(mx0, __shfl_xor_sync(0xffffffffu, mx0, 2));
            mx1 = fmaxf(mx1, __shfl_xor_sync(0xffffffffu, mx1, 1));
            mx1 = fmaxf(mx1, __shfl_xor_sync(0xffffffffu, mx1, 2));
            const float mn0 = fmaxf(m0, mx0), mn1 = fmaxf(m1, mx1);
            const float a0 = exp2f(m0 - mn0), a1 = exp2f(m1 - mn1);
            m0 = mn0; m1 = mn1;
            float ps0 = 0.0f, ps1 = 0.0f;
#pragma unroll
            for (int nt = 0; nt < 4; nt++) {
                sc[nt][0] = exp2f(sc[nt][0] - mn0); ps0 += sc[nt][0];
                sc[nt][1] = exp2f(sc[nt][1] - mn0); ps0 += sc[nt][1];
                sc[nt][2] = exp2f(sc[nt][2] - mn1); ps1 += sc[nt][2];
                sc[nt][3] = exp2f(sc[nt][3] - mn1); ps1 += sc[nt][3];
            }
            l0 = l0 * a0 + ps0;
            l1 = l1 * a1 + ps1;
#pragma unroll
            for (int dt = 0; dt < 16; dt++) {
                out[dt][0] *= a0; out[dt][1] *= a0;
                out[dt][2] *= a1; out[dt][3] *= a1;
            }

            // ---- O += P V  (16 x 128 x 32) ----
#pragma unroll
            for (int ktp = 0; ktp < 2; ktp++) {
                uint32_t aph[4], apl[4];
                const int t0 = ktp * 2, t1 = t0 + 1;
                pack_hilo(sc[t0][0], sc[t0][1], aph[0], apl[0]);
                pack_hilo(sc[t0][2], sc[t0][3], aph[1], apl[1]);
                pack_hilo(sc[t1][0], sc[t1][1], aph[2], apl[2]);
                pack_hilo(sc[t1][2], sc[t1][3], aph[3], apl[3]);
#pragma unroll
                for (int dt = 0; dt < 8; dt++) {
                    uint32_t bvh[4], bvl[4];
                    ldm_x4t_256(bvh, stK + SVH, ktp * 16, dt * 2);
                    ldm_x4t_256(bvl, stK + SVL, ktp * 16, dt * 2);
                    mma_bf16(out[dt * 2],     aph, bvh[0], bvh[1]);
                    mma_bf16(out[dt * 2],     aph, bvl[0], bvl[1]);
                    mma_bf16(out[dt * 2],     apl, bvh[0], bvh[1]);
                    mma_bf16(out[dt * 2 + 1], aph, bvh[2], bvh[3]);
                    mma_bf16(out[dt * 2 + 1], aph, bvl[2], bvl[3]);
                    mma_bf16(out[dt * 2 + 1], apl, bvh[2], bvh[3]);
                }
            }
        }

        if (kb + 2 < ntile) issue_kv((kb + 2) % 3, (kb + 2) * ABKV);
    }

    // ---- finalize: write bf16 hi/lo directly (feeds O-projection GEMM) ----
    l0 += __shfl_xor_sync(0xffffffffu, l0, 1);
    l0 += __shfl_xor_sync(0xffffffffu, l0, 2);
    l1 += __shfl_xor_sync(0xffffffffu, l1, 1);
    l1 += __shfl_xor_sync(0xffffffffu, l1, 2);
    const float i0 = 1.0f / l0, i1 = 1.0f / l1;
    const int r0g = rowmin + (lane >> 2);
    const size_t base0 = ((size_t)(b * S_LEN + r0g) * NH + h) * HD;
    const size_t base1 = base0 + (size_t)8 * NH * HD;
#pragma unroll
    for (int dt = 0; dt < 16; dt++) {
        const int col = dt * 8 + (lane & 3) * 2;
        uint32_t h0, l0p, h1, l1p;
        pack_hilo(out[dt][0] * i0, out[dt][1] * i0, h0, l0p);
        pack_hilo(out[dt][2] * i1, out[dt][3] * i1, h1, l1p);
        *(uint32_t*)(AOh + base0 + col) = h0;
        *(uint32_t*)(AOl + base0 + col) = l0p;
        *(uint32_t*)(AOh + base1 + col) = h1;
        *(uint32_t*)(AOl + base1 + col) = l1p;
    }
}

// ---------------------------------------------------------------------------
// Launch
// ---------------------------------------------------------------------------
extern "C" void kernel_launch(void* const* d_in, const int* in_sizes, int n_in,
                              void* d_out, int out_size)
{
    const float* hs = (const float*)d_in[0];
    const float* wq = (const float*)d_in[1];
    const float* wk = (const float*)d_in[2];
    const float* wv = (const float*)d_in[3];
    const float* wo = (const float*)d_in[4];
    const int*  pos = (const int*)  d_in[6];
    float*      out = (float*)d_out;

    float *q, *k;
    cudaGetSymbolAddress((void**)&q,  g_q);
    cudaGetSymbolAddress((void**)&k,  g_k);

    __nv_bfloat16 *hsh, *hsl, *wh, *wl, *woh, *wol, *aoh, *aol;
    __nv_bfloat16 *qh, *ql, *kh, *kl, *vh, *vl;
    cudaGetSymbolAddress((void**)&hsh, g_hs_h); cudaGetSymbolAddress((void**)&hsl, g_hs_l);
    cudaGetSymbolAddress((void**)&wh,  g_w_h);  cudaGetSymbolAddress((void**)&wl,  g_w_l);
    cudaGetSymbolAddress((void**)&woh, g_wo_h); cudaGetSymbolAddress((void**)&wol, g_wo_l);
    cudaGetSymbolAddress((void**)&aoh, g_ao_h); cudaGetSymbolAddress((void**)&aol, g_ao_l);
    cudaGetSymbolAddress((void**)&qh,  g_q_h);  cudaGetSymbolAddress((void**)&ql,  g_q_l);
    cudaGetSymbolAddress((void**)&kh,  g_k_h);  cudaGetSymbolAddress((void**)&kl,  g_k_l);
    cudaGetSymbolAddress((void**)&vh,  g_v_h);  cudaGetSymbolAddress((void**)&vl,  g_v_l);

    cudaFuncSetAttribute(gemm_mma_kernel, cudaFuncAttributeMaxDynamicSharedMemorySize, GEMM_SMEM);
    cudaFuncSetAttribute(attn_mma_kernel, cudaFuncAttributeMaxDynamicSharedMemorySize, ATTN_SMEM);

    // One merged conversion launch for all five inputs (MLP=8 per thread).
    // wq|wk|wv land in the combined [6144,4096] buffer at offsets 0/16M/20M.
    cvt_all_kernel<<<CVT_BLOCKS, 256>>>(
        (const float4*)hs, (uint2*)hsh, (uint2*)hsl,
        (const float4*)wq, (uint2*)wh,              (uint2*)wl,
        (const float4*)wk, (uint2*)(wh + 16777216u), (uint2*)(wl + 16777216u),
        (const float4*)wv, (uint2*)(wh + 20971520u), (uint2*)(wl + 20971520u),
        (const float4*)wo, (uint2*)woh, (uint2*)wol);

    // Merged QKV projection: N = 6144; q,k -> fp32, v -> bf16 hi/lo directly
    gemm_mma_kernel<<<dim3(6144 / TBN, MROWS / TBM), 128, GEMM_SMEM>>>(
        hsh, hsl, wh, wl, q, k, vh, vl,
        4096, 5120, NH * HD, NKV * HD, NKV * HD,
        MROWS, 6144, HID);

    // RoPE + hi/lo conversion for q, k
    rope_cvt_kernel<<<MROWS, 256>>>(q, k, pos, qh, ql, kh, kl);

    // Causal flash attention (mma.sync, 2 CTAs/SM, 3-stage ring, 1 sync/tile)
    attn_mma_kernel<<<dim3(S_LEN / ABQ, NH, B_SZ), 128, ATTN_SMEM>>>(
        qh, ql, kh, kl, vh, vl, aoh, aol);

    // Output projection
    gemm_mma_kernel<<<dim3(HID / TBN, MROWS / TBM), 128, GEMM_SMEM>>>(
        aoh, aol, woh, wol, out, out, nullptr, nullptr,
        HID, HID, HID, HID, HID,
        MROWS, HID, NH * HD);
}